// round 9
// baseline (speedup 1.0000x reference)
#include <cuda_runtime.h>
#include <cuda_bf16.h>
#include <cstdint>

#define HW 65536
#define CC 256

// ---------------- scratch ---------------------------------------------------
__device__ float g_big[100663296];
__device__ float g_obn[33554432];
__device__ __align__(16) __nv_bfloat16 g_wA[2359296];
__device__ __align__(16) __nv_bfloat16 g_wQ[442368];
__device__ __align__(16) __nv_bfloat16 g_wP[147456];
__device__ __align__(16) __nv_bfloat16 g_xsplit[67108864];

// ---------------- helpers ---------------------------------------------------
__device__ __forceinline__ uint32_t smem_u32(const void* p) {
    uint32_t a;
    asm("{ .reg .u64 t; cvta.to.shared.u64 t, %1; cvt.u32.u64 %0, t; }" : "=r"(a) : "l"(p));
    return a;
}
__device__ __forceinline__ void ldsm4(uint32_t& r0, uint32_t& r1, uint32_t& r2, uint32_t& r3,
                                      uint32_t addr) {
    asm volatile("ldmatrix.sync.aligned.m8n8.x4.shared.b16 {%0,%1,%2,%3}, [%4];"
                 : "=r"(r0), "=r"(r1), "=r"(r2), "=r"(r3) : "r"(addr));
}
__device__ __forceinline__ void mma16816(float* c, uint32_t a0, uint32_t a1, uint32_t a2,
                                         uint32_t a3, uint32_t b0, uint32_t b1) {
    asm volatile("mma.sync.aligned.m16n8k16.row.col.f32.bf16.bf16.f32 "
                 "{%0,%1,%2,%3}, {%4,%5,%6,%7}, {%8,%9}, {%0,%1,%2,%3};"
                 : "+f"(c[0]), "+f"(c[1]), "+f"(c[2]), "+f"(c[3])
                 : "r"(a0), "r"(a1), "r"(a2), "r"(a3), "r"(b0), "r"(b1));
}
__device__ __forceinline__ void split2(float v0, float v1, __nv_bfloat162& ph, __nv_bfloat162& pl) {
    __nv_bfloat16 h0 = __float2bfloat16(v0), h1 = __float2bfloat16(v1);
    ph.x = h0; ph.y = h1;
    pl.x = __float2bfloat16(v0 - __bfloat162float(h0));
    pl.y = __float2bfloat16(v1 - __bfloat162float(h1));
}
__device__ __forceinline__ void cpa16(uint32_t dst, const void* src) {
    asm volatile("cp.async.cg.shared.global [%0], [%1], 16;" :: "r"(dst), "l"(src));
}
__device__ __forceinline__ void cpa_wait() {
    asm volatile("cp.async.commit_group;");
    asm volatile("cp.async.wait_group 0;" ::: "memory");
}

// ---------------- weight/input prep kernels --------------------------------
__global__ void aprep_kernel(const float* __restrict__ wx, const float* __restrict__ wy) {
    int e = blockIdx.x * 256 + threadIdx.x;
    if (e >= 1048576) return;
    int k = e & 63, o_l = (e >> 6) & 127, s = (e >> 13) & 63, mt = e >> 19;
    int c = 4 * s + (k >> 4);
    int conv = (k >> 3) & 1, tap = k & 7;
    int o = mt * 128 + o_l;
    float v = (conv ? wy : wx)[(o * 256 + c) * 8 + tap];
    __nv_bfloat16 h = __float2bfloat16(v);
    __nv_bfloat16 l = __float2bfloat16(v - __bfloat162float(h));
    size_t base = (size_t)(mt * 64 + s) * 18432;
    g_wA[base + o_l * 72 + k] = h;
    g_wA[base + 9216 + o_l * 72 + k] = l;
}
__global__ void qprep_kernel(const float* __restrict__ wqkv) {
    int e = blockIdx.x * 256 + threadIdx.x;
    if (e >= 196608) return;
    int k = e & 63, o_l = (e >> 6) & 127, s = (e >> 13) & 3, mt = e >> 15;
    float v = wqkv[(mt * 128 + o_l) * 256 + s * 64 + k];
    __nv_bfloat16 h = __float2bfloat16(v);
    __nv_bfloat16 l = __float2bfloat16(v - __bfloat162float(h));
    size_t base = (size_t)(mt * 4 + s) * 18432;
    g_wQ[base + o_l * 72 + k] = h;
    g_wQ[base + 9216 + o_l * 72 + k] = l;
}
__global__ void pprep_kernel(const float* __restrict__ wp) {
    int e = blockIdx.x * 256 + threadIdx.x;
    int k = e & 63, o_l = (e >> 6) & 127, s = (e >> 13) & 3, mt = e >> 15;
    float v = wp[(mt * 128 + o_l) * 256 + s * 64 + k];
    __nv_bfloat16 h = __float2bfloat16(v);
    __nv_bfloat16 l = __float2bfloat16(v - __bfloat162float(h));
    size_t base = (size_t)(mt * 4 + s) * 18432;
    g_wP[base + o_l * 72 + k] = h;
    g_wP[base + 9216 + o_l * 72 + k] = l;
}
__global__ void xprep_kernel(const float* __restrict__ x) {
    int g = blockIdx.x * 256 + threadIdx.x;
    int pos = g & (HW - 1);
    int cpb = g >> 16;
    const float* src = x + (size_t)(2 * cpb) * HW + pos;
    float v0 = src[0], v1 = src[HW];
    __nv_bfloat162 h, l;
    split2(v0, v1, h, l);
    ((__nv_bfloat162*)g_xsplit)[g] = h;
    ((__nv_bfloat162*)g_xsplit)[g + 16777216] = l;
}

// ---------------- shared mma consume (M128xN128, one K-stage of 64) ---------
#define MMA_CONSUME(BBASE)                                                               \
    do {                                                                                 \
        _Pragma("unroll")                                                                \
        for (int kstep = 0; kstep < 4; kstep++) {                                        \
            uint32_t ah[2][4], al[2][4];                                                 \
            _Pragma("unroll")                                                            \
            for (int ma = 0; ma < 2; ma++) {                                             \
                uint32_t aaddr = a_base + a_loff + ma * 16 * 144 + kstep * 32;           \
                ldsm4(ah[ma][0], ah[ma][1], ah[ma][2], ah[ma][3], aaddr);                \
                ldsm4(al[ma][0], al[ma][1], al[ma][2], al[ma][3], aaddr + 18432);        \
            }                                                                            \
            _Pragma("unroll")                                                            \
            for (int nc = 0; nc < 4; nc++) {                                             \
                uint32_t baddr = (BBASE) + b_loff + (wn * 64 + nc * 16) * 144 + kstep * 32; \
                uint32_t bh0, bh1, bh2, bh3, bl0, bl1, bl2, bl3;                         \
                ldsm4(bh0, bh1, bh2, bh3, baddr);                                        \
                ldsm4(bl0, bl1, bl2, bl3, baddr + 18432);                                \
                _Pragma("unroll")                                                        \
                for (int ma = 0; ma < 2; ma++) {                                         \
                    mma16816(acc[ma][nc * 2 + 0], ah[ma][0], ah[ma][1], ah[ma][2], ah[ma][3], bh0, bh1); \
                    mma16816(acc[ma][nc * 2 + 1], ah[ma][0], ah[ma][1], ah[ma][2], ah[ma][3], bh2, bh3); \
                    mma16816(acc[ma][nc * 2 + 0], ah[ma][0], ah[ma][1], ah[ma][2], ah[ma][3], bl0, bl1); \
                    mma16816(acc[ma][nc * 2 + 1], ah[ma][0], ah[ma][1], ah[ma][2], ah[ma][3], bl2, bl3); \
                    mma16816(acc[ma][nc * 2 + 0], al[ma][0], al[ma][1], al[ma][2], al[ma][3], bh0, bh1); \
                    mma16816(acc[ma][nc * 2 + 1], al[ma][0], al[ma][1], al[ma][2], al[ma][3], bh2, bh3); \
                }                                                                        \
            }                                                                            \
        }                                                                                \
    } while (0)

// ---------------- kernel A: qkv via mma, pipelined B -------------------------
__device__ __forceinline__ void qkv_fillB(__nv_bfloat16* Bh, int t, size_t rowb, int ss) {
    const __nv_bfloat162* xph = (const __nv_bfloat162*)g_xsplit;
    const __nv_bfloat162* xpl = xph + 16777216;
    int cp0 = ss * 32;
#pragma unroll
    for (int i = 0; i < 16; i++) {
        int id = t + (i << 8);
        int xl = id & 127, j = id >> 7;
        size_t g = rowb + (size_t)(cp0 + j) * HW + xl;
        int idx = xl * 72 + 2 * j;
        *(__nv_bfloat162*)(Bh + idx) = xph[g];
        *(__nv_bfloat162*)(Bh + 9216 + idx) = xpl[g];
    }
}

__global__ void __launch_bounds__(256, 2) qkv_mma_kernel() {
    extern __shared__ __align__(16) char dsm[];
    __nv_bfloat16* Asm = (__nv_bfloat16*)dsm;
    __nv_bfloat16* Bsm0 = (__nv_bfloat16*)(dsm + 36864);
    __nv_bfloat16* Bsm1 = (__nv_bfloat16*)(dsm + 73728);
    int t = threadIdx.x, wid = t >> 5, lane = t & 31;
    int y = blockIdx.x, b = blockIdx.y, z = blockIdx.z;
    int mt = z >> 1, nt = z & 1;
    int x0 = nt * 128;
    int wm = wid & 3, wn = wid >> 2;

    float acc[2][8][4];
#pragma unroll
    for (int i = 0; i < 2; i++)
#pragma unroll
        for (int j = 0; j < 8; j++)
#pragma unroll
            for (int r = 0; r < 4; r++) acc[i][j][r] = 0.f;

    uint32_t a_base = smem_u32(Asm);
    uint32_t b_base0 = smem_u32(Bsm0);
    uint32_t a_loff = (uint32_t)((wm * 32 + (lane & 15)) * 144 + (lane >> 4) * 16);
    uint32_t b_loff = (uint32_t)(((lane & 7) + ((lane >> 4) << 3)) * 144 + ((lane >> 3) & 1) * 16);
    size_t rowb = (size_t)(b * 128) * HW + y * 256 + x0;

    // prologue: A(0) + B(0)
    {
        const float4* wsrc = (const float4*)(g_wQ + (size_t)(mt * 4) * 18432);
#pragma unroll
        for (int i = 0; i < 9; i++) cpa16(a_base + (t + (i << 8)) * 16, wsrc + t + (i << 8));
        qkv_fillB(Bsm0, t, rowb, 0);
        cpa_wait();
        __syncthreads();
    }
    for (int s = 0; s < 4; s++) {
        int cur = s & 1;
        if (s < 3) qkv_fillB(cur ? Bsm0 : Bsm1, t, rowb, s + 1);
        uint32_t bb = b_base0 + cur * 36864;
        MMA_CONSUME(bb);
        __syncthreads();
        if (s < 3) {
            const float4* wsrc = (const float4*)(g_wQ + (size_t)(mt * 4 + s + 1) * 18432);
#pragma unroll
            for (int i = 0; i < 9; i++) cpa16(a_base + (t + (i << 8)) * 16, wsrc + t + (i << 8));
            cpa_wait();
            __syncthreads();
        }
    }

    // epilogue: scatter to window layout q/k/v
    int g = lane >> 2, tq = lane & 3;
    int win_row = b * 1024 + (y >> 3) * 32;
    int tokb = (y & 7) * 8;
#pragma unroll
    for (int ma = 0; ma < 2; ma++) {
        int o_a = mt * 128 + wm * 32 + ma * 16 + g;
        int o_b = o_a + 8;
        int sel_a = o_a >> 8, h_a = (o_a >> 4) & 15, dd_a = o_a & 15;
        int sel_b = o_b >> 8, h_b = (o_b >> 4) & 15, dd_b = o_b & 15;
#pragma unroll
        for (int na = 0; na < 8; na++) {
            int xq = x0 + wn * 64 + na * 8 + tq * 2;
            int win = win_row + (xq >> 3);
            int tok = tokb + (xq & 7);
            size_t pa = (size_t)sel_a * 33554432 + (size_t)((win * 16 + h_a) * 64 + tok) * 16 + dd_a;
            size_t pb = (size_t)sel_b * 33554432 + (size_t)((win * 16 + h_b) * 64 + tok) * 16 + dd_b;
            g_big[pa] = acc[ma][na][0];
            g_big[pa + 16] = acc[ma][na][1];
            g_big[pb] = acc[ma][na][2];
            g_big[pb + 16] = acc[ma][na][3];
        }
    }
}

// ---------------- kernel B: window attention (writes split planes) ---------
__global__ void __launch_bounds__(64) attn_kernel(const float* __restrict__ rel_table) {
    __shared__ float ks[1024], vs[1024], bs[232];
    int t = threadIdx.x;
    int w = blockIdx.x;
    int h = blockIdx.y;
    size_t base = ((size_t)(w * 16 + h)) * 1024;
    const float* gq = g_big;
    const float* gk = g_big + 33554432;
    const float* gv = g_big + 67108864;
#pragma unroll
    for (int i = 0; i < 4; i++) {
        *(float4*)(ks + t * 16 + i * 4) = *(const float4*)(gk + base + t * 16 + i * 4);
        *(float4*)(vs + t * 16 + i * 4) = *(const float4*)(gv + base + t * 16 + i * 4);
    }
    for (int r = t; r < 225; r += 64) bs[r] = rel_table[r * 16 + h];
    __syncthreads();

    float q[16];
#pragma unroll
    for (int i = 0; i < 4; i++)
        *(float4*)(q + i * 4) = *(const float4*)(gq + base + t * 16 + i * 4);
    int i1 = t >> 3, i2 = t & 7;

    float d[64];
#pragma unroll
    for (int j = 0; j < 64; j++) {
        const float4* kp = (const float4*)(ks + j * 16);
        float4 k0 = kp[0], k1 = kp[1], k2 = kp[2], k3 = kp[3];
        float s = q[0] * k0.x + q[1] * k0.y + q[2] * k0.z + q[3] * k0.w +
                  q[4] * k1.x + q[5] * k1.y + q[6] * k1.z + q[7] * k1.w +
                  q[8] * k2.x + q[9] * k2.y + q[10] * k2.z + q[11] * k2.w +
                  q[12] * k3.x + q[13] * k3.y + q[14] * k3.z + q[15] * k3.w;
        int j1 = j >> 3, j2 = j & 7;
        d[j] = 0.25f * s + bs[(i1 - j1 + 7) * 15 + (i2 - j2 + 7)];
    }
    float m = -1e30f;
#pragma unroll
    for (int j = 0; j < 64; j++) m = fmaxf(m, d[j]);
    float sum = 0.f;
#pragma unroll
    for (int j = 0; j < 64; j++) { d[j] = __expf(d[j] - m); sum += d[j]; }
    float inv = 1.0f / sum;

    float acc[16] = {};
#pragma unroll
    for (int j = 0; j < 64; j++) {
        float a = d[j] * inv;
        const float4* vp = (const float4*)(vs + j * 16);
        float4 v0 = vp[0], v1 = vp[1], v2 = vp[2], v3 = vp[3];
        acc[0] += a * v0.x;  acc[1] += a * v0.y;  acc[2] += a * v0.z;  acc[3] += a * v0.w;
        acc[4] += a * v1.x;  acc[5] += a * v1.y;  acc[6] += a * v1.z;  acc[7] += a * v1.w;
        acc[8] += a * v2.x;  acc[9] += a * v2.y;  acc[10] += a * v2.z; acc[11] += a * v2.w;
        acc[12] += a * v3.x; acc[13] += a * v3.y; acc[14] += a * v3.z; acc[15] += a * v3.w;
    }
    int b = w >> 10, wy = (w >> 5) & 31, wx = w & 31;
    int y = wy * 8 + i1, xq = wx * 8 + i2;
    __nv_bfloat16* ophi = (__nv_bfloat16*)g_obn;
    __nv_bfloat16* oplo = ophi + 33554432;
    size_t ob = ((size_t)(b * 256 + h * 16)) * HW + y * 256 + xq;
#pragma unroll
    for (int e = 0; e < 16; e++) {
        float v = acc[e];
        __nv_bfloat16 hh = __float2bfloat16(v);
        ophi[ob + (size_t)e * HW] = hh;
        oplo[ob + (size_t)e * HW] = __float2bfloat16(v - __bfloat162float(hh));
    }
}

// ---------------- kernel C: conv2 via mma, pipelined B -----------------------
__device__ __forceinline__ __nv_bfloat16 ldpb(const __nv_bfloat16* p, int r, int q) {
    if ((unsigned)r > 256u || (unsigned)q > 256u) return __float2bfloat16(0.f);
    return p[((r == 256) ? 254 : r) * 256 + ((q == 256) ? 254 : q)];
}

__device__ __forceinline__ void conv_fillB(__nv_bfloat16* Bh, int t, size_t cbase,
                                           int y, int x0, int ss) {
    const __nv_bfloat16* ophi = (const __nv_bfloat16*)g_obn;
    const __nv_bfloat16* oplo = ophi + 33554432;
    int c0 = 4 * ss;
#pragma unroll
    for (int i = 0; i < 8; i++) {           // vertical taps
        int id = t + (i << 8);
        int xl = id & 127, u = id >> 7;
        int c_l = u >> 2, rp = u & 3;
        const __nv_bfloat16* chi = ophi + cbase + (size_t)(c0 + c_l) * HW;
        const __nv_bfloat16* clo = oplo + cbase + (size_t)(c0 + c_l) * HW;
        int xq = x0 + xl;
        int r0 = y - 3 + 2 * rp, r1 = r0 + 1;
        __nv_bfloat162 ph, pl;
        ph.x = ldpb(chi, r0, xq); ph.y = ldpb(chi, r1, xq);
        pl.x = ldpb(clo, r0, xq); pl.y = ldpb(clo, r1, xq);
        int idx = xl * 72 + c_l * 16 + 2 * rp;
        *(__nv_bfloat162*)(Bh + idx) = ph;
        *(__nv_bfloat162*)(Bh + 9216 + idx) = pl;
    }
#pragma unroll
    for (int i = 0; i < 8; i++) {           // horizontal taps
        int id = t + (i << 8);
        int xl = id & 127, u = id >> 7;
        int c_l = u >> 2, tp = u & 3;
        const __nv_bfloat16* chi = ophi + cbase + (size_t)(c0 + c_l) * HW;
        const __nv_bfloat16* clo = oplo + cbase + (size_t)(c0 + c_l) * HW;
        int xq = x0 + xl;
        int q0 = xq + 2 * tp - 3, q1 = q0 + 1;
        __nv_bfloat162 ph, pl;
        ph.x = ldpb(chi, y, q0); ph.y = ldpb(chi, y, q1);
        pl.x = ldpb(clo, y, q0); pl.y = ldpb(clo, y, q1);
        int idx = xl * 72 + c_l * 16 + 8 + 2 * tp;
        *(__nv_bfloat162*)(Bh + idx) = ph;
        *(__nv_bfloat162*)(Bh + 9216 + idx) = pl;
    }
}

__global__ void __launch_bounds__(256, 2) conv2_mma_kernel(const float* __restrict__ bias_x,
                                                           const float* __restrict__ bias_y) {
    extern __shared__ __align__(16) char dsm[];
    __nv_bfloat16* Asm = (__nv_bfloat16*)dsm;
    __nv_bfloat16* Bsm0 = (__nv_bfloat16*)(dsm + 36864);
    __nv_bfloat16* Bsm1 = (__nv_bfloat16*)(dsm + 73728);
    int t = threadIdx.x, wid = t >> 5, lane = t & 31;
    int y = blockIdx.x, b = blockIdx.y, z = blockIdx.z;
    int mt = z >> 1, nt = z & 1;
    int x0 = nt * 128;
    int wm = wid & 3, wn = wid >> 2;
    size_t cbase = (size_t)b * CC * HW;

    float acc[2][8][4];
#pragma unroll
    for (int i = 0; i < 2; i++)
#pragma unroll
        for (int j = 0; j < 8; j++)
#pragma unroll
            for (int r = 0; r < 4; r++) acc[i][j][r] = 0.f;

    uint32_t a_base = smem_u32(Asm);
    uint32_t b_base0 = smem_u32(Bsm0);
    uint32_t a_loff = (uint32_t)((wm * 32 + (lane & 15)) * 144 + (lane >> 4) * 16);
    uint32_t b_loff = (uint32_t)(((lane & 7) + ((lane >> 4) << 3)) * 144 + ((lane >> 3) & 1) * 16);

    // prologue
    {
        const float4* wsrc = (const float4*)(g_wA + (size_t)(mt * 64) * 18432);
#pragma unroll
        for (int i = 0; i < 9; i++) cpa16(a_base + (t + (i << 8)) * 16, wsrc + t + (i << 8));
        conv_fillB(Bsm0, t, cbase, y, x0, 0);
        cpa_wait();
        __syncthreads();
    }
    for (int s = 0; s < 64; s++) {
        int cur = s & 1;
        if (s < 63) conv_fillB(cur ? Bsm0 : Bsm1, t, cbase, y, x0, s + 1);
        uint32_t bb = b_base0 + cur * 36864;
        MMA_CONSUME(bb);
        __syncthreads();
        if (s < 63) {
            const float4* wsrc = (const float4*)(g_wA + (size_t)(mt * 64 + s + 1) * 18432);
#pragma unroll
            for (int i = 0; i < 9; i++) cpa16(a_base + (t + (i << 8)) * 16, wsrc + t + (i << 8));
            cpa_wait();
            __syncthreads();
        }
    }

    // epilogue: bias + float2 stores
    float* out1 = g_big;
    int g = lane >> 2, tq = lane & 3;
#pragma unroll
    for (int ma = 0; ma < 2; ma++) {
        int o_base = mt * 128 + wm * 32 + ma * 16;
        int o0 = o_base + g, o1 = o_base + g + 8;
        float bia0 = bias_x[o0] + bias_y[o0];
        float bia1 = bias_x[o1] + bias_y[o1];
        float* r0 = out1 + (size_t)(b * 256 + o0) * HW + y * 256;
        float* r1 = out1 + (size_t)(b * 256 + o1) * HW + y * 256;
#pragma unroll
        for (int na = 0; na < 8; na++) {
            int xq = x0 + wn * 64 + na * 8 + tq * 2;
            float2 w0; w0.x = acc[ma][na][0] + bia0; w0.y = acc[ma][na][1] + bia0;
            float2 w1; w1.x = acc[ma][na][2] + bia1; w1.y = acc[ma][na][3] + bia1;
            *(float2*)(r0 + xq) = w0;
            *(float2*)(r1 + xq) = w1;
        }
    }
}

// ---------------- kernel D: depthwise 8x8 + BN, channel-paired split out ---
__global__ void __launch_bounds__(256) dwbn_kernel(const float* __restrict__ wdw,
                                                   const float* __restrict__ gamma,
                                                   const float* __restrict__ beta,
                                                   const float* __restrict__ mean,
                                                   const float* __restrict__ var) {
    __shared__ float S[2][1560];
    __shared__ float ws[128];
    int t = threadIdx.x;
    int tile = blockIdx.x;
    int cp = blockIdx.y, b = blockIdx.z;
    int c0 = 2 * cp;
    int y0 = (tile >> 3) * 32, x0 = (tile & 7) * 32;
#pragma unroll
    for (int ch = 0; ch < 2; ch++) {
        const float* in = g_big + ((size_t)(b * 256 + c0 + ch)) * HW;
        for (int e = t; e < 39 * 39; e += 256) {
            int r = e / 39, j = e - r * 39;
            int row = y0 - 3 + r, col = x0 - 3 + j;
            float v = 0.f;
            if (row >= 0 && row <= 256 && col >= 0 && col <= 256) {
                int rr = (row == 256) ? 254 : row;
                int cc = (col == 256) ? 254 : col;
                v = in[rr * 256 + cc];
            }
            S[ch][r * 40 + j] = v;
        }
    }
    if (t < 128) ws[t] = wdw[c0 * 64 + t];
    __syncthreads();

    int ly = t >> 3, lx0 = (t & 7) * 4;
    float acc[2][4] = {};
#pragma unroll
    for (int ch = 0; ch < 2; ch++) {
#pragma unroll
        for (int ky = 0; ky < 8; ky++) {
            float rv[11];
#pragma unroll
            for (int u = 0; u < 11; u++) rv[u] = S[ch][(ly + ky) * 40 + lx0 + u];
#pragma unroll
            for (int kx = 0; kx < 8; kx++) {
                float wv = ws[ch * 64 + ky * 8 + kx];
#pragma unroll
                for (int j = 0; j < 4; j++) acc[ch][j] += wv * rv[kx + j];
            }
        }
    }
    float iv0 = rsqrtf(var[c0] + 1e-5f), iv1 = rsqrtf(var[c0 + 1] + 1e-5f);
    float sc0 = gamma[c0] * iv0, sc1 = gamma[c0 + 1] * iv1;
    float sh0 = beta[c0] - mean[c0] * sc0, sh1 = beta[c0 + 1] - mean[c0 + 1] * sc1;
    __nv_bfloat162* oh = (__nv_bfloat162*)g_obn;
    __nv_bfloat162* ol = oh + 16777216;
    size_t g = ((size_t)(b * 128 + cp)) * HW + (y0 + ly) * 256 + x0 + lx0;
#pragma unroll
    for (int j = 0; j < 4; j++) {
        float u0 = acc[0][j] * sc0 + sh0;
        float u1 = acc[1][j] * sc1 + sh1;
        __nv_bfloat162 hh, ll;
        split2(u0, u1, hh, ll);
        oh[g + j] = hh;
        ol[g + j] = ll;
    }
}

// ---------------- kernel E: proj via mma, pipelined B -> d_out --------------
__device__ __forceinline__ void proj_fillB(__nv_bfloat16* Bh, int t, size_t rowb, int ss) {
    const __nv_bfloat162* dph = (const __nv_bfloat162*)g_obn;
    const __nv_bfloat162* dpl = dph + 16777216;
    int cp0 = ss * 32;
#pragma unroll
    for (int i = 0; i < 16; i++) {
        int id = t + (i << 8);
        int xl = id & 127, j = id >> 7;
        size_t g = rowb + (size_t)(cp0 + j) * HW + xl;
        int idx = xl * 72 + 2 * j;
        *(__nv_bfloat162*)(Bh + idx) = dph[g];
        *(__nv_bfloat162*)(Bh + 9216 + idx) = dpl[g];
    }
}

__global__ void __launch_bounds__(256, 2) proj_mma_kernel(float* __restrict__ out) {
    extern __shared__ __align__(16) char dsm[];
    __nv_bfloat16* Asm = (__nv_bfloat16*)dsm;
    __nv_bfloat16* Bsm0 = (__nv_bfloat16*)(dsm + 36864);
    __nv_bfloat16* Bsm1 = (__nv_bfloat16*)(dsm + 73728);
    int t = threadIdx.x, wid = t >> 5, lane = t & 31;
    int y = blockIdx.x, b = blockIdx.y, z = blockIdx.z;
    int mt = z >> 1, nt = z & 1;
    int x0 = nt * 128;
    int wm = wid & 3, wn = wid >> 2;

    float acc[2][8][4];
#pragma unroll
    for (int i = 0; i < 2; i++)
#pragma unroll
        for (int j = 0; j < 8; j++)
#pragma unroll
            for (int r = 0; r < 4; r++) acc[i][j][r] = 0.f;

    uint32_t a_base = smem_u32(Asm);
    uint32_t b_base0 = smem_u32(Bsm0);
    uint32_t a_loff = (uint32_t)((wm * 32 + (lane & 15)) * 144 + (lane >> 4) * 16);
    uint32_t b_loff = (uint32_t)(((lane & 7) + ((lane >> 4) << 3)) * 144 + ((lane >> 3) & 1) * 16);
    size_t rowb = (size_t)(b * 128) * HW + y * 256 + x0;

    {
        const float4* wsrc = (const float4*)(g_wP + (size_t)(mt * 4) * 18432);
#pragma unroll
        for (int i = 0; i < 9; i++) cpa16(a_base + (t + (i << 8)) * 16, wsrc + t + (i << 8));
        proj_fillB(Bsm0, t, rowb, 0);
        cpa_wait();
        __syncthreads();
    }
    for (int s = 0; s < 4; s++) {
        int cur = s & 1;
        if (s < 3) proj_fillB(cur ? Bsm0 : Bsm1, t, rowb, s + 1);
        uint32_t bb = b_base0 + cur * 36864;
        MMA_CONSUME(bb);
        __syncthreads();
        if (s < 3) {
            const float4* wsrc = (const float4*)(g_wP + (size_t)(mt * 4 + s + 1) * 18432);
#pragma unroll
            for (int i = 0; i < 9; i++) cpa16(a_base + (t + (i << 8)) * 16, wsrc + t + (i << 8));
            cpa_wait();
            __syncthreads();
        }
    }

    int g = lane >> 2, tq = lane & 3;
#pragma unroll
    for (int ma = 0; ma < 2; ma++) {
        int o_base = mt * 128 + wm * 32 + ma * 16;
        int o0 = o_base + g, o1 = o_base + g + 8;
        float* r0 = out + (size_t)(b * 256 + o0) * HW + y * 256;
        float* r1 = out + (size_t)(b * 256 + o1) * HW + y * 256;
#pragma unroll
        for (int na = 0; na < 8; na++) {
            int xq = x0 + wn * 64 + na * 8 + tq * 2;
            float2 w0; w0.x = acc[ma][na][0]; w0.y = acc[ma][na][1];
            float2 w1; w1.x = acc[ma][na][2]; w1.y = acc[ma][na][3];
            *(float2*)(r0 + xq) = w0;
            *(float2*)(r1 + xq) = w1;
        }
    }
}

// ---------------- launch ----------------------------------------------------
extern "C" void kernel_launch(void* const* d_in, const int* in_sizes, int n_in,
                              void* d_out, int out_size) {
    const float* x     = (const float*)d_in[0];
    const float* wqkv  = (const float*)d_in[1];
    const float* rel   = (const float*)d_in[2];
    const float* w_ax  = (const float*)d_in[3];
    const float* b_ax  = (const float*)d_in[4];
    const float* w_ay  = (const float*)d_in[5];
    const float* b_ay  = (const float*)d_in[6];
    const float* w_dw  = (const float*)d_in[7];
    const float* gm    = (const float*)d_in[8];
    const float* bt    = (const float*)d_in[9];
    const float* mn    = (const float*)d_in[10];
    const float* vr    = (const float*)d_in[11];
    const float* w_pr  = (const float*)d_in[12];
    float* out = (float*)d_out;

    cudaFuncSetAttribute(conv2_mma_kernel, cudaFuncAttributeMaxDynamicSharedMemorySize, 110592);
    cudaFuncSetAttribute(qkv_mma_kernel, cudaFuncAttributeMaxDynamicSharedMemorySize, 110592);
    cudaFuncSetAttribute(proj_mma_kernel, cudaFuncAttributeMaxDynamicSharedMemorySize, 110592);

    aprep_kernel<<<4096, 256>>>(w_ax, w_ay);
    qprep_kernel<<<768, 256>>>(wqkv);
    pprep_kernel<<<256, 256>>>(w_pr);
    xprep_kernel<<<65536, 256>>>(x);
    qkv_mma_kernel<<<dim3(256, 2, 12), 256, 110592>>>();
    attn_kernel<<<dim3(2048, 16), 64>>>(rel);
    conv2_mma_kernel<<<dim3(256, 2, 4), 256, 110592>>>(b_ax, b_ay);
    dwbn_kernel<<<dim3(64, 128, 2), 256>>>(w_dw, gm, bt, mn, vr);
    proj_mma_kernel<<<dim3(256, 2, 4), 256, 110592>>>(out);
}

// round 10
// speedup vs baseline: 1.4534x; 1.4534x over previous
#include <cuda_runtime.h>
#include <cuda_bf16.h>
#include <cstdint>

#define HW 65536
#define CC 256

// ---------------- scratch ---------------------------------------------------
__device__ float g_big[100663296];
__device__ float g_obn[33554432];
// conv weights as per-lane A-frag blocks: (((mt*64+s)*4+wm)*32+lane)*128 elems
__device__ __align__(16) __nv_bfloat16 g_wA[2359296];
__device__ __align__(16) __nv_bfloat16 g_wQ[442368];
__device__ __align__(16) __nv_bfloat16 g_wP[147456];
__device__ __align__(16) __nv_bfloat16 g_xsplit[67108864];

// ---------------- helpers ---------------------------------------------------
__device__ __forceinline__ uint32_t smem_u32(const void* p) {
    uint32_t a;
    asm("{ .reg .u64 t; cvta.to.shared.u64 t, %1; cvt.u32.u64 %0, t; }" : "=r"(a) : "l"(p));
    return a;
}
__device__ __forceinline__ void ldsm4(uint32_t& r0, uint32_t& r1, uint32_t& r2, uint32_t& r3,
                                      uint32_t addr) {
    asm volatile("ldmatrix.sync.aligned.m8n8.x4.shared.b16 {%0,%1,%2,%3}, [%4];"
                 : "=r"(r0), "=r"(r1), "=r"(r2), "=r"(r3) : "r"(addr));
}
__device__ __forceinline__ void ldsm4t(uint32_t& r0, uint32_t& r1, uint32_t& r2, uint32_t& r3,
                                       uint32_t addr) {
    asm volatile("ldmatrix.sync.aligned.m8n8.x4.trans.shared.b16 {%0,%1,%2,%3}, [%4];"
                 : "=r"(r0), "=r"(r1), "=r"(r2), "=r"(r3) : "r"(addr));
}
__device__ __forceinline__ void mma16816(float* c, uint32_t a0, uint32_t a1, uint32_t a2,
                                         uint32_t a3, uint32_t b0, uint32_t b1) {
    asm volatile("mma.sync.aligned.m16n8k16.row.col.f32.bf16.bf16.f32 "
                 "{%0,%1,%2,%3}, {%4,%5,%6,%7}, {%8,%9}, {%0,%1,%2,%3};"
                 : "+f"(c[0]), "+f"(c[1]), "+f"(c[2]), "+f"(c[3])
                 : "r"(a0), "r"(a1), "r"(a2), "r"(a3), "r"(b0), "r"(b1));
}
__device__ __forceinline__ void split2(float v0, float v1, __nv_bfloat162& ph, __nv_bfloat162& pl) {
    __nv_bfloat16 h0 = __float2bfloat16(v0), h1 = __float2bfloat16(v1);
    ph.x = h0; ph.y = h1;
    pl.x = __float2bfloat16(v0 - __bfloat162float(h0));
    pl.y = __float2bfloat16(v1 - __bfloat162float(h1));
}
__device__ __forceinline__ void cpa16(uint32_t dst, const void* src) {
    asm volatile("cp.async.cg.shared.global [%0], [%1], 16;" :: "r"(dst), "l"(src));
}
__device__ __forceinline__ void cpa16z(uint32_t dst, const void* src, int sz) {
    asm volatile("cp.async.cg.shared.global [%0], [%1], 16, %2;" :: "r"(dst), "l"(src), "r"(sz));
}
__device__ __forceinline__ void cpa_commit() {
    asm volatile("cp.async.commit_group;");
}
__device__ __forceinline__ void cpa_wait() {
    asm volatile("cp.async.wait_group 0;" ::: "memory");
}

// ---------------- weight/input prep kernels --------------------------------
// conv weights -> per-lane A-frag blocks (hi 64 elems, lo 64 elems per lane/stage)
__global__ void aprep_kernel(const float* __restrict__ wx, const float* __restrict__ wy) {
    int e = blockIdx.x * 256 + threadIdx.x;     // < 2097152
    if (e >= 2097152) return;
    int j = e & 7, kstep = (e >> 3) & 3, ma = (e >> 5) & 1, plane = (e >> 6) & 1;
    int lane = (e >> 7) & 31, wm = (e >> 12) & 3, s = (e >> 14) & 63, mt = (e >> 20) & 1;
    int r = wm * 32 + ma * 16 + (lane >> 2) + 8 * ((j >> 1) & 1);
    int c = kstep * 16 + (lane & 3) * 2 + (j & 1) + 8 * (j >> 2);   // k in [0,64)
    int c_l = c >> 4, conv = (c >> 3) & 1, tap = c & 7;
    int o = mt * 128 + r;
    int ch = 4 * s + c_l;
    float v = (conv ? wy : wx)[(o * 256 + ch) * 8 + tap];
    __nv_bfloat16 h = __float2bfloat16(v);
    __nv_bfloat16 l = __float2bfloat16(v - __bfloat162float(h));
    g_wA[e] = plane ? l : h;
}
__global__ void qprep_kernel(const float* __restrict__ wqkv) {
    int e = blockIdx.x * 256 + threadIdx.x;
    if (e >= 196608) return;
    int k = e & 63, o_l = (e >> 6) & 127, s = (e >> 13) & 3, mt = e >> 15;
    float v = wqkv[(mt * 128 + o_l) * 256 + s * 64 + k];
    __nv_bfloat16 h = __float2bfloat16(v);
    __nv_bfloat16 l = __float2bfloat16(v - __bfloat162float(h));
    size_t base = (size_t)(mt * 4 + s) * 18432;
    g_wQ[base + o_l * 72 + k] = h;
    g_wQ[base + 9216 + o_l * 72 + k] = l;
}
__global__ void pprep_kernel(const float* __restrict__ wp) {
    int e = blockIdx.x * 256 + threadIdx.x;
    int k = e & 63, o_l = (e >> 6) & 127, s = (e >> 13) & 3, mt = e >> 15;
    float v = wp[(mt * 128 + o_l) * 256 + s * 64 + k];
    __nv_bfloat16 h = __float2bfloat16(v);
    __nv_bfloat16 l = __float2bfloat16(v - __bfloat162float(h));
    size_t base = (size_t)(mt * 4 + s) * 18432;
    g_wP[base + o_l * 72 + k] = h;
    g_wP[base + 9216 + o_l * 72 + k] = l;
}
__global__ void xprep_kernel(const float* __restrict__ x) {
    int g = blockIdx.x * 256 + threadIdx.x;
    int pos = g & (HW - 1);
    int cpb = g >> 16;
    const float* src = x + (size_t)(2 * cpb) * HW + pos;
    float v0 = src[0], v1 = src[HW];
    __nv_bfloat162 h, l;
    split2(v0, v1, h, l);
    ((__nv_bfloat162*)g_xsplit)[g] = h;
    ((__nv_bfloat162*)g_xsplit)[g + 16777216] = l;
}

// ---------------- shared mma consume for qkv/proj ([n][k] layout) -----------
#define MMA_CONSUME(BBASE)                                                               \
    do {                                                                                 \
        _Pragma("unroll")                                                                \
        for (int kstep = 0; kstep < 4; kstep++) {                                        \
            uint32_t ah[2][4], al[2][4];                                                 \
            _Pragma("unroll")                                                            \
            for (int ma = 0; ma < 2; ma++) {                                             \
                uint32_t aaddr = a_base + a_loff + ma * 16 * 144 + kstep * 32;           \
                ldsm4(ah[ma][0], ah[ma][1], ah[ma][2], ah[ma][3], aaddr);                \
                ldsm4(al[ma][0], al[ma][1], al[ma][2], al[ma][3], aaddr + 18432);        \
            }                                                                            \
            _Pragma("unroll")                                                            \
            for (int nc = 0; nc < 4; nc++) {                                             \
                uint32_t baddr = (BBASE) + b_loff + (wn * 64 + nc * 16) * 144 + kstep * 32; \
                uint32_t bh0, bh1, bh2, bh3, bl0, bl1, bl2, bl3;                         \
                ldsm4(bh0, bh1, bh2, bh3, baddr);                                        \
                ldsm4(bl0, bl1, bl2, bl3, baddr + 18432);                                \
                _Pragma("unroll")                                                        \
                for (int ma = 0; ma < 2; ma++) {                                         \
                    mma16816(acc[ma][nc * 2 + 0], ah[ma][0], ah[ma][1], ah[ma][2], ah[ma][3], bh0, bh1); \
                    mma16816(acc[ma][nc * 2 + 1], ah[ma][0], ah[ma][1], ah[ma][2], ah[ma][3], bh2, bh3); \
                    mma16816(acc[ma][nc * 2 + 0], ah[ma][0], ah[ma][1], ah[ma][2], ah[ma][3], bl0, bl1); \
                    mma16816(acc[ma][nc * 2 + 1], ah[ma][0], ah[ma][1], ah[ma][2], ah[ma][3], bl2, bl3); \
                    mma16816(acc[ma][nc * 2 + 0], al[ma][0], al[ma][1], al[ma][2], al[ma][3], bh0, bh1); \
                    mma16816(acc[ma][nc * 2 + 1], al[ma][0], al[ma][1], al[ma][2], al[ma][3], bh2, bh3); \
                }                                                                        \
            }                                                                            \
        }                                                                                \
    } while (0)

// ---------------- kernel A: qkv via mma (R8 form) ---------------------------
__global__ void __launch_bounds__(256, 2) qkv_mma_kernel() {
    extern __shared__ __align__(16) char dsm[];
    __nv_bfloat16* Asm = (__nv_bfloat16*)dsm;
    __nv_bfloat16* Bsm = (__nv_bfloat16*)(dsm + 36864);
    int t = threadIdx.x, wid = t >> 5, lane = t & 31;
    int y = blockIdx.x, b = blockIdx.y, z = blockIdx.z;
    int mt = z >> 1, nt = z & 1;
    int x0 = nt * 128;
    int wm = wid & 3, wn = wid >> 2;

    float acc[2][8][4];
#pragma unroll
    for (int i = 0; i < 2; i++)
#pragma unroll
        for (int j = 0; j < 8; j++)
#pragma unroll
            for (int r = 0; r < 4; r++) acc[i][j][r] = 0.f;

    uint32_t a_base = smem_u32(Asm);
    uint32_t b_base = smem_u32(Bsm);
    uint32_t a_loff = (uint32_t)((wm * 32 + (lane & 15)) * 144 + (lane >> 4) * 16);
    uint32_t b_loff = (uint32_t)(((lane & 7) + ((lane >> 4) << 3)) * 144 + ((lane >> 3) & 1) * 16);

    const __nv_bfloat162* xph = (const __nv_bfloat162*)g_xsplit;
    const __nv_bfloat162* xpl = xph + 16777216;
    size_t rowb = (size_t)(b * 128) * HW + y * 256 + x0;

    for (int s = 0; s < 4; s++) {
        const float4* wsrc = (const float4*)(g_wQ + (size_t)(mt * 4 + s) * 18432);
#pragma unroll
        for (int i = 0; i < 9; i++) cpa16(a_base + (t + (i << 8)) * 16, wsrc + t + (i << 8));

        int cp0 = s * 32;
#pragma unroll
        for (int i = 0; i < 16; i++) {
            int id = t + (i << 8);
            int xl = id & 127, j = id >> 7;
            size_t g = rowb + (size_t)(cp0 + j) * HW + xl;
            int idx = xl * 72 + 2 * j;
            *(__nv_bfloat162*)(Bsm + idx) = xph[g];
            *(__nv_bfloat162*)(Bsm + 9216 + idx) = xpl[g];
        }
        cpa_commit();
        cpa_wait();
        __syncthreads();
        MMA_CONSUME(b_base);
        __syncthreads();
    }

    int g = lane >> 2, tq = lane & 3;
    int win_row = b * 1024 + (y >> 3) * 32;
    int tokb = (y & 7) * 8;
#pragma unroll
    for (int ma = 0; ma < 2; ma++) {
        int o_a = mt * 128 + wm * 32 + ma * 16 + g;
        int o_b = o_a + 8;
        int sel_a = o_a >> 8, h_a = (o_a >> 4) & 15, dd_a = o_a & 15;
        int sel_b = o_b >> 8, h_b = (o_b >> 4) & 15, dd_b = o_b & 15;
#pragma unroll
        for (int na = 0; na < 8; na++) {
            int xq = x0 + wn * 64 + na * 8 + tq * 2;
            int win = win_row + (xq >> 3);
            int tok = tokb + (xq & 7);
            size_t pa = (size_t)sel_a * 33554432 + (size_t)((win * 16 + h_a) * 64 + tok) * 16 + dd_a;
            size_t pb = (size_t)sel_b * 33554432 + (size_t)((win * 16 + h_b) * 64 + tok) * 16 + dd_b;
            g_big[pa] = acc[ma][na][0];
            g_big[pa + 16] = acc[ma][na][1];
            g_big[pb] = acc[ma][na][2];
            g_big[pb + 16] = acc[ma][na][3];
        }
    }
}

// ---------------- kernel B: window attention (writes split planes) ---------
__global__ void __launch_bounds__(64) attn_kernel(const float* __restrict__ rel_table) {
    __shared__ float ks[1024], vs[1024], bs[232];
    int t = threadIdx.x;
    int w = blockIdx.x;
    int h = blockIdx.y;
    size_t base = ((size_t)(w * 16 + h)) * 1024;
    const float* gq = g_big;
    const float* gk = g_big + 33554432;
    const float* gv = g_big + 67108864;
#pragma unroll
    for (int i = 0; i < 4; i++) {
        *(float4*)(ks + t * 16 + i * 4) = *(const float4*)(gk + base + t * 16 + i * 4);
        *(float4*)(vs + t * 16 + i * 4) = *(const float4*)(gv + base + t * 16 + i * 4);
    }
    for (int r = t; r < 225; r += 64) bs[r] = rel_table[r * 16 + h];
    __syncthreads();

    float q[16];
#pragma unroll
    for (int i = 0; i < 4; i++)
        *(float4*)(q + i * 4) = *(const float4*)(gq + base + t * 16 + i * 4);
    int i1 = t >> 3, i2 = t & 7;

    float d[64];
#pragma unroll
    for (int j = 0; j < 64; j++) {
        const float4* kp = (const float4*)(ks + j * 16);
        float4 k0 = kp[0], k1 = kp[1], k2 = kp[2], k3 = kp[3];
        float s = q[0] * k0.x + q[1] * k0.y + q[2] * k0.z + q[3] * k0.w +
                  q[4] * k1.x + q[5] * k1.y + q[6] * k1.z + q[7] * k1.w +
                  q[8] * k2.x + q[9] * k2.y + q[10] * k2.z + q[11] * k2.w +
                  q[12] * k3.x + q[13] * k3.y + q[14] * k3.z + q[15] * k3.w;
        int j1 = j >> 3, j2 = j & 7;
        d[j] = 0.25f * s + bs[(i1 - j1 + 7) * 15 + (i2 - j2 + 7)];
    }
    float m = -1e30f;
#pragma unroll
    for (int j = 0; j < 64; j++) m = fmaxf(m, d[j]);
    float sum = 0.f;
#pragma unroll
    for (int j = 0; j < 64; j++) { d[j] = __expf(d[j] - m); sum += d[j]; }
    float inv = 1.0f / sum;

    float acc[16] = {};
#pragma unroll
    for (int j = 0; j < 64; j++) {
        float a = d[j] * inv;
        const float4* vp = (const float4*)(vs + j * 16);
        float4 v0 = vp[0], v1 = vp[1], v2 = vp[2], v3 = vp[3];
        acc[0] += a * v0.x;  acc[1] += a * v0.y;  acc[2] += a * v0.z;  acc[3] += a * v0.w;
        acc[4] += a * v1.x;  acc[5] += a * v1.y;  acc[6] += a * v1.z;  acc[7] += a * v1.w;
        acc[8] += a * v2.x;  acc[9] += a * v2.y;  acc[10] += a * v2.z; acc[11] += a * v2.w;
        acc[12] += a * v3.x; acc[13] += a * v3.y; acc[14] += a * v3.z; acc[15] += a * v3.w;
    }
    int b = w >> 10, wy = (w >> 5) & 31, wx = w & 31;
    int y = wy * 8 + i1, xq = wx * 8 + i2;
    __nv_bfloat16* ophi = (__nv_bfloat16*)g_obn;
    __nv_bfloat16* oplo = ophi + 33554432;
    size_t ob = ((size_t)(b * 256 + h * 16)) * HW + y * 256 + xq;
#pragma unroll
    for (int e = 0; e < 16; e++) {
        float v = acc[e];
        __nv_bfloat16 hh = __float2bfloat16(v);
        ophi[ob + (size_t)e * HW] = hh;
        oplo[ob + (size_t)e * HW] = __float2bfloat16(v - __bfloat162float(hh));
    }
}

// ---------------- kernel C: conv2 — regs-A + [k][n] B + async pipeline -----
__device__ __forceinline__ __nv_bfloat16 ldpb(const __nv_bfloat16* p, int r, int q) {
    if ((unsigned)r > 256u || (unsigned)q > 256u) return __float2bfloat16(0.f);
    return p[((r == 256) ? 254 : r) * 256 + ((q == 256) ? 254 : q)];
}

// B buffer: 128 rows (hi k0-63, lo k64-127) x 272 B  => 34816 B
#define BROW 272
#define BBUF 34816

__device__ __forceinline__ void conv_vert_cpasync(uint32_t bdst, int t, size_t cbase,
                                                  int y, int x0, int ss) {
    const __nv_bfloat16* ophi = (const __nv_bfloat16*)g_obn;
    const __nv_bfloat16* oplo = ophi + 33554432;
#pragma unroll
    for (int i = 0; i < 4; i++) {
        int id = t + (i << 8);
        int chunk = id & 15, u = id >> 4;
        int c_l = u >> 4, tap = (u >> 1) & 7, p = u & 1;
        int k = c_l * 16 + tap;
        int gr = y - 3 + tap;
        int valid = (gr >= 0 && gr <= 256);
        int rr = (gr == 256) ? 254 : (valid ? gr : 0);
        const __nv_bfloat16* src = (p ? oplo : ophi) + cbase +
                                   (size_t)(4 * ss + c_l) * HW + rr * 256 + x0 + chunk * 8;
        cpa16z(bdst + (p * 64 + k) * BROW + chunk * 16, src, valid ? 16 : 0);
    }
}

__device__ __forceinline__ void conv_horiz_load(__nv_bfloat162* hr, int t, size_t cbase,
                                                int y, int x0, int ss) {
    const __nv_bfloat16* ophi = (const __nv_bfloat16*)g_obn;
    const __nv_bfloat16* oplo = ophi + 33554432;
#pragma unroll
    for (int i = 0; i < 16; i++) {
        int id = t + (i << 8);
        int m = id & 63, u = id >> 6;
        int c_l = u >> 4, tap = (u >> 1) & 7, p = u & 1;
        const __nv_bfloat16* cp_ = (p ? oplo : ophi) + cbase + (size_t)(4 * ss + c_l) * HW;
        int gc = x0 + 2 * m + tap - 3;
        __nv_bfloat162 v;
        v.x = ldpb(cp_, y, gc);
        v.y = ldpb(cp_, y, gc + 1);
        hr[i] = v;
    }
}

__device__ __forceinline__ void conv_horiz_store(char* bptr, const __nv_bfloat162* hr, int t) {
#pragma unroll
    for (int i = 0; i < 16; i++) {
        int id = t + (i << 8);
        int m = id & 63, u = id >> 6;
        int c_l = u >> 4, tap = (u >> 1) & 7, p = u & 1;
        *(__nv_bfloat162*)(bptr + (p * 64 + c_l * 16 + 8 + tap) * BROW + m * 4) = hr[i];
    }
}

__global__ void __launch_bounds__(256, 2) conv2_mma_kernel(const float* __restrict__ bias_x,
                                                           const float* __restrict__ bias_y) {
    extern __shared__ __align__(16) char dsm[];
    int t = threadIdx.x, wid = t >> 5, lane = t & 31;
    int y = blockIdx.x, b = blockIdx.y, z = blockIdx.z;
    int mt = z >> 1, nt = z & 1;
    int x0 = nt * 128;
    int wm = wid & 3, wn = wid >> 2;
    size_t cbase = (size_t)b * CC * HW;

    float acc[2][8][4];
#pragma unroll
    for (int i = 0; i < 2; i++)
#pragma unroll
        for (int j = 0; j < 8; j++)
#pragma unroll
            for (int r = 0; r < 4; r++) acc[i][j][r] = 0.f;

    uint32_t b_base0 = smem_u32(dsm);
    // ldmatrix.trans lane offsets: lanes0-15 -> k rows, lanes16-31 -> +8 cols
    uint32_t b_loff = (uint32_t)((lane & 15) * BROW + (lane >> 4) * 16);
    __nv_bfloat162 hr[16];

    // prologue: stage 0
    conv_vert_cpasync(b_base0, t, cbase, y, x0, 0);
    cpa_commit();
    conv_horiz_load(hr, t, cbase, y, x0, 0);
    cpa_wait();
    conv_horiz_store(dsm, hr, t);
    __syncthreads();

    for (int s = 0; s < 64; s++) {
        int cur = s & 1;
        uint32_t curbuf = b_base0 + cur * BBUF;
        char* altptr = dsm + (cur ^ 1) * BBUF;
        uint32_t altbuf = b_base0 + (cur ^ 1) * BBUF;
        if (s < 63) {
            conv_vert_cpasync(altbuf, t, cbase, y, x0, s + 1);
            cpa_commit();
            conv_horiz_load(hr, t, cbase, y, x0, s + 1);
        }
        // A-frags direct from global (per-lane packed blocks), MMA
        const uint4* ap = (const uint4*)(g_wA +
                          (size_t)((((mt * 64 + s) * 4 + wm) * 32 + lane)) * 128);
#pragma unroll
        for (int kstep = 0; kstep < 4; kstep++) {
            uint4 h0 = ap[kstep], h1 = ap[4 + kstep];
            uint4 l0 = ap[8 + kstep], l1 = ap[12 + kstep];
#pragma unroll
            for (int nc = 0; nc < 4; nc++) {
                uint32_t baddr = curbuf + b_loff + kstep * (16 * BROW) + (wn * 64 + nc * 16) * 2;
                uint32_t bh0, bh1, bh2, bh3, bl0, bl1, bl2, bl3;
                ldsm4t(bh0, bh1, bh2, bh3, baddr);
                ldsm4t(bl0, bl1, bl2, bl3, baddr + 64 * BROW);
                mma16816(acc[0][nc * 2 + 0], h0.x, h0.y, h0.z, h0.w, bh0, bh1);
                mma16816(acc[0][nc * 2 + 1], h0.x, h0.y, h0.z, h0.w, bh2, bh3);
                mma16816(acc[1][nc * 2 + 0], h1.x, h1.y, h1.z, h1.w, bh0, bh1);
                mma16816(acc[1][nc * 2 + 1], h1.x, h1.y, h1.z, h1.w, bh2, bh3);
                mma16816(acc[0][nc * 2 + 0], h0.x, h0.y, h0.z, h0.w, bl0, bl1);
                mma16816(acc[0][nc * 2 + 1], h0.x, h0.y, h0.z, h0.w, bl2, bl3);
                mma16816(acc[1][nc * 2 + 0], h1.x, h1.y, h1.z, h1.w, bl0, bl1);
                mma16816(acc[1][nc * 2 + 1], h1.x, h1.y, h1.z, h1.w, bl2, bl3);
                mma16816(acc[0][nc * 2 + 0], l0.x, l0.y, l0.z, l0.w, bh0, bh1);
                mma16816(acc[0][nc * 2 + 1], l0.x, l0.y, l0.z, l0.w, bh2, bh3);
                mma16816(acc[1][nc * 2 + 0], l1.x, l1.y, l1.z, l1.w, bh0, bh1);
                mma16816(acc[1][nc * 2 + 1], l1.x, l1.y, l1.z, l1.w, bh2, bh3);
            }
        }
        if (s < 63) {
            conv_horiz_store(altptr, hr, t);
            cpa_wait();
        }
        __syncthreads();
    }

    // epilogue: bias + float2 stores
    float* out1 = g_big;
    int g = lane >> 2, tq = lane & 3;
#pragma unroll
    for (int ma = 0; ma < 2; ma++) {
        int o_base = mt * 128 + wm * 32 + ma * 16;
        int o0 = o_base + g, o1 = o_base + g + 8;
        float bia0 = bias_x[o0] + bias_y[o0];
        float bia1 = bias_x[o1] + bias_y[o1];
        float* r0 = out1 + (size_t)(b * 256 + o0) * HW + y * 256;
        float* r1 = out1 + (size_t)(b * 256 + o1) * HW + y * 256;
#pragma unroll
        for (int na = 0; na < 8; na++) {
            int xq = x0 + wn * 64 + na * 8 + tq * 2;
            float2 w0; w0.x = acc[ma][na][0] + bia0; w0.y = acc[ma][na][1] + bia0;
            float2 w1; w1.x = acc[ma][na][2] + bia1; w1.y = acc[ma][na][3] + bia1;
            *(float2*)(r0 + xq) = w0;
            *(float2*)(r1 + xq) = w1;
        }
    }
}

// ---------------- kernel D: depthwise 8x8 + BN, channel-paired split out ---
__global__ void __launch_bounds__(256) dwbn_kernel(const float* __restrict__ wdw,
                                                   const float* __restrict__ gamma,
                                                   const float* __restrict__ beta,
                                                   const float* __restrict__ mean,
                                                   const float* __restrict__ var) {
    __shared__ float S[2][1560];
    __shared__ float ws[128];
    int t = threadIdx.x;
    int tile = blockIdx.x;
    int cp = blockIdx.y, b = blockIdx.z;
    int c0 = 2 * cp;
    int y0 = (tile >> 3) * 32, x0 = (tile & 7) * 32;
#pragma unroll
    for (int ch = 0; ch < 2; ch++) {
        const float* in = g_big + ((size_t)(b * 256 + c0 + ch)) * HW;
        for (int e = t; e < 39 * 39; e += 256) {
            int r = e / 39, j = e - r * 39;
            int row = y0 - 3 + r, col = x0 - 3 + j;
            float v = 0.f;
            if (row >= 0 && row <= 256 && col >= 0 && col <= 256) {
                int rr = (row == 256) ? 254 : row;
                int cc = (col == 256) ? 254 : col;
                v = in[rr * 256 + cc];
            }
            S[ch][r * 40 + j] = v;
        }
    }
    if (t < 128) ws[t] = wdw[c0 * 64 + t];
    __syncthreads();

    int ly = t >> 3, lx0 = (t & 7) * 4;
    float acc[2][4] = {};
#pragma unroll
    for (int ch = 0; ch < 2; ch++) {
#pragma unroll
        for (int ky = 0; ky < 8; ky++) {
            float rv[11];
#pragma unroll
            for (int u = 0; u < 11; u++) rv[u] = S[ch][(ly + ky) * 40 + lx0 + u];
#pragma unroll
            for (int kx = 0; kx < 8; kx++) {
                float wv = ws[ch * 64 + ky * 8 + kx];
#pragma unroll
                for (int j = 0; j < 4; j++) acc[ch][j] += wv * rv[kx + j];
            }
        }
    }
    float iv0 = rsqrtf(var[c0] + 1e-5f), iv1 = rsqrtf(var[c0 + 1] + 1e-5f);
    float sc0 = gamma[c0] * iv0, sc1 = gamma[c0 + 1] * iv1;
    float sh0 = beta[c0] - mean[c0] * sc0, sh1 = beta[c0 + 1] - mean[c0 + 1] * sc1;
    __nv_bfloat162* oh = (__nv_bfloat162*)g_obn;
    __nv_bfloat162* ol = oh + 16777216;
    size_t g = ((size_t)(b * 128 + cp)) * HW + (y0 + ly) * 256 + x0 + lx0;
#pragma unroll
    for (int j = 0; j < 4; j++) {
        float u0 = acc[0][j] * sc0 + sh0;
        float u1 = acc[1][j] * sc1 + sh1;
        __nv_bfloat162 hh, ll;
        split2(u0, u1, hh, ll);
        oh[g + j] = hh;
        ol[g + j] = ll;
    }
}

// ---------------- kernel E: proj via mma -> d_out (R8 form) -----------------
__global__ void __launch_bounds__(256, 2) proj_mma_kernel(float* __restrict__ out) {
    extern __shared__ __align__(16) char dsm[];
    __nv_bfloat16* Asm = (__nv_bfloat16*)dsm;
    __nv_bfloat16* Bsm = (__nv_bfloat16*)(dsm + 36864);
    int t = threadIdx.x, wid = t >> 5, lane = t & 31;
    int y = blockIdx.x, b = blockIdx.y, z = blockIdx.z;
    int mt = z >> 1, nt = z & 1;
    int x0 = nt * 128;
    int wm = wid & 3, wn = wid >> 2;

    float acc[2][8][4];
#pragma unroll
    for (int i = 0; i < 2; i++)
#pragma unroll
        for (int j = 0; j < 8; j++)
#pragma unroll
            for (int r = 0; r < 4; r++) acc[i][j][r] = 0.f;

    uint32_t a_base = smem_u32(Asm);
    uint32_t b_base = smem_u32(Bsm);
    uint32_t a_loff = (uint32_t)((wm * 32 + (lane & 15)) * 144 + (lane >> 4) * 16);
    uint32_t b_loff = (uint32_t)(((lane & 7) + ((lane >> 4) << 3)) * 144 + ((lane >> 3) & 1) * 16);

    const __nv_bfloat162* dph = (const __nv_bfloat162*)g_obn;
    const __nv_bfloat162* dpl = dph + 16777216;
    size_t rowb = (size_t)(b * 128) * HW + y * 256 + x0;

    for (int s = 0; s < 4; s++) {
        const float4* wsrc = (const float4*)(g_wP + (size_t)(mt * 4 + s) * 18432);
#pragma unroll
        for (int i = 0; i < 9; i++) cpa16(a_base + (t + (i << 8)) * 16, wsrc + t + (i << 8));

        int cp0 = s * 32;
#pragma unroll
        for (int i = 0; i < 16; i++) {
            int id = t + (i << 8);
            int xl = id & 127, j = id >> 7;
            size_t g = rowb + (size_t)(cp0 + j) * HW + xl;
            int idx = xl * 72 + 2 * j;
            *(__nv_bfloat162*)(Bsm + idx) = dph[g];
            *(__nv_bfloat162*)(Bsm + 9216 + idx) = dpl[g];
        }
        cpa_commit();
        cpa_wait();
        __syncthreads();
        MMA_CONSUME(b_base);
        __syncthreads();
    }

    int g = lane >> 2, tq = lane & 3;
#pragma unroll
    for (int ma = 0; ma < 2; ma++) {
        int o_base = mt * 128 + wm * 32 + ma * 16;
        int o0 = o_base + g, o1 = o_base + g + 8;
        float* r0 = out + (size_t)(b * 256 + o0) * HW + y * 256;
        float* r1 = out + (size_t)(b * 256 + o1) * HW + y * 256;
#pragma unroll
        for (int na = 0; na < 8; na++) {
            int xq = x0 + wn * 64 + na * 8 + tq * 2;
            float2 w0; w0.x = acc[ma][na][0]; w0.y = acc[ma][na][1];
            float2 w1; w1.x = acc[ma][na][2]; w1.y = acc[ma][na][3];
            *(float2*)(r0 + xq) = w0;
            *(float2*)(r1 + xq) = w1;
        }
    }
}

// ---------------- launch ----------------------------------------------------
extern "C" void kernel_launch(void* const* d_in, const int* in_sizes, int n_in,
                              void* d_out, int out_size) {
    const float* x     = (const float*)d_in[0];
    const float* wqkv  = (const float*)d_in[1];
    const float* rel   = (const float*)d_in[2];
    const float* w_ax  = (const float*)d_in[3];
    const float* b_ax  = (const float*)d_in[4];
    const float* w_ay  = (const float*)d_in[5];
    const float* b_ay  = (const float*)d_in[6];
    const float* w_dw  = (const float*)d_in[7];
    const float* gm    = (const float*)d_in[8];
    const float* bt    = (const float*)d_in[9];
    const float* mn    = (const float*)d_in[10];
    const float* vr    = (const float*)d_in[11];
    const float* w_pr  = (const float*)d_in[12];
    float* out = (float*)d_out;

    cudaFuncSetAttribute(conv2_mma_kernel, cudaFuncAttributeMaxDynamicSharedMemorySize, 2 * BBUF);
    cudaFuncSetAttribute(qkv_mma_kernel, cudaFuncAttributeMaxDynamicSharedMemorySize, 73728);
    cudaFuncSetAttribute(proj_mma_kernel, cudaFuncAttributeMaxDynamicSharedMemorySize, 73728);

    aprep_kernel<<<8192, 256>>>(w_ax, w_ay);
    qprep_kernel<<<768, 256>>>(wqkv);
    pprep_kernel<<<256, 256>>>(w_pr);
    xprep_kernel<<<65536, 256>>>(x);
    qkv_mma_kernel<<<dim3(256, 2, 12), 256, 73728>>>();
    attn_kernel<<<dim3(2048, 16), 64>>>(rel);
    conv2_mma_kernel<<<dim3(256, 2, 4), 256, 2 * BBUF>>>(b_ax, b_ay);
    dwbn_kernel<<<dim3(64, 128, 2), 256>>>(w_dw, gm, bt, mn, vr);
    proj_mma_kernel<<<dim3(256, 2, 4), 256, 73728>>>(out);
}

// round 11
// speedup vs baseline: 1.6834x; 1.1583x over previous
#include <cuda_runtime.h>
#include <cuda_bf16.h>
#include <cstdint>

#define HW 65536
#define CC 256

// ---------------- scratch ---------------------------------------------------
__device__ float g_big[100663296];
__device__ float g_obn[33554432];
// conv weights, pre-swizzled sub-stage tiles: per (mt, u of 128): hi[128o][32k] lo[...]
__device__ __align__(16) __nv_bfloat16 g_wA[2097152];
__device__ __align__(16) __nv_bfloat16 g_wQ[442368];
__device__ __align__(16) __nv_bfloat16 g_wP[147456];
__device__ __align__(16) __nv_bfloat16 g_xsplit[67108864];

// ---------------- helpers ---------------------------------------------------
__device__ __forceinline__ uint32_t smem_u32(const void* p) {
    uint32_t a;
    asm("{ .reg .u64 t; cvta.to.shared.u64 t, %1; cvt.u32.u64 %0, t; }" : "=r"(a) : "l"(p));
    return a;
}
__device__ __forceinline__ void ldsm4(uint32_t& r0, uint32_t& r1, uint32_t& r2, uint32_t& r3,
                                      uint32_t addr) {
    asm volatile("ldmatrix.sync.aligned.m8n8.x4.shared.b16 {%0,%1,%2,%3}, [%4];"
                 : "=r"(r0), "=r"(r1), "=r"(r2), "=r"(r3) : "r"(addr));
}
__device__ __forceinline__ void mma16816(float* c, uint32_t a0, uint32_t a1, uint32_t a2,
                                         uint32_t a3, uint32_t b0, uint32_t b1) {
    asm volatile("mma.sync.aligned.m16n8k16.row.col.f32.bf16.bf16.f32 "
                 "{%0,%1,%2,%3}, {%4,%5,%6,%7}, {%8,%9}, {%0,%1,%2,%3};"
                 : "+f"(c[0]), "+f"(c[1]), "+f"(c[2]), "+f"(c[3])
                 : "r"(a0), "r"(a1), "r"(a2), "r"(a3), "r"(b0), "r"(b1));
}
__device__ __forceinline__ void split2(float v0, float v1, __nv_bfloat162& ph, __nv_bfloat162& pl) {
    __nv_bfloat16 h0 = __float2bfloat16(v0), h1 = __float2bfloat16(v1);
    ph.x = h0; ph.y = h1;
    pl.x = __float2bfloat16(v0 - __bfloat162float(h0));
    pl.y = __float2bfloat16(v1 - __bfloat162float(h1));
}
__device__ __forceinline__ void cpa16(uint32_t dst, const void* src) {
    asm volatile("cp.async.cg.shared.global [%0], [%1], 16;" :: "r"(dst), "l"(src));
}
__device__ __forceinline__ void cpa_commit() {
    asm volatile("cp.async.commit_group;");
}
__device__ __forceinline__ void cpa_wait() {
    asm volatile("cp.async.wait_group 0;" ::: "memory");
}

// ---------------- weight/input prep kernels --------------------------------
// conv weights -> swizzled sub-stage tiles. e = mt*1048576 + u*8192 + plane*4096 + o*32 + k
__global__ void aprep_kernel(const float* __restrict__ wx, const float* __restrict__ wy) {
    int e = blockIdx.x * 256 + threadIdx.x;     // < 2097152
    if (e >= 2097152) return;
    int k = e & 31, o = (e >> 5) & 127, plane = (e >> 12) & 1;
    int u = (e >> 13) & 127, mt = e >> 20;
    int ch = 2 * u + (k >> 4);
    int conv = (k >> 3) & 1, tap = k & 7;
    float v = (conv ? wy : wx)[((mt * 128 + o) * 256 + ch) * 8 + tap];
    __nv_bfloat16 h = __float2bfloat16(v);
    __nv_bfloat16 l = __float2bfloat16(v - __bfloat162float(h));
    int c = k >> 3;
    int phys = o * 32 + (((c ^ ((o >> 1) & 3)) & 3) << 3) + (k & 7);
    size_t base = (size_t)(mt * 128 + u) * 8192 + plane * 4096;
    g_wA[base + phys] = plane ? l : h;
}
__global__ void qprep_kernel(const float* __restrict__ wqkv) {
    int e = blockIdx.x * 256 + threadIdx.x;
    if (e >= 196608) return;
    int k = e & 63, o_l = (e >> 6) & 127, s = (e >> 13) & 3, mt = e >> 15;
    float v = wqkv[(mt * 128 + o_l) * 256 + s * 64 + k];
    __nv_bfloat16 h = __float2bfloat16(v);
    __nv_bfloat16 l = __float2bfloat16(v - __bfloat162float(h));
    size_t base = (size_t)(mt * 4 + s) * 18432;
    g_wQ[base + o_l * 72 + k] = h;
    g_wQ[base + 9216 + o_l * 72 + k] = l;
}
__global__ void pprep_kernel(const float* __restrict__ wp) {
    int e = blockIdx.x * 256 + threadIdx.x;
    int k = e & 63, o_l = (e >> 6) & 127, s = (e >> 13) & 3, mt = e >> 15;
    float v = wp[(mt * 128 + o_l) * 256 + s * 64 + k];
    __nv_bfloat16 h = __float2bfloat16(v);
    __nv_bfloat16 l = __float2bfloat16(v - __bfloat162float(h));
    size_t base = (size_t)(mt * 4 + s) * 18432;
    g_wP[base + o_l * 72 + k] = h;
    g_wP[base + 9216 + o_l * 72 + k] = l;
}
__global__ void xprep_kernel(const float* __restrict__ x) {
    int g = blockIdx.x * 256 + threadIdx.x;
    int pos = g & (HW - 1);
    int cpb = g >> 16;
    const float* src = x + (size_t)(2 * cpb) * HW + pos;
    float v0 = src[0], v1 = src[HW];
    __nv_bfloat162 h, l;
    split2(v0, v1, h, l);
    ((__nv_bfloat162*)g_xsplit)[g] = h;
    ((__nv_bfloat162*)g_xsplit)[g + 16777216] = l;
}

// ---------------- shared mma consume for qkv/proj (R8, 144B rows) -----------
#define MMA_CONSUME(BBASE)                                                               \
    do {                                                                                 \
        _Pragma("unroll")                                                                \
        for (int kstep = 0; kstep < 4; kstep++) {                                        \
            uint32_t ah[2][4], al[2][4];                                                 \
            _Pragma("unroll")                                                            \
            for (int ma = 0; ma < 2; ma++) {                                             \
                uint32_t aaddr = a_base + a_loff + ma * 16 * 144 + kstep * 32;           \
                ldsm4(ah[ma][0], ah[ma][1], ah[ma][2], ah[ma][3], aaddr);                \
                ldsm4(al[ma][0], al[ma][1], al[ma][2], al[ma][3], aaddr + 18432);        \
            }                                                                            \
            _Pragma("unroll")                                                            \
            for (int nc = 0; nc < 4; nc++) {                                             \
                uint32_t baddr = (BBASE) + b_loff + (wn * 64 + nc * 16) * 144 + kstep * 32; \
                uint32_t bh0, bh1, bh2, bh3, bl0, bl1, bl2, bl3;                         \
                ldsm4(bh0, bh1, bh2, bh3, baddr);                                        \
                ldsm4(bl0, bl1, bl2, bl3, baddr + 18432);                                \
                _Pragma("unroll")                                                        \
                for (int ma = 0; ma < 2; ma++) {                                         \
                    mma16816(acc[ma][nc * 2 + 0], ah[ma][0], ah[ma][1], ah[ma][2], ah[ma][3], bh0, bh1); \
                    mma16816(acc[ma][nc * 2 + 1], ah[ma][0], ah[ma][1], ah[ma][2], ah[ma][3], bh2, bh3); \
                    mma16816(acc[ma][nc * 2 + 0], ah[ma][0], ah[ma][1], ah[ma][2], ah[ma][3], bl0, bl1); \
                    mma16816(acc[ma][nc * 2 + 1], ah[ma][0], ah[ma][1], ah[ma][2], ah[ma][3], bl2, bl3); \
                    mma16816(acc[ma][nc * 2 + 0], al[ma][0], al[ma][1], al[ma][2], al[ma][3], bh0, bh1); \
                    mma16816(acc[ma][nc * 2 + 1], al[ma][0], al[ma][1], al[ma][2], al[ma][3], bh2, bh3); \
                }                                                                        \
            }                                                                            \
        }                                                                                \
    } while (0)

// ---------------- kernel A: qkv via mma (exact R8) ---------------------------
__global__ void __launch_bounds__(256, 2) qkv_mma_kernel() {
    extern __shared__ __align__(16) char dsm[];
    __nv_bfloat16* Asm = (__nv_bfloat16*)dsm;
    __nv_bfloat16* Bsm = (__nv_bfloat16*)(dsm + 36864);
    int t = threadIdx.x, wid = t >> 5, lane = t & 31;
    int y = blockIdx.x, b = blockIdx.y, z = blockIdx.z;
    int mt = z >> 1, nt = z & 1;
    int x0 = nt * 128;
    int wm = wid & 3, wn = wid >> 2;

    float acc[2][8][4];
#pragma unroll
    for (int i = 0; i < 2; i++)
#pragma unroll
        for (int j = 0; j < 8; j++)
#pragma unroll
            for (int r = 0; r < 4; r++) acc[i][j][r] = 0.f;

    uint32_t a_base = smem_u32(Asm);
    uint32_t b_base = smem_u32(Bsm);
    uint32_t a_loff = (uint32_t)((wm * 32 + (lane & 15)) * 144 + (lane >> 4) * 16);
    uint32_t b_loff = (uint32_t)(((lane & 7) + ((lane >> 4) << 3)) * 144 + ((lane >> 3) & 1) * 16);

    const __nv_bfloat162* xph = (const __nv_bfloat162*)g_xsplit;
    const __nv_bfloat162* xpl = xph + 16777216;
    size_t rowb = (size_t)(b * 128) * HW + y * 256 + x0;

    for (int s = 0; s < 4; s++) {
        const float4* wsrc = (const float4*)(g_wQ + (size_t)(mt * 4 + s) * 18432);
#pragma unroll
        for (int i = 0; i < 9; i++) cpa16(a_base + (t + (i << 8)) * 16, wsrc + t + (i << 8));

        int cp0 = s * 32;
#pragma unroll
        for (int i = 0; i < 16; i++) {
            int id = t + (i << 8);
            int xl = id & 127, j = id >> 7;
            size_t g = rowb + (size_t)(cp0 + j) * HW + xl;
            int idx = xl * 72 + 2 * j;
            *(__nv_bfloat162*)(Bsm + idx) = xph[g];
            *(__nv_bfloat162*)(Bsm + 9216 + idx) = xpl[g];
        }
        cpa_commit();
        cpa_wait();
        __syncthreads();
        MMA_CONSUME(b_base);
        __syncthreads();
    }

    int g = lane >> 2, tq = lane & 3;
    int win_row = b * 1024 + (y >> 3) * 32;
    int tokb = (y & 7) * 8;
#pragma unroll
    for (int ma = 0; ma < 2; ma++) {
        int o_a = mt * 128 + wm * 32 + ma * 16 + g;
        int o_b = o_a + 8;
        int sel_a = o_a >> 8, h_a = (o_a >> 4) & 15, dd_a = o_a & 15;
        int sel_b = o_b >> 8, h_b = (o_b >> 4) & 15, dd_b = o_b & 15;
#pragma unroll
        for (int na = 0; na < 8; na++) {
            int xq = x0 + wn * 64 + na * 8 + tq * 2;
            int win = win_row + (xq >> 3);
            int tok = tokb + (xq & 7);
            size_t pa = (size_t)sel_a * 33554432 + (size_t)((win * 16 + h_a) * 64 + tok) * 16 + dd_a;
            size_t pb = (size_t)sel_b * 33554432 + (size_t)((win * 16 + h_b) * 64 + tok) * 16 + dd_b;
            g_big[pa] = acc[ma][na][0];
            g_big[pa + 16] = acc[ma][na][1];
            g_big[pb] = acc[ma][na][2];
            g_big[pb + 16] = acc[ma][na][3];
        }
    }
}

// ---------------- kernel B: window attention (exact R8) ---------------------
__global__ void __launch_bounds__(64) attn_kernel(const float* __restrict__ rel_table) {
    __shared__ float ks[1024], vs[1024], bs[232];
    int t = threadIdx.x;
    int w = blockIdx.x;
    int h = blockIdx.y;
    size_t base = ((size_t)(w * 16 + h)) * 1024;
    const float* gq = g_big;
    const float* gk = g_big + 33554432;
    const float* gv = g_big + 67108864;
#pragma unroll
    for (int i = 0; i < 4; i++) {
        *(float4*)(ks + t * 16 + i * 4) = *(const float4*)(gk + base + t * 16 + i * 4);
        *(float4*)(vs + t * 16 + i * 4) = *(const float4*)(gv + base + t * 16 + i * 4);
    }
    for (int r = t; r < 225; r += 64) bs[r] = rel_table[r * 16 + h];
    __syncthreads();

    float q[16];
#pragma unroll
    for (int i = 0; i < 4; i++)
        *(float4*)(q + i * 4) = *(const float4*)(gq + base + t * 16 + i * 4);
    int i1 = t >> 3, i2 = t & 7;

    float d[64];
#pragma unroll
    for (int j = 0; j < 64; j++) {
        const float4* kp = (const float4*)(ks + j * 16);
        float4 k0 = kp[0], k1 = kp[1], k2 = kp[2], k3 = kp[3];
        float s = q[0] * k0.x + q[1] * k0.y + q[2] * k0.z + q[3] * k0.w +
                  q[4] * k1.x + q[5] * k1.y + q[6] * k1.z + q[7] * k1.w +
                  q[8] * k2.x + q[9] * k2.y + q[10] * k2.z + q[11] * k2.w +
                  q[12] * k3.x + q[13] * k3.y + q[14] * k3.z + q[15] * k3.w;
        int j1 = j >> 3, j2 = j & 7;
        d[j] = 0.25f * s + bs[(i1 - j1 + 7) * 15 + (i2 - j2 + 7)];
    }
    float m = -1e30f;
#pragma unroll
    for (int j = 0; j < 64; j++) m = fmaxf(m, d[j]);
    float sum = 0.f;
#pragma unroll
    for (int j = 0; j < 64; j++) { d[j] = __expf(d[j] - m); sum += d[j]; }
    float inv = 1.0f / sum;

    float acc[16] = {};
#pragma unroll
    for (int j = 0; j < 64; j++) {
        float a = d[j] * inv;
        const float4* vp = (const float4*)(vs + j * 16);
        float4 v0 = vp[0], v1 = vp[1], v2 = vp[2], v3 = vp[3];
        acc[0] += a * v0.x;  acc[1] += a * v0.y;  acc[2] += a * v0.z;  acc[3] += a * v0.w;
        acc[4] += a * v1.x;  acc[5] += a * v1.y;  acc[6] += a * v1.z;  acc[7] += a * v1.w;
        acc[8] += a * v2.x;  acc[9] += a * v2.y;  acc[10] += a * v2.z; acc[11] += a * v2.w;
        acc[12] += a * v3.x; acc[13] += a * v3.y; acc[14] += a * v3.z; acc[15] += a * v3.w;
    }
    int b = w >> 10, wy = (w >> 5) & 31, wx = w & 31;
    int y = wy * 8 + i1, xq = wx * 8 + i2;
    __nv_bfloat16* ophi = (__nv_bfloat16*)g_obn;
    __nv_bfloat16* oplo = ophi + 33554432;
    size_t ob = ((size_t)(b * 256 + h * 16)) * HW + y * 256 + xq;
#pragma unroll
    for (int e = 0; e < 16; e++) {
        float v = acc[e];
        __nv_bfloat16 hh = __float2bfloat16(v);
        ophi[ob + (size_t)e * HW] = hh;
        oplo[ob + (size_t)e * HW] = __float2bfloat16(v - __bfloat162float(hh));
    }
}

// ---------------- kernel C: conv2 — ping-pong A/B, K-substage 32 ------------
__device__ __forceinline__ __nv_bfloat16 ldpb(const __nv_bfloat16* p, int r, int q) {
    if ((unsigned)r > 256u || (unsigned)q > 256u) return __float2bfloat16(0.f);
    return p[((r == 256) ? 254 : r) * 256 + ((q == 256) ? 254 : q)];
}

// smem: A0 [0,16K) A1 [16K,32K) B0 [32K,48K) B1 [48K,64K); each buf = hi 8K + lo 8K
// tile row = 64 B (32 k elems), 16B-chunk swizzle: chunk' = c ^ ((row>>1)&3)

__device__ __forceinline__ void conv_sub_load(__nv_bfloat162* vh, __nv_bfloat162* vl,
                                              int t, size_t cbase, int y, int x0, int uu) {
    const __nv_bfloat16* ophi = (const __nv_bfloat16*)g_obn;
    const __nv_bfloat16* oplo = ophi + 33554432;
#pragma unroll
    for (int i = 0; i < 8; i++) {
        int id = t + (i << 8);                  // [0,2048)
        int xl = id & 127, w = id >> 7;         // w in [0,16)
        int vert = (w < 8) ? 1 : 0;
        int w2 = w & 7;
        int cl = w2 >> 2, tp = w2 & 3;
        const __nv_bfloat16* chi = ophi + cbase + (size_t)(2 * uu + cl) * HW;
        const __nv_bfloat16* clo = oplo + cbase + (size_t)(2 * uu + cl) * HW;
        int xq = x0 + xl;
        __nv_bfloat162 ph, pl;
        if (vert) {
            int r0 = y - 3 + 2 * tp, r1 = r0 + 1;
            ph.x = ldpb(chi, r0, xq); ph.y = ldpb(chi, r1, xq);
            pl.x = ldpb(clo, r0, xq); pl.y = ldpb(clo, r1, xq);
        } else {
            int q0 = xq + 2 * tp - 3, q1 = q0 + 1;
            ph.x = ldpb(chi, y, q0); ph.y = ldpb(chi, y, q1);
            pl.x = ldpb(clo, y, q0); pl.y = ldpb(clo, y, q1);
        }
        vh[i] = ph; vl[i] = pl;
    }
}

__device__ __forceinline__ void conv_sub_store(char* bptr, const __nv_bfloat162* vh,
                                               const __nv_bfloat162* vl, int t) {
#pragma unroll
    for (int i = 0; i < 8; i++) {
        int id = t + (i << 8);
        int xl = id & 127, w = id >> 7;
        int vert = (w < 8) ? 1 : 0;
        int w2 = w & 7;
        int cl = w2 >> 2, tp = w2 & 3;
        int klocal = cl * 16 + (vert ? 0 : 8) + 2 * tp;
        int c = klocal >> 3;
        int off = xl * 64 + (((c ^ ((xl >> 1) & 3)) & 3) << 4) + (klocal & 7) * 2;
        *(__nv_bfloat162*)(bptr + off) = vh[i];
        *(__nv_bfloat162*)(bptr + 8192 + off) = vl[i];
    }
}

__global__ void __launch_bounds__(256, 2) conv2_mma_kernel(const float* __restrict__ bias_x,
                                                           const float* __restrict__ bias_y) {
    extern __shared__ __align__(16) char dsm[];
    int t = threadIdx.x, wid = t >> 5, lane = t & 31;
    int y = blockIdx.x, b = blockIdx.y, z = blockIdx.z;
    int mt = z >> 1, nt = z & 1;
    int x0 = nt * 128;
    int wm = wid & 3, wn = wid >> 2;
    size_t cbase = (size_t)b * CC * HW;

    float acc[2][8][4];
#pragma unroll
    for (int i = 0; i < 2; i++)
#pragma unroll
        for (int j = 0; j < 8; j++)
#pragma unroll
            for (int r = 0; r < 4; r++) acc[i][j][r] = 0.f;

    uint32_t smb = smem_u32(dsm);
    // A frag addressing: row = wm*32 + ma*16 + (lane&15); key constant per thread
    int arow_l = (lane & 15);
    uint32_t kA = ((wm * 32 + arow_l) >> 1) & 3;
    // B frag addressing: nl in [0,16); key constant per thread
    int nl = (lane & 7) + ((lane >> 4) << 3);
    uint32_t kB = (nl >> 1) & 3;
    uint32_t cA_half = (uint32_t)(lane >> 4);       // 0 or 1 within kstep pair
    uint32_t cB_half = (uint32_t)((lane >> 3) & 1);

    __nv_bfloat162 vh[8], vl[8];

    // prologue: A(0) via cp.async, B(0) gather
    {
        const float4* wsrc = (const float4*)(g_wA + (size_t)(mt * 128) * 8192);
#pragma unroll
        for (int i = 0; i < 4; i++) cpa16(smb + (t + (i << 8)) * 16, wsrc + t + (i << 8));
        cpa_commit();
        conv_sub_load(vh, vl, t, cbase, y, x0, 0);
        cpa_wait();
        conv_sub_store(dsm + 32768, vh, vl, t);
        __syncthreads();
    }

    for (int u = 0; u < 128; u++) {
        int cur = u & 1;
        uint32_t acur = smb + cur * 16384;
        uint32_t bcur = smb + 32768 + cur * 16384;
        if (u < 127) {
            const float4* wsrc = (const float4*)(g_wA + (size_t)(mt * 128 + u + 1) * 8192);
            uint32_t aalt = smb + (cur ^ 1) * 16384;
#pragma unroll
            for (int i = 0; i < 4; i++) cpa16(aalt + (t + (i << 8)) * 16, wsrc + t + (i << 8));
            cpa_commit();
            conv_sub_load(vh, vl, t, cbase, y, x0, u + 1);
        }
#pragma unroll
        for (int kstep = 0; kstep < 2; kstep++) {
            uint32_t ah[2][4], al[2][4];
#pragma unroll
            for (int ma = 0; ma < 2; ma++) {
                uint32_t row = (uint32_t)(wm * 32 + ma * 16 + arow_l);
                uint32_t c = cA_half + kstep * 2;
                uint32_t aaddr = acur + row * 64 + (((c ^ kA) & 3) << 4);
                ldsm4(ah[ma][0], ah[ma][1], ah[ma][2], ah[ma][3], aaddr);
                ldsm4(al[ma][0], al[ma][1], al[ma][2], al[ma][3], aaddr + 8192);
            }
#pragma unroll
            for (int nc = 0; nc < 4; nc++) {
                uint32_t nrow = (uint32_t)(wn * 64 + nc * 16 + nl);
                uint32_t c = cB_half + kstep * 2;
                uint32_t baddr = bcur + nrow * 64 + (((c ^ kB) & 3) << 4);
                uint32_t bh0, bh1, bh2, bh3, bl0, bl1, bl2, bl3;
                ldsm4(bh0, bh1, bh2, bh3, baddr);
                ldsm4(bl0, bl1, bl2, bl3, baddr + 8192);
#pragma unroll
                for (int ma = 0; ma < 2; ma++) {
                    mma16816(acc[ma][nc * 2 + 0], ah[ma][0], ah[ma][1], ah[ma][2], ah[ma][3], bh0, bh1);
                    mma16816(acc[ma][nc * 2 + 1], ah[ma][0], ah[ma][1], ah[ma][2], ah[ma][3], bh2, bh3);
                    mma16816(acc[ma][nc * 2 + 0], ah[ma][0], ah[ma][1], ah[ma][2], ah[ma][3], bl0, bl1);
                    mma16816(acc[ma][nc * 2 + 1], ah[ma][0], ah[ma][1], ah[ma][2], ah[ma][3], bl2, bl3);
                    mma16816(acc[ma][nc * 2 + 0], al[ma][0], al[ma][1], al[ma][2], al[ma][3], bh0, bh1);
                    mma16816(acc[ma][nc * 2 + 1], al[ma][0], al[ma][1], al[ma][2], al[ma][3], bh2, bh3);
                }
            }
        }
        if (u < 127) {
            conv_sub_store(dsm + 32768 + (cur ^ 1) * 16384, vh, vl, t);
            cpa_wait();
        }
        __syncthreads();
    }

    // epilogue: bias + float2 stores
    float* out1 = g_big;
    int g = lane >> 2, tq = lane & 3;
#pragma unroll
    for (int ma = 0; ma < 2; ma++) {
        int o_base = mt * 128 + wm * 32 + ma * 16;
        int o0 = o_base + g, o1 = o_base + g + 8;
        float bia0 = bias_x[o0] + bias_y[o0];
        float bia1 = bias_x[o1] + bias_y[o1];
        float* r0 = out1 + (size_t)(b * 256 + o0) * HW + y * 256;
        float* r1 = out1 + (size_t)(b * 256 + o1) * HW + y * 256;
#pragma unroll
        for (int na = 0; na < 8; na++) {
            int xq = x0 + wn * 64 + na * 8 + tq * 2;
            float2 w0; w0.x = acc[ma][na][0] + bia0; w0.y = acc[ma][na][1] + bia0;
            float2 w1; w1.x = acc[ma][na][2] + bia1; w1.y = acc[ma][na][3] + bia1;
            *(float2*)(r0 + xq) = w0;
            *(float2*)(r1 + xq) = w1;
        }
    }
}

// ---------------- kernel D: depthwise 8x8 + BN (exact R8) -------------------
__global__ void __launch_bounds__(256) dwbn_kernel(const float* __restrict__ wdw,
                                                   const float* __restrict__ gamma,
                                                   const float* __restrict__ beta,
                                                   const float* __restrict__ mean,
                                                   const float* __restrict__ var) {
    __shared__ float S[2][1560];
    __shared__ float ws[128];
    int t = threadIdx.x;
    int tile = blockIdx.x;
    int cp = blockIdx.y, b = blockIdx.z;
    int c0 = 2 * cp;
    int y0 = (tile >> 3) * 32, x0 = (tile & 7) * 32;
#pragma unroll
    for (int ch = 0; ch < 2; ch++) {
        const float* in = g_big + ((size_t)(b * 256 + c0 + ch)) * HW;
        for (int e = t; e < 39 * 39; e += 256) {
            int r = e / 39, j = e - r * 39;
            int row = y0 - 3 + r, col = x0 - 3 + j;
            float v = 0.f;
            if (row >= 0 && row <= 256 && col >= 0 && col <= 256) {
                int rr = (row == 256) ? 254 : row;
                int cc = (col == 256) ? 254 : col;
                v = in[rr * 256 + cc];
            }
            S[ch][r * 40 + j] = v;
        }
    }
    if (t < 128) ws[t] = wdw[c0 * 64 + t];
    __syncthreads();

    int ly = t >> 3, lx0 = (t & 7) * 4;
    float acc[2][4] = {};
#pragma unroll
    for (int ch = 0; ch < 2; ch++) {
#pragma unroll
        for (int ky = 0; ky < 8; ky++) {
            float rv[11];
#pragma unroll
            for (int u = 0; u < 11; u++) rv[u] = S[ch][(ly + ky) * 40 + lx0 + u];
#pragma unroll
            for (int kx = 0; kx < 8; kx++) {
                float wv = ws[ch * 64 + ky * 8 + kx];
#pragma unroll
                for (int j = 0; j < 4; j++) acc[ch][j] += wv * rv[kx + j];
            }
        }
    }
    float iv0 = rsqrtf(var[c0] + 1e-5f), iv1 = rsqrtf(var[c0 + 1] + 1e-5f);
    float sc0 = gamma[c0] * iv0, sc1 = gamma[c0 + 1] * iv1;
    float sh0 = beta[c0] - mean[c0] * sc0, sh1 = beta[c0 + 1] - mean[c0 + 1] * sc1;
    __nv_bfloat162* oh = (__nv_bfloat162*)g_obn;
    __nv_bfloat162* ol = oh + 16777216;
    size_t g = ((size_t)(b * 128 + cp)) * HW + (y0 + ly) * 256 + x0 + lx0;
#pragma unroll
    for (int j = 0; j < 4; j++) {
        float u0 = acc[0][j] * sc0 + sh0;
        float u1 = acc[1][j] * sc1 + sh1;
        __nv_bfloat162 hh, ll;
        split2(u0, u1, hh, ll);
        oh[g + j] = hh;
        ol[g + j] = ll;
    }
}

// ---------------- kernel E: proj via mma -> d_out (exact R8) ----------------
__global__ void __launch_bounds__(256, 2) proj_mma_kernel(float* __restrict__ out) {
    extern __shared__ __align__(16) char dsm[];
    __nv_bfloat16* Asm = (__nv_bfloat16*)dsm;
    __nv_bfloat16* Bsm = (__nv_bfloat16*)(dsm + 36864);
    int t = threadIdx.x, wid = t >> 5, lane = t & 31;
    int y = blockIdx.x, b = blockIdx.y, z = blockIdx.z;
    int mt = z >> 1, nt = z & 1;
    int x0 = nt * 128;
    int wm = wid & 3, wn = wid >> 2;

    float acc[2][8][4];
#pragma unroll
    for (int i = 0; i < 2; i++)
#pragma unroll
        for (int j = 0; j < 8; j++)
#pragma unroll
            for (int r = 0; r < 4; r++) acc[i][j][r] = 0.f;

    uint32_t a_base = smem_u32(Asm);
    uint32_t b_base = smem_u32(Bsm);
    uint32_t a_loff = (uint32_t)((wm * 32 + (lane & 15)) * 144 + (lane >> 4) * 16);
    uint32_t b_loff = (uint32_t)(((lane & 7) + ((lane >> 4) << 3)) * 144 + ((lane >> 3) & 1) * 16);

    const __nv_bfloat162* dph = (const __nv_bfloat162*)g_obn;
    const __nv_bfloat162* dpl = dph + 16777216;
    size_t rowb = (size_t)(b * 128) * HW + y * 256 + x0;

    for (int s = 0; s < 4; s++) {
        const float4* wsrc = (const float4*)(g_wP + (size_t)(mt * 4 + s) * 18432);
#pragma unroll
        for (int i = 0; i < 9; i++) cpa16(a_base + (t + (i << 8)) * 16, wsrc + t + (i << 8));

        int cp0 = s * 32;
#pragma unroll
        for (int i = 0; i < 16; i++) {
            int id = t + (i << 8);
            int xl = id & 127, j = id >> 7;
            size_t g = rowb + (size_t)(cp0 + j) * HW + xl;
            int idx = xl * 72 + 2 * j;
            *(__nv_bfloat162*)(Bsm + idx) = dph[g];
            *(__nv_bfloat162*)(Bsm + 9216 + idx) = dpl[g];
        }
        cpa_commit();
        cpa_wait();
        __syncthreads();
        MMA_CONSUME(b_base);
        __syncthreads();
    }

    int g = lane >> 2, tq = lane & 3;
#pragma unroll
    for (int ma = 0; ma < 2; ma++) {
        int o_base = mt * 128 + wm * 32 + ma * 16;
        int o0 = o_base + g, o1 = o_base + g + 8;
        float* r0 = out + (size_t)(b * 256 + o0) * HW + y * 256;
        float* r1 = out + (size_t)(b * 256 + o1) * HW + y * 256;
#pragma unroll
        for (int na = 0; na < 8; na++) {
            int xq = x0 + wn * 64 + na * 8 + tq * 2;
            float2 w0; w0.x = acc[ma][na][0]; w0.y = acc[ma][na][1];
            float2 w1; w1.x = acc[ma][na][2]; w1.y = acc[ma][na][3];
            *(float2*)(r0 + xq) = w0;
            *(float2*)(r1 + xq) = w1;
        }
    }
}

// ---------------- launch ----------------------------------------------------
extern "C" void kernel_launch(void* const* d_in, const int* in_sizes, int n_in,
                              void* d_out, int out_size) {
    const float* x     = (const float*)d_in[0];
    const float* wqkv  = (const float*)d_in[1];
    const float* rel   = (const float*)d_in[2];
    const float* w_ax  = (const float*)d_in[3];
    const float* b_ax  = (const float*)d_in[4];
    const float* w_ay  = (const float*)d_in[5];
    const float* b_ay  = (const float*)d_in[6];
    const float* w_dw  = (const float*)d_in[7];
    const float* gm    = (const float*)d_in[8];
    const float* bt    = (const float*)d_in[9];
    const float* mn    = (const float*)d_in[10];
    const float* vr    = (const float*)d_in[11];
    const float* w_pr  = (const float*)d_in[12];
    float* out = (float*)d_out;

    cudaFuncSetAttribute(conv2_mma_kernel, cudaFuncAttributeMaxDynamicSharedMemorySize, 65536);
    cudaFuncSetAttribute(qkv_mma_kernel, cudaFuncAttributeMaxDynamicSharedMemorySize, 73728);
    cudaFuncSetAttribute(proj_mma_kernel, cudaFuncAttributeMaxDynamicSharedMemorySize, 73728);

    aprep_kernel<<<8192, 256>>>(w_ax, w_ay);
    qprep_kernel<<<768, 256>>>(wqkv);
    pprep_kernel<<<256, 256>>>(w_pr);
    xprep_kernel<<<65536, 256>>>(x);
    qkv_mma_kernel<<<dim3(256, 2, 12), 256, 73728>>>();
    attn_kernel<<<dim3(2048, 16), 64>>>(rel);
    conv2_mma_kernel<<<dim3(256, 2, 4), 256, 65536>>>(b_ax, b_ay);
    dwbn_kernel<<<dim3(64, 128, 2), 256>>>(w_dw, gm, bt, mn, vr);
    proj_mma_kernel<<<dim3(256, 2, 4), 256, 73728>>>(out);
}

// round 12
// speedup vs baseline: 2.1590x; 1.2825x over previous
#include <cuda_runtime.h>
#include <cuda_bf16.h>
#include <cuda_fp16.h>
#include <cstdint>

#define HW 65536
#define CC 256

// ---------------- scratch ---------------------------------------------------
__device__ float g_big[100663296];
// g_obn: attn writes split fp16 planes (hi [0,33.5M) half, lo [33.5M,67M) half);
//        dwbn later overwrites with channel-paired split bf16 planes for proj
__device__ float g_obn[33554432];
// conv weights: single fp16 plane per (mt, stage): [128 o][72 k]
__device__ __align__(16) __half g_wA[1179648];
__device__ __align__(16) __nv_bfloat16 g_wQ[442368];
__device__ __align__(16) __nv_bfloat16 g_wP[147456];
__device__ __align__(16) __nv_bfloat16 g_xsplit[67108864];

// ---------------- helpers ---------------------------------------------------
__device__ __forceinline__ uint32_t smem_u32(const void* p) {
    uint32_t a;
    asm("{ .reg .u64 t; cvta.to.shared.u64 t, %1; cvt.u32.u64 %0, t; }" : "=r"(a) : "l"(p));
    return a;
}
__device__ __forceinline__ void ldsm4(uint32_t& r0, uint32_t& r1, uint32_t& r2, uint32_t& r3,
                                      uint32_t addr) {
    asm volatile("ldmatrix.sync.aligned.m8n8.x4.shared.b16 {%0,%1,%2,%3}, [%4];"
                 : "=r"(r0), "=r"(r1), "=r"(r2), "=r"(r3) : "r"(addr));
}
__device__ __forceinline__ void mma16816(float* c, uint32_t a0, uint32_t a1, uint32_t a2,
                                         uint32_t a3, uint32_t b0, uint32_t b1) {
    asm volatile("mma.sync.aligned.m16n8k16.row.col.f32.bf16.bf16.f32 "
                 "{%0,%1,%2,%3}, {%4,%5,%6,%7}, {%8,%9}, {%0,%1,%2,%3};"
                 : "+f"(c[0]), "+f"(c[1]), "+f"(c[2]), "+f"(c[3])
                 : "r"(a0), "r"(a1), "r"(a2), "r"(a3), "r"(b0), "r"(b1));
}
__device__ __forceinline__ void mma16816h(float* c, uint32_t a0, uint32_t a1, uint32_t a2,
                                          uint32_t a3, uint32_t b0, uint32_t b1) {
    asm volatile("mma.sync.aligned.m16n8k16.row.col.f32.f16.f16.f32 "
                 "{%0,%1,%2,%3}, {%4,%5,%6,%7}, {%8,%9}, {%0,%1,%2,%3};"
                 : "+f"(c[0]), "+f"(c[1]), "+f"(c[2]), "+f"(c[3])
                 : "r"(a0), "r"(a1), "r"(a2), "r"(a3), "r"(b0), "r"(b1));
}
__device__ __forceinline__ void split2(float v0, float v1, __nv_bfloat162& ph, __nv_bfloat162& pl) {
    __nv_bfloat16 h0 = __float2bfloat16(v0), h1 = __float2bfloat16(v1);
    ph.x = h0; ph.y = h1;
    pl.x = __float2bfloat16(v0 - __bfloat162float(h0));
    pl.y = __float2bfloat16(v1 - __bfloat162float(h1));
}
__device__ __forceinline__ void cpa16(uint32_t dst, const void* src) {
    asm volatile("cp.async.cg.shared.global [%0], [%1], 16;" :: "r"(dst), "l"(src));
}
__device__ __forceinline__ void cpa_commit() {
    asm volatile("cp.async.commit_group;");
}
__device__ __forceinline__ void cpa_wait() {
    asm volatile("cp.async.wait_group 0;" ::: "memory");
}

// ---------------- weight/input prep kernels --------------------------------
// conv weights -> single fp16 plane: per (mt, s): [128 o][72 k], k = c_l*16+conv*8+tap
__global__ void aprep_kernel(const float* __restrict__ wx, const float* __restrict__ wy) {
    int e = blockIdx.x * 256 + threadIdx.x;     // < 1048576 logical (k<64)
    if (e >= 1048576) return;
    int k = e & 63, o_l = (e >> 6) & 127, s = (e >> 13) & 63, mt = e >> 19;
    int c = 4 * s + (k >> 4);
    int conv = (k >> 3) & 1, tap = k & 7;
    int o = mt * 128 + o_l;
    float v = (conv ? wy : wx)[(o * 256 + c) * 8 + tap];
    g_wA[(size_t)(mt * 64 + s) * 9216 + o_l * 72 + k] = __float2half_rn(v);
}
__global__ void qprep_kernel(const float* __restrict__ wqkv) {
    int e = blockIdx.x * 256 + threadIdx.x;
    if (e >= 196608) return;
    int k = e & 63, o_l = (e >> 6) & 127, s = (e >> 13) & 3, mt = e >> 15;
    float v = wqkv[(mt * 128 + o_l) * 256 + s * 64 + k];
    __nv_bfloat16 h = __float2bfloat16(v);
    __nv_bfloat16 l = __float2bfloat16(v - __bfloat162float(h));
    size_t base = (size_t)(mt * 4 + s) * 18432;
    g_wQ[base + o_l * 72 + k] = h;
    g_wQ[base + 9216 + o_l * 72 + k] = l;
}
__global__ void pprep_kernel(const float* __restrict__ wp) {
    int e = blockIdx.x * 256 + threadIdx.x;
    int k = e & 63, o_l = (e >> 6) & 127, s = (e >> 13) & 3, mt = e >> 15;
    float v = wp[(mt * 128 + o_l) * 256 + s * 64 + k];
    __nv_bfloat16 h = __float2bfloat16(v);
    __nv_bfloat16 l = __float2bfloat16(v - __bfloat162float(h));
    size_t base = (size_t)(mt * 4 + s) * 18432;
    g_wP[base + o_l * 72 + k] = h;
    g_wP[base + 9216 + o_l * 72 + k] = l;
}
__global__ void xprep_kernel(const float* __restrict__ x) {
    int g = blockIdx.x * 256 + threadIdx.x;
    int pos = g & (HW - 1);
    int cpb = g >> 16;
    const float* src = x + (size_t)(2 * cpb) * HW + pos;
    float v0 = src[0], v1 = src[HW];
    __nv_bfloat162 h, l;
    split2(v0, v1, h, l);
    ((__nv_bfloat162*)g_xsplit)[g] = h;
    ((__nv_bfloat162*)g_xsplit)[g + 16777216] = l;
}

// ---------------- shared mma consume for qkv/proj (bf16 3-pass, R8) ---------
#define MMA_CONSUME(BBASE)                                                               \
    do {                                                                                 \
        _Pragma("unroll")                                                                \
        for (int kstep = 0; kstep < 4; kstep++) {                                        \
            uint32_t ah[2][4], al[2][4];                                                 \
            _Pragma("unroll")                                                            \
            for (int ma = 0; ma < 2; ma++) {                                             \
                uint32_t aaddr = a_base + a_loff + ma * 16 * 144 + kstep * 32;           \
                ldsm4(ah[ma][0], ah[ma][1], ah[ma][2], ah[ma][3], aaddr);                \
                ldsm4(al[ma][0], al[ma][1], al[ma][2], al[ma][3], aaddr + 18432);        \
            }                                                                            \
            _Pragma("unroll")                                                            \
            for (int nc = 0; nc < 4; nc++) {                                             \
                uint32_t baddr = (BBASE) + b_loff + (wn * 64 + nc * 16) * 144 + kstep * 32; \
                uint32_t bh0, bh1, bh2, bh3, bl0, bl1, bl2, bl3;                         \
                ldsm4(bh0, bh1, bh2, bh3, baddr);                                        \
                ldsm4(bl0, bl1, bl2, bl3, baddr + 18432);                                \
                _Pragma("unroll")                                                        \
                for (int ma = 0; ma < 2; ma++) {                                         \
                    mma16816(acc[ma][nc * 2 + 0], ah[ma][0], ah[ma][1], ah[ma][2], ah[ma][3], bh0, bh1); \
                    mma16816(acc[ma][nc * 2 + 1], ah[ma][0], ah[ma][1], ah[ma][2], ah[ma][3], bh2, bh3); \
                    mma16816(acc[ma][nc * 2 + 0], ah[ma][0], ah[ma][1], ah[ma][2], ah[ma][3], bl0, bl1); \
                    mma16816(acc[ma][nc * 2 + 1], ah[ma][0], ah[ma][1], ah[ma][2], ah[ma][3], bl2, bl3); \
                    mma16816(acc[ma][nc * 2 + 0], al[ma][0], al[ma][1], al[ma][2], al[ma][3], bh0, bh1); \
                    mma16816(acc[ma][nc * 2 + 1], al[ma][0], al[ma][1], al[ma][2], al[ma][3], bh2, bh3); \
                }                                                                        \
            }                                                                            \
        }                                                                                \
    } while (0)

// ---------------- kernel A: qkv via mma (exact R8) ---------------------------
__global__ void __launch_bounds__(256, 2) qkv_mma_kernel() {
    extern __shared__ __align__(16) char dsm[];
    __nv_bfloat16* Asm = (__nv_bfloat16*)dsm;
    __nv_bfloat16* Bsm = (__nv_bfloat16*)(dsm + 36864);
    int t = threadIdx.x, wid = t >> 5, lane = t & 31;
    int y = blockIdx.x, b = blockIdx.y, z = blockIdx.z;
    int mt = z >> 1, nt = z & 1;
    int x0 = nt * 128;
    int wm = wid & 3, wn = wid >> 2;

    float acc[2][8][4];
#pragma unroll
    for (int i = 0; i < 2; i++)
#pragma unroll
        for (int j = 0; j < 8; j++)
#pragma unroll
            for (int r = 0; r < 4; r++) acc[i][j][r] = 0.f;

    uint32_t a_base = smem_u32(Asm);
    uint32_t b_base = smem_u32(Bsm);
    uint32_t a_loff = (uint32_t)((wm * 32 + (lane & 15)) * 144 + (lane >> 4) * 16);
    uint32_t b_loff = (uint32_t)(((lane & 7) + ((lane >> 4) << 3)) * 144 + ((lane >> 3) & 1) * 16);

    const __nv_bfloat162* xph = (const __nv_bfloat162*)g_xsplit;
    const __nv_bfloat162* xpl = xph + 16777216;
    size_t rowb = (size_t)(b * 128) * HW + y * 256 + x0;

    for (int s = 0; s < 4; s++) {
        const float4* wsrc = (const float4*)(g_wQ + (size_t)(mt * 4 + s) * 18432);
#pragma unroll
        for (int i = 0; i < 9; i++) cpa16(a_base + (t + (i << 8)) * 16, wsrc + t + (i << 8));

        int cp0 = s * 32;
#pragma unroll
        for (int i = 0; i < 16; i++) {
            int id = t + (i << 8);
            int xl = id & 127, j = id >> 7;
            size_t g = rowb + (size_t)(cp0 + j) * HW + xl;
            int idx = xl * 72 + 2 * j;
            *(__nv_bfloat162*)(Bsm + idx) = xph[g];
            *(__nv_bfloat162*)(Bsm + 9216 + idx) = xpl[g];
        }
        cpa_commit();
        cpa_wait();
        __syncthreads();
        MMA_CONSUME(b_base);
        __syncthreads();
    }

    int g = lane >> 2, tq = lane & 3;
    int win_row = b * 1024 + (y >> 3) * 32;
    int tokb = (y & 7) * 8;
#pragma unroll
    for (int ma = 0; ma < 2; ma++) {
        int o_a = mt * 128 + wm * 32 + ma * 16 + g;
        int o_b = o_a + 8;
        int sel_a = o_a >> 8, h_a = (o_a >> 4) & 15, dd_a = o_a & 15;
        int sel_b = o_b >> 8, h_b = (o_b >> 4) & 15, dd_b = o_b & 15;
#pragma unroll
        for (int na = 0; na < 8; na++) {
            int xq = x0 + wn * 64 + na * 8 + tq * 2;
            int win = win_row + (xq >> 3);
            int tok = tokb + (xq & 7);
            size_t pa = (size_t)sel_a * 33554432 + (size_t)((win * 16 + h_a) * 64 + tok) * 16 + dd_a;
            size_t pb = (size_t)sel_b * 33554432 + (size_t)((win * 16 + h_b) * 64 + tok) * 16 + dd_b;
            g_big[pa] = acc[ma][na][0];
            g_big[pa + 16] = acc[ma][na][1];
            g_big[pb] = acc[ma][na][2];
            g_big[pb + 16] = acc[ma][na][3];
        }
    }
}

// ---------------- kernel B: window attention (fp16 split planes out) --------
__global__ void __launch_bounds__(64) attn_kernel(const float* __restrict__ rel_table) {
    __shared__ float ks[1024], vs[1024], bs[232];
    int t = threadIdx.x;
    int w = blockIdx.x;
    int h = blockIdx.y;
    size_t base = ((size_t)(w * 16 + h)) * 1024;
    const float* gq = g_big;
    const float* gk = g_big + 33554432;
    const float* gv = g_big + 67108864;
#pragma unroll
    for (int i = 0; i < 4; i++) {
        *(float4*)(ks + t * 16 + i * 4) = *(const float4*)(gk + base + t * 16 + i * 4);
        *(float4*)(vs + t * 16 + i * 4) = *(const float4*)(gv + base + t * 16 + i * 4);
    }
    for (int r = t; r < 225; r += 64) bs[r] = rel_table[r * 16 + h];
    __syncthreads();

    float q[16];
#pragma unroll
    for (int i = 0; i < 4; i++)
        *(float4*)(q + i * 4) = *(const float4*)(gq + base + t * 16 + i * 4);
    int i1 = t >> 3, i2 = t & 7;

    float d[64];
#pragma unroll
    for (int j = 0; j < 64; j++) {
        const float4* kp = (const float4*)(ks + j * 16);
        float4 k0 = kp[0], k1 = kp[1], k2 = kp[2], k3 = kp[3];
        float s = q[0] * k0.x + q[1] * k0.y + q[2] * k0.z + q[3] * k0.w +
                  q[4] * k1.x + q[5] * k1.y + q[6] * k1.z + q[7] * k1.w +
                  q[8] * k2.x + q[9] * k2.y + q[10] * k2.z + q[11] * k2.w +
                  q[12] * k3.x + q[13] * k3.y + q[14] * k3.z + q[15] * k3.w;
        int j1 = j >> 3, j2 = j & 7;
        d[j] = 0.25f * s + bs[(i1 - j1 + 7) * 15 + (i2 - j2 + 7)];
    }
    float m = -1e30f;
#pragma unroll
    for (int j = 0; j < 64; j++) m = fmaxf(m, d[j]);
    float sum = 0.f;
#pragma unroll
    for (int j = 0; j < 64; j++) { d[j] = __expf(d[j] - m); sum += d[j]; }
    float inv = 1.0f / sum;

    float acc[16] = {};
#pragma unroll
    for (int j = 0; j < 64; j++) {
        float a = d[j] * inv;
        const float4* vp = (const float4*)(vs + j * 16);
        float4 v0 = vp[0], v1 = vp[1], v2 = vp[2], v3 = vp[3];
        acc[0] += a * v0.x;  acc[1] += a * v0.y;  acc[2] += a * v0.z;  acc[3] += a * v0.w;
        acc[4] += a * v1.x;  acc[5] += a * v1.y;  acc[6] += a * v1.z;  acc[7] += a * v1.w;
        acc[8] += a * v2.x;  acc[9] += a * v2.y;  acc[10] += a * v2.z; acc[11] += a * v2.w;
        acc[12] += a * v3.x; acc[13] += a * v3.y; acc[14] += a * v3.z; acc[15] += a * v3.w;
    }
    int b = w >> 10, wy = (w >> 5) & 31, wx = w & 31;
    int y = wy * 8 + i1, xq = wx * 8 + i2;
    __half* ophi = (__half*)g_obn;
    __half* oplo = ophi + 33554432;
    size_t ob = ((size_t)(b * 256 + h * 16)) * HW + y * 256 + xq;
#pragma unroll
    for (int e = 0; e < 16; e++) {
        float v = acc[e];
        __half hh = __float2half_rn(v);
        ophi[ob + (size_t)e * HW] = hh;
        oplo[ob + (size_t)e * HW] = __float2half_rn(v - __half2float(hh));
    }
}

// ---------------- kernel C: conv2 via fp16 mma (2-pass: a*bh + a*bl) --------
__device__ __forceinline__ __half ldph(const __half* p, int r, int q) {
    if ((unsigned)r > 256u || (unsigned)q > 256u) return __float2half_rn(0.f);
    return p[((r == 256) ? 254 : r) * 256 + ((q == 256) ? 254 : q)];
}

__global__ void __launch_bounds__(256, 2) conv2_mma_kernel(const float* __restrict__ bias_x,
                                                           const float* __restrict__ bias_y) {
    extern __shared__ __align__(16) char dsm[];
    __half* Asm = (__half*)dsm;                  // [128][72] fp16 = 18432 B
    __half* Bsm = (__half*)(dsm + 18432);        // hi [0,9216) elems, lo +9216 elems
    int t = threadIdx.x, wid = t >> 5, lane = t & 31;
    int y = blockIdx.x, b = blockIdx.y, z = blockIdx.z;
    int mt = z >> 1, nt = z & 1;
    int x0 = nt * 128;
    int wm = wid & 3, wn = wid >> 2;
    const __half* ophi = (const __half*)g_obn;
    const __half* oplo = ophi + 33554432;
    size_t cbase = (size_t)b * CC * HW;

    float acc[2][8][4];
#pragma unroll
    for (int i = 0; i < 2; i++)
#pragma unroll
        for (int j = 0; j < 8; j++)
#pragma unroll
            for (int r = 0; r < 4; r++) acc[i][j][r] = 0.f;

    uint32_t a_base = smem_u32(Asm);
    uint32_t b_base = smem_u32(Bsm);
    uint32_t a_loff = (uint32_t)((wm * 32 + (lane & 15)) * 144 + (lane >> 4) * 16);
    uint32_t b_loff = (uint32_t)(((lane & 7) + ((lane >> 4) << 3)) * 144 + ((lane >> 3) & 1) * 16);

    for (int s = 0; s < 64; s++) {
        // A fill: 18432 B = 1152 float4 via cp.async
        const float4* wsrc = (const float4*)(g_wA + (size_t)(mt * 64 + s) * 9216);
#pragma unroll
        for (int i = 0; i < 5; i++) {
            int e = t + (i << 8);
            if (e < 1152) cpa16(a_base + e * 16, wsrc + e);
        }

        int c0 = 4 * s;
#pragma unroll
        for (int i = 0; i < 8; i++) {           // vertical taps
            int id = t + (i << 8);
            int xl = id & 127, u = id >> 7;
            int c_l = u >> 2, rp = u & 3;
            const __half* chi = ophi + cbase + (size_t)(c0 + c_l) * HW;
            const __half* clo = oplo + cbase + (size_t)(c0 + c_l) * HW;
            int xq = x0 + xl;
            int r0 = y - 3 + 2 * rp, r1 = r0 + 1;
            __half2 ph, pl;
            ph.x = ldph(chi, r0, xq); ph.y = ldph(chi, r1, xq);
            pl.x = ldph(clo, r0, xq); pl.y = ldph(clo, r1, xq);
            int idx = xl * 72 + c_l * 16 + 2 * rp;
            *(__half2*)(Bsm + idx) = ph;
            *(__half2*)(Bsm + 9216 + idx) = pl;
        }
#pragma unroll
        for (int i = 0; i < 8; i++) {           // horizontal taps
            int id = t + (i << 8);
            int xl = id & 127, u = id >> 7;
            int c_l = u >> 2, tp = u & 3;
            const __half* chi = ophi + cbase + (size_t)(c0 + c_l) * HW;
            const __half* clo = oplo + cbase + (size_t)(c0 + c_l) * HW;
            int xq = x0 + xl;
            int q0 = xq + 2 * tp - 3, q1 = q0 + 1;
            __half2 ph, pl;
            ph.x = ldph(chi, y, q0); ph.y = ldph(chi, y, q1);
            pl.x = ldph(clo, y, q0); pl.y = ldph(clo, y, q1);
            int idx = xl * 72 + c_l * 16 + 8 + 2 * tp;
            *(__half2*)(Bsm + idx) = ph;
            *(__half2*)(Bsm + 9216 + idx) = pl;
        }
        cpa_commit();
        cpa_wait();
        __syncthreads();

#pragma unroll
        for (int kstep = 0; kstep < 4; kstep++) {
            uint32_t ah[2][4];
#pragma unroll
            for (int ma = 0; ma < 2; ma++) {
                uint32_t aaddr = a_base + a_loff + ma * 16 * 144 + kstep * 32;
                ldsm4(ah[ma][0], ah[ma][1], ah[ma][2], ah[ma][3], aaddr);
            }
#pragma unroll
            for (int nc = 0; nc < 4; nc++) {
                uint32_t baddr = b_base + b_loff + (wn * 64 + nc * 16) * 144 + kstep * 32;
                uint32_t bh0, bh1, bh2, bh3, bl0, bl1, bl2, bl3;
                ldsm4(bh0, bh1, bh2, bh3, baddr);
                ldsm4(bl0, bl1, bl2, bl3, baddr + 18432);
#pragma unroll
                for (int ma = 0; ma < 2; ma++) {
                    mma16816h(acc[ma][nc * 2 + 0], ah[ma][0], ah[ma][1], ah[ma][2], ah[ma][3], bh0, bh1);
                    mma16816h(acc[ma][nc * 2 + 1], ah[ma][0], ah[ma][1], ah[ma][2], ah[ma][3], bh2, bh3);
                    mma16816h(acc[ma][nc * 2 + 0], ah[ma][0], ah[ma][1], ah[ma][2], ah[ma][3], bl0, bl1);
                    mma16816h(acc[ma][nc * 2 + 1], ah[ma][0], ah[ma][1], ah[ma][2], ah[ma][3], bl2, bl3);
                }
            }
        }
        __syncthreads();
    }

    // epilogue: bias + float2 stores
    float* out1 = g_big;
    int g = lane >> 2, tq = lane & 3;
#pragma unroll
    for (int ma = 0; ma < 2; ma++) {
        int o_base = mt * 128 + wm * 32 + ma * 16;
        int o0 = o_base + g, o1 = o_base + g + 8;
        float bia0 = bias_x[o0] + bias_y[o0];
        float bia1 = bias_x[o1] + bias_y[o1];
        float* r0 = out1 + (size_t)(b * 256 + o0) * HW + y * 256;
        float* r1 = out1 + (size_t)(b * 256 + o1) * HW + y * 256;
#pragma unroll
        for (int na = 0; na < 8; na++) {
            int xq = x0 + wn * 64 + na * 8 + tq * 2;
            float2 w0; w0.x = acc[ma][na][0] + bia0; w0.y = acc[ma][na][1] + bia0;
            float2 w1; w1.x = acc[ma][na][2] + bia1; w1.y = acc[ma][na][3] + bia1;
            *(float2*)(r0 + xq) = w0;
            *(float2*)(r1 + xq) = w1;
        }
    }
}

// ---------------- kernel D: depthwise 8x8 + BN (exact R8) -------------------
__global__ void __launch_bounds__(256) dwbn_kernel(const float* __restrict__ wdw,
                                                   const float* __restrict__ gamma,
                                                   const float* __restrict__ beta,
                                                   const float* __restrict__ mean,
                                                   const float* __restrict__ var) {
    __shared__ float S[2][1560];
    __shared__ float ws[128];
    int t = threadIdx.x;
    int tile = blockIdx.x;
    int cp = blockIdx.y, b = blockIdx.z;
    int c0 = 2 * cp;
    int y0 = (tile >> 3) * 32, x0 = (tile & 7) * 32;
#pragma unroll
    for (int ch = 0; ch < 2; ch++) {
        const float* in = g_big + ((size_t)(b * 256 + c0 + ch)) * HW;
        for (int e = t; e < 39 * 39; e += 256) {
            int r = e / 39, j = e - r * 39;
            int row = y0 - 3 + r, col = x0 - 3 + j;
            float v = 0.f;
            if (row >= 0 && row <= 256 && col >= 0 && col <= 256) {
                int rr = (row == 256) ? 254 : row;
                int cc = (col == 256) ? 254 : col;
                v = in[rr * 256 + cc];
            }
            S[ch][r * 40 + j] = v;
        }
    }
    if (t < 128) ws[t] = wdw[c0 * 64 + t];
    __syncthreads();

    int ly = t >> 3, lx0 = (t & 7) * 4;
    float acc[2][4] = {};
#pragma unroll
    for (int ch = 0; ch < 2; ch++) {
#pragma unroll
        for (int ky = 0; ky < 8; ky++) {
            float rv[11];
#pragma unroll
            for (int u = 0; u < 11; u++) rv[u] = S[ch][(ly + ky) * 40 + lx0 + u];
#pragma unroll
            for (int kx = 0; kx < 8; kx++) {
                float wv = ws[ch * 64 + ky * 8 + kx];
#pragma unroll
                for (int j = 0; j < 4; j++) acc[ch][j] += wv * rv[kx + j];
            }
        }
    }
    float iv0 = rsqrtf(var[c0] + 1e-5f), iv1 = rsqrtf(var[c0 + 1] + 1e-5f);
    float sc0 = gamma[c0] * iv0, sc1 = gamma[c0 + 1] * iv1;
    float sh0 = beta[c0] - mean[c0] * sc0, sh1 = beta[c0 + 1] - mean[c0 + 1] * sc1;
    __nv_bfloat162* oh = (__nv_bfloat162*)g_obn;
    __nv_bfloat162* ol = oh + 16777216;
    size_t g = ((size_t)(b * 128 + cp)) * HW + (y0 + ly) * 256 + x0 + lx0;
#pragma unroll
    for (int j = 0; j < 4; j++) {
        float u0 = acc[0][j] * sc0 + sh0;
        float u1 = acc[1][j] * sc1 + sh1;
        __nv_bfloat162 hh, ll;
        split2(u0, u1, hh, ll);
        oh[g + j] = hh;
        ol[g + j] = ll;
    }
}

// ---------------- kernel E: proj via mma -> d_out (exact R8) ----------------
__global__ void __launch_bounds__(256, 2) proj_mma_kernel(float* __restrict__ out) {
    extern __shared__ __align__(16) char dsm[];
    __nv_bfloat16* Asm = (__nv_bfloat16*)dsm;
    __nv_bfloat16* Bsm = (__nv_bfloat16*)(dsm + 36864);
    int t = threadIdx.x, wid = t >> 5, lane = t & 31;
    int y = blockIdx.x, b = blockIdx.y, z = blockIdx.z;
    int mt = z >> 1, nt = z & 1;
    int x0 = nt * 128;
    int wm = wid & 3, wn = wid >> 2;

    float acc[2][8][4];
#pragma unroll
    for (int i = 0; i < 2; i++)
#pragma unroll
        for (int j = 0; j < 8; j++)
#pragma unroll
            for (int r = 0; r < 4; r++) acc[i][j][r] = 0.f;

    uint32_t a_base = smem_u32(Asm);
    uint32_t b_base = smem_u32(Bsm);
    uint32_t a_loff = (uint32_t)((wm * 32 + (lane & 15)) * 144 + (lane >> 4) * 16);
    uint32_t b_loff = (uint32_t)(((lane & 7) + ((lane >> 4) << 3)) * 144 + ((lane >> 3) & 1) * 16);

    const __nv_bfloat162* dph = (const __nv_bfloat162*)g_obn;
    const __nv_bfloat162* dpl = dph + 16777216;
    size_t rowb = (size_t)(b * 128) * HW + y * 256 + x0;

    for (int s = 0; s < 4; s++) {
        const float4* wsrc = (const float4*)(g_wP + (size_t)(mt * 4 + s) * 18432);
#pragma unroll
        for (int i = 0; i < 9; i++) cpa16(a_base + (t + (i << 8)) * 16, wsrc + t + (i << 8));

        int cp0 = s * 32;
#pragma unroll
        for (int i = 0; i < 16; i++) {
            int id = t + (i << 8);
            int xl = id & 127, j = id >> 7;
            size_t g = rowb + (size_t)(cp0 + j) * HW + xl;
            int idx = xl * 72 + 2 * j;
            *(__nv_bfloat162*)(Bsm + idx) = dph[g];
            *(__nv_bfloat162*)(Bsm + 9216 + idx) = dpl[g];
        }
        cpa_commit();
        cpa_wait();
        __syncthreads();
        MMA_CONSUME(b_base);
        __syncthreads();
    }

    int g = lane >> 2, tq = lane & 3;
#pragma unroll
    for (int ma = 0; ma < 2; ma++) {
        int o_base = mt * 128 + wm * 32 + ma * 16;
        int o0 = o_base + g, o1 = o_base + g + 8;
        float* r0 = out + (size_t)(b * 256 + o0) * HW + y * 256;
        float* r1 = out + (size_t)(b * 256 + o1) * HW + y * 256;
#pragma unroll
        for (int na = 0; na < 8; na++) {
            int xq = x0 + wn * 64 + na * 8 + tq * 2;
            float2 w0; w0.x = acc[ma][na][0]; w0.y = acc[ma][na][1];
            float2 w1; w1.x = acc[ma][na][2]; w1.y = acc[ma][na][3];
            *(float2*)(r0 + xq) = w0;
            *(float2*)(r1 + xq) = w1;
        }
    }
}

// ---------------- launch ----------------------------------------------------
extern "C" void kernel_launch(void* const* d_in, const int* in_sizes, int n_in,
                              void* d_out, int out_size) {
    const float* x     = (const float*)d_in[0];
    const float* wqkv  = (const float*)d_in[1];
    const float* rel   = (const float*)d_in[2];
    const float* w_ax  = (const float*)d_in[3];
    const float* b_ax  = (const float*)d_in[4];
    const float* w_ay  = (const float*)d_in[5];
    const float* b_ay  = (const float*)d_in[6];
    const float* w_dw  = (const float*)d_in[7];
    const float* gm    = (const float*)d_in[8];
    const float* bt    = (const float*)d_in[9];
    const float* mn    = (const float*)d_in[10];
    const float* vr    = (const float*)d_in[11];
    const float* w_pr  = (const float*)d_in[12];
    float* out = (float*)d_out;

    cudaFuncSetAttribute(conv2_mma_kernel, cudaFuncAttributeMaxDynamicSharedMemorySize, 55296);
    cudaFuncSetAttribute(qkv_mma_kernel, cudaFuncAttributeMaxDynamicSharedMemorySize, 73728);
    cudaFuncSetAttribute(proj_mma_kernel, cudaFuncAttributeMaxDynamicSharedMemorySize, 73728);

    aprep_kernel<<<4096, 256>>>(w_ax, w_ay);
    qprep_kernel<<<768, 256>>>(wqkv);
    pprep_kernel<<<256, 256>>>(w_pr);
    xprep_kernel<<<65536, 256>>>(x);
    qkv_mma_kernel<<<dim3(256, 2, 12), 256, 73728>>>();
    attn_kernel<<<dim3(2048, 16), 64>>>(rel);
    conv2_mma_kernel<<<dim3(256, 2, 4), 256, 55296>>>(b_ax, b_ay);
    dwbn_kernel<<<dim3(64, 128, 2), 256>>>(w_dw, gm, bt, mn, vr);
    proj_mma_kernel<<<dim3(256, 2, 4), 256, 73728>>>(out);
}

// round 13
// speedup vs baseline: 2.2245x; 1.0304x over previous
#include <cuda_runtime.h>
#include <cuda_bf16.h>
#include <cuda_fp16.h>
#include <cstdint>

#define HW 65536
#define CC 256

// ---------------- scratch ---------------------------------------------------
__device__ float g_big[100663296];
// g_obn: attn writes split fp16 planes (hi [0,33.5M) half, lo [33.5M,67M) half);
//        dwbn later overwrites with channel-paired split fp16 planes for proj
__device__ float g_obn[33554432];
// conv weights: single fp16 plane per (mt, stage): [128 o][72 k]
__device__ __align__(16) __half g_wA[1179648];
// qkv weights: single fp16 plane per (mt 0..5, s 0..3): [128 o][72 k]
__device__ __align__(16) __half g_wQ[221184];
// proj weights: single fp16 plane per (mt 0..1, s 0..3)
__device__ __align__(16) __half g_wP[73728];
// input x split fp16, channel-paired: hi pairs [0,16.7M), lo pairs [16.7M,33.5M) half2
__device__ __align__(16) __half g_xsplit[67108864];

// ---------------- helpers ---------------------------------------------------
__device__ __forceinline__ uint32_t smem_u32(const void* p) {
    uint32_t a;
    asm("{ .reg .u64 t; cvta.to.shared.u64 t, %1; cvt.u32.u64 %0, t; }" : "=r"(a) : "l"(p));
    return a;
}
__device__ __forceinline__ void ldsm4(uint32_t& r0, uint32_t& r1, uint32_t& r2, uint32_t& r3,
                                      uint32_t addr) {
    asm volatile("ldmatrix.sync.aligned.m8n8.x4.shared.b16 {%0,%1,%2,%3}, [%4];"
                 : "=r"(r0), "=r"(r1), "=r"(r2), "=r"(r3) : "r"(addr));
}
__device__ __forceinline__ void mma16816h(float* c, uint32_t a0, uint32_t a1, uint32_t a2,
                                          uint32_t a3, uint32_t b0, uint32_t b1) {
    asm volatile("mma.sync.aligned.m16n8k16.row.col.f32.f16.f16.f32 "
                 "{%0,%1,%2,%3}, {%4,%5,%6,%7}, {%8,%9}, {%0,%1,%2,%3};"
                 : "+f"(c[0]), "+f"(c[1]), "+f"(c[2]), "+f"(c[3])
                 : "r"(a0), "r"(a1), "r"(a2), "r"(a3), "r"(b0), "r"(b1));
}
__device__ __forceinline__ void split2h(float v0, float v1, __half2& ph, __half2& pl) {
    __half h0 = __float2half_rn(v0), h1 = __float2half_rn(v1);
    ph.x = h0; ph.y = h1;
    pl.x = __float2half_rn(v0 - __half2float(h0));
    pl.y = __float2half_rn(v1 - __half2float(h1));
}
__device__ __forceinline__ void cpa16(uint32_t dst, const void* src) {
    asm volatile("cp.async.cg.shared.global [%0], [%1], 16;" :: "r"(dst), "l"(src));
}
__device__ __forceinline__ void cpa_commit() {
    asm volatile("cp.async.commit_group;");
}
__device__ __forceinline__ void cpa_wait() {
    asm volatile("cp.async.wait_group 0;" ::: "memory");
}

// ---------------- weight/input prep kernels --------------------------------
__global__ void aprep_kernel(const float* __restrict__ wx, const float* __restrict__ wy) {
    int e = blockIdx.x * 256 + threadIdx.x;     // < 1048576 (k<64)
    if (e >= 1048576) return;
    int k = e & 63, o_l = (e >> 6) & 127, s = (e >> 13) & 63, mt = e >> 19;
    int c = 4 * s + (k >> 4);
    int conv = (k >> 3) & 1, tap = k & 7;
    int o = mt * 128 + o_l;
    float v = (conv ? wy : wx)[(o * 256 + c) * 8 + tap];
    g_wA[(size_t)(mt * 64 + s) * 9216 + o_l * 72 + k] = __float2half_rn(v);
}
__global__ void qprep_kernel(const float* __restrict__ wqkv) {
    int e = blockIdx.x * 256 + threadIdx.x;     // < 196608
    if (e >= 196608) return;
    int k = e & 63, o_l = (e >> 6) & 127, s = (e >> 13) & 3, mt = e >> 15;
    float v = wqkv[(mt * 128 + o_l) * 256 + s * 64 + k];
    g_wQ[(size_t)(mt * 4 + s) * 9216 + o_l * 72 + k] = __float2half_rn(v);
}
__global__ void pprep_kernel(const float* __restrict__ wp) {
    int e = blockIdx.x * 256 + threadIdx.x;     // < 65536
    int k = e & 63, o_l = (e >> 6) & 127, s = (e >> 13) & 3, mt = e >> 15;
    float v = wp[(mt * 128 + o_l) * 256 + s * 64 + k];
    g_wP[(size_t)(mt * 4 + s) * 9216 + o_l * 72 + k] = __float2half_rn(v);
}
__global__ void xprep_kernel(const float* __restrict__ x) {
    int g = blockIdx.x * 256 + threadIdx.x;
    int pos = g & (HW - 1);
    int cpb = g >> 16;
    const float* src = x + (size_t)(2 * cpb) * HW + pos;
    float v0 = src[0], v1 = src[HW];
    __half2 h, l;
    split2h(v0, v1, h, l);
    ((__half2*)g_xsplit)[g] = h;
    ((__half2*)g_xsplit)[g + 16777216] = l;
}

// ---------------- shared fp16 2-pass consume (A single, B hi/lo) ------------
#define MMA_CONSUME_H(BBASE)                                                             \
    do {                                                                                 \
        _Pragma("unroll")                                                                \
        for (int kstep = 0; kstep < 4; kstep++) {                                        \
            uint32_t ah[2][4];                                                           \
            _Pragma("unroll")                                                            \
            for (int ma = 0; ma < 2; ma++) {                                             \
                uint32_t aaddr = a_base + a_loff + ma * 16 * 144 + kstep * 32;           \
                ldsm4(ah[ma][0], ah[ma][1], ah[ma][2], ah[ma][3], aaddr);                \
            }                                                                            \
            _Pragma("unroll")                                                            \
            for (int nc = 0; nc < 4; nc++) {                                             \
                uint32_t baddr = (BBASE) + b_loff + (wn * 64 + nc * 16) * 144 + kstep * 32; \
                uint32_t bh0, bh1, bh2, bh3, bl0, bl1, bl2, bl3;                         \
                ldsm4(bh0, bh1, bh2, bh3, baddr);                                        \
                ldsm4(bl0, bl1, bl2, bl3, baddr + 18432);                                \
                _Pragma("unroll")                                                        \
                for (int ma = 0; ma < 2; ma++) {                                         \
                    mma16816h(acc[ma][nc * 2 + 0], ah[ma][0], ah[ma][1], ah[ma][2], ah[ma][3], bh0, bh1); \
                    mma16816h(acc[ma][nc * 2 + 1], ah[ma][0], ah[ma][1], ah[ma][2], ah[ma][3], bh2, bh3); \
                    mma16816h(acc[ma][nc * 2 + 0], ah[ma][0], ah[ma][1], ah[ma][2], ah[ma][3], bl0, bl1); \
                    mma16816h(acc[ma][nc * 2 + 1], ah[ma][0], ah[ma][1], ah[ma][2], ah[ma][3], bl2, bl3); \
                }                                                                        \
            }                                                                            \
        }                                                                                \
    } while (0)

// ---------------- kernel A: qkv via fp16 2-pass mma -------------------------
__global__ void __launch_bounds__(256, 2) qkv_mma_kernel() {
    extern __shared__ __align__(16) char dsm[];
    __half* Asm = (__half*)dsm;                  // [128][72] fp16 = 18432 B
    __half* Bsm = (__half*)(dsm + 18432);        // hi 9216 elems, lo +9216 elems
    int t = threadIdx.x, wid = t >> 5, lane = t & 31;
    int y = blockIdx.x, b = blockIdx.y, z = blockIdx.z;
    int mt = z >> 1, nt = z & 1;
    int x0 = nt * 128;
    int wm = wid & 3, wn = wid >> 2;

    float acc[2][8][4];
#pragma unroll
    for (int i = 0; i < 2; i++)
#pragma unroll
        for (int j = 0; j < 8; j++)
#pragma unroll
            for (int r = 0; r < 4; r++) acc[i][j][r] = 0.f;

    uint32_t a_base = smem_u32(Asm);
    uint32_t b_base = smem_u32(Bsm);
    uint32_t a_loff = (uint32_t)((wm * 32 + (lane & 15)) * 144 + (lane >> 4) * 16);
    uint32_t b_loff = (uint32_t)(((lane & 7) + ((lane >> 4) << 3)) * 144 + ((lane >> 3) & 1) * 16);

    const __half2* xph = (const __half2*)g_xsplit;
    const __half2* xpl = xph + 16777216;
    size_t rowb = (size_t)(b * 128) * HW + y * 256 + x0;

    for (int s = 0; s < 4; s++) {
        const float4* wsrc = (const float4*)(g_wQ + (size_t)(mt * 4 + s) * 9216);
#pragma unroll
        for (int i = 0; i < 5; i++) {
            int e = t + (i << 8);
            if (e < 1152) cpa16(a_base + e * 16, wsrc + e);
        }

        int cp0 = s * 32;
#pragma unroll
        for (int i = 0; i < 16; i++) {
            int id = t + (i << 8);
            int xl = id & 127, j = id >> 7;
            size_t g = rowb + (size_t)(cp0 + j) * HW + xl;
            int idx = xl * 72 + 2 * j;
            *(__half2*)(Bsm + idx) = xph[g];
            *(__half2*)(Bsm + 9216 + idx) = xpl[g];
        }
        cpa_commit();
        cpa_wait();
        __syncthreads();
        MMA_CONSUME_H(b_base);
        __syncthreads();
    }

    int g = lane >> 2, tq = lane & 3;
    int win_row = b * 1024 + (y >> 3) * 32;
    int tokb = (y & 7) * 8;
#pragma unroll
    for (int ma = 0; ma < 2; ma++) {
        int o_a = mt * 128 + wm * 32 + ma * 16 + g;
        int o_b = o_a + 8;
        int sel_a = o_a >> 8, h_a = (o_a >> 4) & 15, dd_a = o_a & 15;
        int sel_b = o_b >> 8, h_b = (o_b >> 4) & 15, dd_b = o_b & 15;
#pragma unroll
        for (int na = 0; na < 8; na++) {
            int xq = x0 + wn * 64 + na * 8 + tq * 2;
            int win = win_row + (xq >> 3);
            int tok = tokb + (xq & 7);
            size_t pa = (size_t)sel_a * 33554432 + (size_t)((win * 16 + h_a) * 64 + tok) * 16 + dd_a;
            size_t pb = (size_t)sel_b * 33554432 + (size_t)((win * 16 + h_b) * 64 + tok) * 16 + dd_b;
            g_big[pa] = acc[ma][na][0];
            g_big[pa + 16] = acc[ma][na][1];
            g_big[pb] = acc[ma][na][2];
            g_big[pb + 16] = acc[ma][na][3];
        }
    }
}

// ---------------- kernel B: window attention (fp16 split planes out) --------
__global__ void __launch_bounds__(64) attn_kernel(const float* __restrict__ rel_table) {
    __shared__ float ks[1024], vs[1024], bs[232];
    int t = threadIdx.x;
    int w = blockIdx.x;
    int h = blockIdx.y;
    size_t base = ((size_t)(w * 16 + h)) * 1024;
    const float* gq = g_big;
    const float* gk = g_big + 33554432;
    const float* gv = g_big + 67108864;
#pragma unroll
    for (int i = 0; i < 4; i++) {
        *(float4*)(ks + t * 16 + i * 4) = *(const float4*)(gk + base + t * 16 + i * 4);
        *(float4*)(vs + t * 16 + i * 4) = *(const float4*)(gv + base + t * 16 + i * 4);
    }
    for (int r = t; r < 225; r += 64) bs[r] = rel_table[r * 16 + h];
    __syncthreads();

    float q[16];
#pragma unroll
    for (int i = 0; i < 4; i++)
        *(float4*)(q + i * 4) = *(const float4*)(gq + base + t * 16 + i * 4);
    int i1 = t >> 3, i2 = t & 7;

    float d[64];
#pragma unroll
    for (int j = 0; j < 64; j++) {
        const float4* kp = (const float4*)(ks + j * 16);
        float4 k0 = kp[0], k1 = kp[1], k2 = kp[2], k3 = kp[3];
        float s = q[0] * k0.x + q[1] * k0.y + q[2] * k0.z + q[3] * k0.w +
                  q[4] * k1.x + q[5] * k1.y + q[6] * k1.z + q[7] * k1.w +
                  q[8] * k2.x + q[9] * k2.y + q[10] * k2.z + q[11] * k2.w +
                  q[12] * k3.x + q[13] * k3.y + q[14] * k3.z + q[15] * k3.w;
        int j1 = j >> 3, j2 = j & 7;
        d[j] = 0.25f * s + bs[(i1 - j1 + 7) * 15 + (i2 - j2 + 7)];
    }
    float m = -1e30f;
#pragma unroll
    for (int j = 0; j < 64; j++) m = fmaxf(m, d[j]);
    float sum = 0.f;
#pragma unroll
    for (int j = 0; j < 64; j++) { d[j] = __expf(d[j] - m); sum += d[j]; }
    float inv = 1.0f / sum;

    float acc[16] = {};
#pragma unroll
    for (int j = 0; j < 64; j++) {
        float a = d[j] * inv;
        const float4* vp = (const float4*)(vs + j * 16);
        float4 v0 = vp[0], v1 = vp[1], v2 = vp[2], v3 = vp[3];
        acc[0] += a * v0.x;  acc[1] += a * v0.y;  acc[2] += a * v0.z;  acc[3] += a * v0.w;
        acc[4] += a * v1.x;  acc[5] += a * v1.y;  acc[6] += a * v1.z;  acc[7] += a * v1.w;
        acc[8] += a * v2.x;  acc[9] += a * v2.y;  acc[10] += a * v2.z; acc[11] += a * v2.w;
        acc[12] += a * v3.x; acc[13] += a * v3.y; acc[14] += a * v3.z; acc[15] += a * v3.w;
    }
    int b = w >> 10, wy = (w >> 5) & 31, wx = w & 31;
    int y = wy * 8 + i1, xq = wx * 8 + i2;
    __half* ophi = (__half*)g_obn;
    __half* oplo = ophi + 33554432;
    size_t ob = ((size_t)(b * 256 + h * 16)) * HW + y * 256 + xq;
#pragma unroll
    for (int e = 0; e < 16; e++) {
        float v = acc[e];
        __half hh = __float2half_rn(v);
        ophi[ob + (size_t)e * HW] = hh;
        oplo[ob + (size_t)e * HW] = __float2half_rn(v - __half2float(hh));
    }
}

// ---------------- kernel C: conv2 via fp16 2-pass mma (exact R12) -----------
__device__ __forceinline__ __half ldph(const __half* p, int r, int q) {
    if ((unsigned)r > 256u || (unsigned)q > 256u) return __float2half_rn(0.f);
    return p[((r == 256) ? 254 : r) * 256 + ((q == 256) ? 254 : q)];
}

__global__ void __launch_bounds__(256, 2) conv2_mma_kernel(const float* __restrict__ bias_x,
                                                           const float* __restrict__ bias_y) {
    extern __shared__ __align__(16) char dsm[];
    __half* Asm = (__half*)dsm;
    __half* Bsm = (__half*)(dsm + 18432);
    int t = threadIdx.x, wid = t >> 5, lane = t & 31;
    int y = blockIdx.x, b = blockIdx.y, z = blockIdx.z;
    int mt = z >> 1, nt = z & 1;
    int x0 = nt * 128;
    int wm = wid & 3, wn = wid >> 2;
    const __half* ophi = (const __half*)g_obn;
    const __half* oplo = ophi + 33554432;
    size_t cbase = (size_t)b * CC * HW;

    float acc[2][8][4];
#pragma unroll
    for (int i = 0; i < 2; i++)
#pragma unroll
        for (int j = 0; j < 8; j++)
#pragma unroll
            for (int r = 0; r < 4; r++) acc[i][j][r] = 0.f;

    uint32_t a_base = smem_u32(Asm);
    uint32_t b_base = smem_u32(Bsm);
    uint32_t a_loff = (uint32_t)((wm * 32 + (lane & 15)) * 144 + (lane >> 4) * 16);
    uint32_t b_loff = (uint32_t)(((lane & 7) + ((lane >> 4) << 3)) * 144 + ((lane >> 3) & 1) * 16);

    for (int s = 0; s < 64; s++) {
        const float4* wsrc = (const float4*)(g_wA + (size_t)(mt * 64 + s) * 9216);
#pragma unroll
        for (int i = 0; i < 5; i++) {
            int e = t + (i << 8);
            if (e < 1152) cpa16(a_base + e * 16, wsrc + e);
        }

        int c0 = 4 * s;
#pragma unroll
        for (int i = 0; i < 8; i++) {           // vertical taps
            int id = t + (i << 8);
            int xl = id & 127, u = id >> 7;
            int c_l = u >> 2, rp = u & 3;
            const __half* chi = ophi + cbase + (size_t)(c0 + c_l) * HW;
            const __half* clo = oplo + cbase + (size_t)(c0 + c_l) * HW;
            int xq = x0 + xl;
            int r0 = y - 3 + 2 * rp, r1 = r0 + 1;
            __half2 ph, pl;
            ph.x = ldph(chi, r0, xq); ph.y = ldph(chi, r1, xq);
            pl.x = ldph(clo, r0, xq); pl.y = ldph(clo, r1, xq);
            int idx = xl * 72 + c_l * 16 + 2 * rp;
            *(__half2*)(Bsm + idx) = ph;
            *(__half2*)(Bsm + 9216 + idx) = pl;
        }
#pragma unroll
        for (int i = 0; i < 8; i++) {           // horizontal taps
            int id = t + (i << 8);
            int xl = id & 127, u = id >> 7;
            int c_l = u >> 2, tp = u & 3;
            const __half* chi = ophi + cbase + (size_t)(c0 + c_l) * HW;
            const __half* clo = oplo + cbase + (size_t)(c0 + c_l) * HW;
            int xq = x0 + xl;
            int q0 = xq + 2 * tp - 3, q1 = q0 + 1;
            __half2 ph, pl;
            ph.x = ldph(chi, y, q0); ph.y = ldph(chi, y, q1);
            pl.x = ldph(clo, y, q0); pl.y = ldph(clo, y, q1);
            int idx = xl * 72 + c_l * 16 + 8 + 2 * tp;
            *(__half2*)(Bsm + idx) = ph;
            *(__half2*)(Bsm + 9216 + idx) = pl;
        }
        cpa_commit();
        cpa_wait();
        __syncthreads();
        MMA_CONSUME_H(b_base);
        __syncthreads();
    }

    // epilogue: bias + float2 stores
    float* out1 = g_big;
    int g = lane >> 2, tq = lane & 3;
#pragma unroll
    for (int ma = 0; ma < 2; ma++) {
        int o_base = mt * 128 + wm * 32 + ma * 16;
        int o0 = o_base + g, o1 = o_base + g + 8;
        float bia0 = bias_x[o0] + bias_y[o0];
        float bia1 = bias_x[o1] + bias_y[o1];
        float* r0 = out1 + (size_t)(b * 256 + o0) * HW + y * 256;
        float* r1 = out1 + (size_t)(b * 256 + o1) * HW + y * 256;
#pragma unroll
        for (int na = 0; na < 8; na++) {
            int xq = x0 + wn * 64 + na * 8 + tq * 2;
            float2 w0; w0.x = acc[ma][na][0] + bia0; w0.y = acc[ma][na][1] + bia0;
            float2 w1; w1.x = acc[ma][na][2] + bia1; w1.y = acc[ma][na][3] + bia1;
            *(float2*)(r0 + xq) = w0;
            *(float2*)(r1 + xq) = w1;
        }
    }
}

// ---------------- kernel D: depthwise 8x8 + BN, fp16 split pairs out --------
__global__ void __launch_bounds__(256) dwbn_kernel(const float* __restrict__ wdw,
                                                   const float* __restrict__ gamma,
                                                   const float* __restrict__ beta,
                                                   const float* __restrict__ mean,
                                                   const float* __restrict__ var) {
    __shared__ float S[2][1560];
    __shared__ float ws[128];
    int t = threadIdx.x;
    int tile = blockIdx.x;
    int cp = blockIdx.y, b = blockIdx.z;
    int c0 = 2 * cp;
    int y0 = (tile >> 3) * 32, x0 = (tile & 7) * 32;
#pragma unroll
    for (int ch = 0; ch < 2; ch++) {
        const float* in = g_big + ((size_t)(b * 256 + c0 + ch)) * HW;
        for (int e = t; e < 39 * 39; e += 256) {
            int r = e / 39, j = e - r * 39;
            int row = y0 - 3 + r, col = x0 - 3 + j;
            float v = 0.f;
            if (row >= 0 && row <= 256 && col >= 0 && col <= 256) {
                int rr = (row == 256) ? 254 : row;
                int cc = (col == 256) ? 254 : col;
                v = in[rr * 256 + cc];
            }
            S[ch][r * 40 + j] = v;
        }
    }
    if (t < 128) ws[t] = wdw[c0 * 64 + t];
    __syncthreads();

    int ly = t >> 3, lx0 = (t & 7) * 4;
    float acc[2][4] = {};
#pragma unroll
    for (int ch = 0; ch < 2; ch++) {
#pragma unroll
        for (int ky = 0; ky < 8; ky++) {
            float rv[11];
#pragma unroll
            for (int u = 0; u < 11; u++) rv[u] = S[ch][(ly + ky) * 40 + lx0 + u];
#pragma unroll
            for (int kx = 0; kx < 8; kx++) {
                float wv = ws[ch * 64 + ky * 8 + kx];
#pragma unroll
                for (int j = 0; j < 4; j++) acc[ch][j] += wv * rv[kx + j];
            }
        }
    }
    float iv0 = rsqrtf(var[c0] + 1e-5f), iv1 = rsqrtf(var[c0 + 1] + 1e-5f);
    float sc0 = gamma[c0] * iv0, sc1 = gamma[c0 + 1] * iv1;
    float sh0 = beta[c0] - mean[c0] * sc0, sh1 = beta[c0 + 1] - mean[c0 + 1] * sc1;
    __half2* oh = (__half2*)g_obn;
    __half2* ol = oh + 16777216;
    size_t g = ((size_t)(b * 128 + cp)) * HW + (y0 + ly) * 256 + x0 + lx0;
#pragma unroll
    for (int j = 0; j < 4; j++) {
        float u0 = acc[0][j] * sc0 + sh0;
        float u1 = acc[1][j] * sc1 + sh1;
        __half2 hh, ll;
        split2h(u0, u1, hh, ll);
        oh[g + j] = hh;
        ol[g + j] = ll;
    }
}

// ---------------- kernel E: proj via fp16 2-pass mma -> d_out ---------------
__global__ void __launch_bounds__(256, 2) proj_mma_kernel(float* __restrict__ out) {
    extern __shared__ __align__(16) char dsm[];
    __half* Asm = (__half*)dsm;
    __half* Bsm = (__half*)(dsm + 18432);
    int t = threadIdx.x, wid = t >> 5, lane = t & 31;
    int y = blockIdx.x, b = blockIdx.y, z = blockIdx.z;
    int mt = z >> 1, nt = z & 1;
    int x0 = nt * 128;
    int wm = wid & 3, wn = wid >> 2;

    float acc[2][8][4];
#pragma unroll
    for (int i = 0; i < 2; i++)
#pragma unroll
        for (int j = 0; j < 8; j++)
#pragma unroll
            for (int r = 0; r < 4; r++) acc[i][j][r] = 0.f;

    uint32_t a_base = smem_u32(Asm);
    uint32_t b_base = smem_u32(Bsm);
    uint32_t a_loff = (uint32_t)((wm * 32 + (lane & 15)) * 144 + (lane >> 4) * 16);
    uint32_t b_loff = (uint32_t)(((lane & 7) + ((lane >> 4) << 3)) * 144 + ((lane >> 3) & 1) * 16);

    const __half2* dph = (const __half2*)g_obn;
    const __half2* dpl = dph + 16777216;
    size_t rowb = (size_t)(b * 128) * HW + y * 256 + x0;

    for (int s = 0; s < 4; s++) {
        const float4* wsrc = (const float4*)(g_wP + (size_t)(mt * 4 + s) * 9216);
#pragma unroll
        for (int i = 0; i < 5; i++) {
            int e = t + (i << 8);
            if (e < 1152) cpa16(a_base + e * 16, wsrc + e);
        }

        int cp0 = s * 32;
#pragma unroll
        for (int i = 0; i < 16; i++) {
            int id = t + (i << 8);
            int xl = id & 127, j = id >> 7;
            size_t g = rowb + (size_t)(cp0 + j) * HW + xl;
            int idx = xl * 72 + 2 * j;
            *(__half2*)(Bsm + idx) = dph[g];
            *(__half2*)(Bsm + 9216 + idx) = dpl[g];
        }
        cpa_commit();
        cpa_wait();
        __syncthreads();
        MMA_CONSUME_H(b_base);
        __syncthreads();
    }

    int g = lane >> 2, tq = lane & 3;
#pragma unroll
    for (int ma = 0; ma < 2; ma++) {
        int o_base = mt * 128 + wm * 32 + ma * 16;
        int o0 = o_base + g, o1 = o_base + g + 8;
        float* r0 = out + (size_t)(b * 256 + o0) * HW + y * 256;
        float* r1 = out + (size_t)(b * 256 + o1) * HW + y * 256;
#pragma unroll
        for (int na = 0; na < 8; na++) {
            int xq = x0 + wn * 64 + na * 8 + tq * 2;
            float2 w0; w0.x = acc[ma][na][0]; w0.y = acc[ma][na][1];
            float2 w1; w1.x = acc[ma][na][2]; w1.y = acc[ma][na][3];
            *(float2*)(r0 + xq) = w0;
            *(float2*)(r1 + xq) = w1;
        }
    }
}

// ---------------- launch ----------------------------------------------------
extern "C" void kernel_launch(void* const* d_in, const int* in_sizes, int n_in,
                              void* d_out, int out_size) {
    const float* x     = (const float*)d_in[0];
    const float* wqkv  = (const float*)d_in[1];
    const float* rel   = (const float*)d_in[2];
    const float* w_ax  = (const float*)d_in[3];
    const float* b_ax  = (const float*)d_in[4];
    const float* w_ay  = (const float*)d_in[5];
    const float* b_ay  = (const float*)d_in[6];
    const float* w_dw  = (const float*)d_in[7];
    const float* gm    = (const float*)d_in[8];
    const float* bt    = (const float*)d_in[9];
    const float* mn    = (const float*)d_in[10];
    const float* vr    = (const float*)d_in[11];
    const float* w_pr  = (const float*)d_in[12];
    float* out = (float*)d_out;

    cudaFuncSetAttribute(conv2_mma_kernel, cudaFuncAttributeMaxDynamicSharedMemorySize, 55296);
    cudaFuncSetAttribute(qkv_mma_kernel, cudaFuncAttributeMaxDynamicSharedMemorySize, 55296);
    cudaFuncSetAttribute(proj_mma_kernel, cudaFuncAttributeMaxDynamicSharedMemorySize, 55296);

    aprep_kernel<<<4096, 256>>>(w_ax, w_ay);
    qprep_kernel<<<768, 256>>>(wqkv);
    pprep_kernel<<<256, 256>>>(w_pr);
    xprep_kernel<<<65536, 256>>>(x);
    qkv_mma_kernel<<<dim3(256, 2, 12), 256, 55296>>>();
    attn_kernel<<<dim3(2048, 16), 64>>>(rel);
    conv2_mma_kernel<<<dim3(256, 2, 4), 256, 55296>>>(b_ax, b_ay);
    dwbn_kernel<<<dim3(64, 128, 2), 256>>>(w_dw, gm, bt, mn, vr);
    proj_mma_kernel<<<dim3(256, 2, 4), 256, 55296>>>(out);
}

// round 15
// speedup vs baseline: 2.9333x; 1.3186x over previous
#include <cuda_runtime.h>
#include <cuda_bf16.h>
#include <cuda_fp16.h>
#include <cstdint>

#define HW 65536
#define CC 256

// ---------------- scratch ---------------------------------------------------
__device__ float g_big[100663296];
// g_obn: attn writes single fp16 plane (hi [0,33.5M) half);
//        dwbn later overwrites with channel-paired split fp16 planes for proj
__device__ float g_obn[33554432];
// conv weights: single fp16 plane per (mt, stage): [128 o][72 k]
__device__ __align__(16) __half g_wA[1179648];
// qkv weights: single fp16 plane per (mt 0..5, s 0..3): [128 o][72 k]
__device__ __align__(16) __half g_wQ[221184];
// proj weights: single fp16 plane per (mt 0..1, s 0..3)
__device__ __align__(16) __half g_wP[73728];
// input x split fp16, channel-paired: hi pairs [0,16.7M), lo pairs [16.7M,33.5M) half2
__device__ __align__(16) __half g_xsplit[67108864];

// ---------------- helpers ---------------------------------------------------
__device__ __forceinline__ uint32_t smem_u32(const void* p) {
    uint32_t a;
    asm("{ .reg .u64 t; cvta.to.shared.u64 t, %1; cvt.u32.u64 %0, t; }" : "=r"(a) : "l"(p));
    return a;
}
__device__ __forceinline__ void ldsm4(uint32_t& r0, uint32_t& r1, uint32_t& r2, uint32_t& r3,
                                      uint32_t addr) {
    asm volatile("ldmatrix.sync.aligned.m8n8.x4.shared.b16 {%0,%1,%2,%3}, [%4];"
                 : "=r"(r0), "=r"(r1), "=r"(r2), "=r"(r3) : "r"(addr));
}
__device__ __forceinline__ void mma16816h(float* c, uint32_t a0, uint32_t a1, uint32_t a2,
                                          uint32_t a3, uint32_t b0, uint32_t b1) {
    asm volatile("mma.sync.aligned.m16n8k16.row.col.f32.f16.f16.f32 "
                 "{%0,%1,%2,%3}, {%4,%5,%6,%7}, {%8,%9}, {%0,%1,%2,%3};"
                 : "+f"(c[0]), "+f"(c[1]), "+f"(c[2]), "+f"(c[3])
                 : "r"(a0), "r"(a1), "r"(a2), "r"(a3), "r"(b0), "r"(b1));
}
__device__ __forceinline__ void split2h(float v0, float v1, __half2& ph, __half2& pl) {
    __half h0 = __float2half_rn(v0), h1 = __float2half_rn(v1);
    ph.x = h0; ph.y = h1;
    pl.x = __float2half_rn(v0 - __half2float(h0));
    pl.y = __float2half_rn(v1 - __half2float(h1));
}
__device__ __forceinline__ void cpa16(uint32_t dst, const void* src) {
    asm volatile("cp.async.cg.shared.global [%0], [%1], 16;" :: "r"(dst), "l"(src));
}
__device__ __forceinline__ void cpa_commit() {
    asm volatile("cp.async.commit_group;");
}
__device__ __forceinline__ void cpa_wait() {
    asm volatile("cp.async.wait_group 0;" ::: "memory");
}

// ---------------- weight/input prep kernels --------------------------------
__global__ void aprep_kernel(const float* __restrict__ wx, const float* __restrict__ wy) {
    int e = blockIdx.x * 256 + threadIdx.x;     // < 1048576 (k<64)
    if (e >= 1048576) return;
    int k = e & 63, o_l = (e >> 6) & 127, s = (e >> 13) & 63, mt = e >> 19;
    int c = 4 * s + (k >> 4);
    int conv = (k >> 3) & 1, tap = k & 7;
    int o = mt * 128 + o_l;
    float v = (conv ? wy : wx)[(o * 256 + c) * 8 + tap];
    g_wA[(size_t)(mt * 64 + s) * 9216 + o_l * 72 + k] = __float2half_rn(v);
}
__global__ void qprep_kernel(const float* __restrict__ wqkv) {
    int e = blockIdx.x * 256 + threadIdx.x;     // < 196608
    if (e >= 196608) return;
    int k = e & 63, o_l = (e >> 6) & 127, s = (e >> 13) & 3, mt = e >> 15;
    float v = wqkv[(mt * 128 + o_l) * 256 + s * 64 + k];
    g_wQ[(size_t)(mt * 4 + s) * 9216 + o_l * 72 + k] = __float2half_rn(v);
}
__global__ void pprep_kernel(const float* __restrict__ wp) {
    int e = blockIdx.x * 256 + threadIdx.x;     // < 65536
    int k = e & 63, o_l = (e >> 6) & 127, s = (e >> 13) & 3, mt = e >> 15;
    float v = wp[(mt * 128 + o_l) * 256 + s * 64 + k];
    g_wP[(size_t)(mt * 4 + s) * 9216 + o_l * 72 + k] = __float2half_rn(v);
}
__global__ void xprep_kernel(const float* __restrict__ x) {
    int g = blockIdx.x * 256 + threadIdx.x;
    int pos = g & (HW - 1);
    int cpb = g >> 16;
    const float* src = x + (size_t)(2 * cpb) * HW + pos;
    float v0 = src[0], v1 = src[HW];
    __half2 h, l;
    split2h(v0, v1, h, l);
    ((__half2*)g_xsplit)[g] = h;
    ((__half2*)g_xsplit)[g + 16777216] = l;
}

// ---------------- fp16 2-pass consume (A single, B hi/lo) — qkv/proj --------
#define MMA_CONSUME_H(BBASE)                                                             \
    do {                                                                                 \
        _Pragma("unroll")                                                                \
        for (int kstep = 0; kstep < 4; kstep++) {                                        \
            uint32_t ah[2][4];                                                           \
            _Pragma("unroll")                                                            \
            for (int ma = 0; ma < 2; ma++) {                                             \
                uint32_t aaddr = a_base + a_loff + ma * 16 * 144 + kstep * 32;           \
                ldsm4(ah[ma][0], ah[ma][1], ah[ma][2], ah[ma][3], aaddr);                \
            }                                                                            \
            _Pragma("unroll")                                                            \
            for (int nc = 0; nc < 4; nc++) {                                             \
                uint32_t baddr = (BBASE) + b_loff + (wn * 64 + nc * 16) * 144 + kstep * 32; \
                uint32_t bh0, bh1, bh2, bh3, bl0, bl1, bl2, bl3;                         \
                ldsm4(bh0, bh1, bh2, bh3, baddr);                                        \
                ldsm4(bl0, bl1, bl2, bl3, baddr + 18432);                                \
                _Pragma("unroll")                                                        \
                for (int ma = 0; ma < 2; ma++) {                                         \
                    mma16816h(acc[ma][nc * 2 + 0], ah[ma][0], ah[ma][1], ah[ma][2], ah[ma][3], bh0, bh1); \
                    mma16816h(acc[ma][nc * 2 + 1], ah[ma][0], ah[ma][1], ah[ma][2], ah[ma][3], bh2, bh3); \
                    mma16816h(acc[ma][nc * 2 + 0], ah[ma][0], ah[ma][1], ah[ma][2], ah[ma][3], bl0, bl1); \
                    mma16816h(acc[ma][nc * 2 + 1], ah[ma][0], ah[ma][1], ah[ma][2], ah[ma][3], bl2, bl3); \
                }                                                                        \
            }                                                                            \
        }                                                                                \
    } while (0)

// ---------------- fp16 1-pass consume (A single, B single) — conv2 ----------
#define MMA_CONSUME_H1(BBASE)                                                            \
    do {                                                                                 \
        _Pragma("unroll")                                                                \
        for (int kstep = 0; kstep < 4; kstep++) {                                        \
            uint32_t ah[2][4];                                                           \
            _Pragma("unroll")                                                            \
            for (int ma = 0; ma < 2; ma++) {                                             \
                uint32_t aaddr = a_base + a_loff + ma * 16 * 144 + kstep * 32;           \
                ldsm4(ah[ma][0], ah[ma][1], ah[ma][2], ah[ma][3], aaddr);                \
            }                                                                            \
            _Pragma("unroll")                                                            \
            for (int nc = 0; nc < 4; nc++) {                                             \
                uint32_t baddr = (BBASE) + b_loff + (wn * 64 + nc * 16) * 144 + kstep * 32; \
                uint32_t bh0, bh1, bh2, bh3;                                             \
                ldsm4(bh0, bh1, bh2, bh3, baddr);                                        \
                _Pragma("unroll")                                                        \
                for (int ma = 0; ma < 2; ma++) {                                         \
                    mma16816h(acc[ma][nc * 2 + 0], ah[ma][0], ah[ma][1], ah[ma][2], ah[ma][3], bh0, bh1); \
                    mma16816h(acc[ma][nc * 2 + 1], ah[ma][0], ah[ma][1], ah[ma][2], ah[ma][3], bh2, bh3); \
                }                                                                        \
            }                                                                            \
        }                                                                                \
    } while (0)

// ---------------- kernel A: qkv via fp16 2-pass mma (exact R13) -------------
__global__ void __launch_bounds__(256, 2) qkv_mma_kernel() {
    extern __shared__ __align__(16) char dsm[];
    __half* Asm = (__half*)dsm;                  // [128][72] fp16 = 18432 B
    __half* Bsm = (__half*)(dsm + 18432);        // hi 9216 elems, lo +9216 elems
    int t = threadIdx.x, wid = t >> 5, lane = t & 31;
    int y = blockIdx.x, b = blockIdx.y, z = blockIdx.z;
    int mt = z >> 1, nt = z & 1;
    int x0 = nt * 128;
    int wm = wid & 3, wn = wid >> 2;

    float acc[2][8][4];
#pragma unroll
    for (int i = 0; i < 2; i++)
#pragma unroll
        for (int j = 0; j < 8; j++)
#pragma unroll
            for (int r = 0; r < 4; r++) acc[i][j][r] = 0.f;

    uint32_t a_base = smem_u32(Asm);
    uint32_t b_base = smem_u32(Bsm);
    uint32_t a_loff = (uint32_t)((wm * 32 + (lane & 15)) * 144 + (lane >> 4) * 16);
    uint32_t b_loff = (uint32_t)(((lane & 7) + ((lane >> 4) << 3)) * 144 + ((lane >> 3) & 1) * 16);

    const __half2* xph = (const __half2*)g_xsplit;
    const __half2* xpl = xph + 16777216;
    size_t rowb = (size_t)(b * 128) * HW + y * 256 + x0;

    for (int s = 0; s < 4; s++) {
        const float4* wsrc = (const float4*)(g_wQ + (size_t)(mt * 4 + s) * 9216);
#pragma unroll
        for (int i = 0; i < 5; i++) {
            int e = t + (i << 8);
            if (e < 1152) cpa16(a_base + e * 16, wsrc + e);
        }

        int cp0 = s * 32;
#pragma unroll
        for (int i = 0; i < 16; i++) {
            int id = t + (i << 8);
            int xl = id & 127, j = id >> 7;
            size_t g = rowb + (size_t)(cp0 + j) * HW + xl;
            int idx = xl * 72 + 2 * j;
            *(__half2*)(Bsm + idx) = xph[g];
            *(__half2*)(Bsm + 9216 + idx) = xpl[g];
        }
        cpa_commit();
        cpa_wait();
        __syncthreads();
        MMA_CONSUME_H(b_base);
        __syncthreads();
    }

    int g = lane >> 2, tq = lane & 3;
    int win_row = b * 1024 + (y >> 3) * 32;
    int tokb = (y & 7) * 8;
#pragma unroll
    for (int ma = 0; ma < 2; ma++) {
        int o_a = mt * 128 + wm * 32 + ma * 16 + g;
        int o_b = o_a + 8;
        int sel_a = o_a >> 8, h_a = (o_a >> 4) & 15, dd_a = o_a & 15;
        int sel_b = o_b >> 8, h_b = (o_b >> 4) & 15, dd_b = o_b & 15;
#pragma unroll
        for (int na = 0; na < 8; na++) {
            int xq = x0 + wn * 64 + na * 8 + tq * 2;
            int win = win_row + (xq >> 3);
            int tok = tokb + (xq & 7);
            size_t pa = (size_t)sel_a * 33554432 + (size_t)((win * 16 + h_a) * 64 + tok) * 16 + dd_a;
            size_t pb = (size_t)sel_b * 33554432 + (size_t)((win * 16 + h_b) * 64 + tok) * 16 + dd_b;
            g_big[pa] = acc[ma][na][0];
            g_big[pa + 16] = acc[ma][na][1];
            g_big[pb] = acc[ma][na][2];
            g_big[pb + 16] = acc[ma][na][3];
        }
    }
}

// ---------------- kernel B: window attention (single fp16 plane out) --------
__global__ void __launch_bounds__(64) attn_kernel(const float* __restrict__ rel_table) {
    __shared__ float ks[1024], vs[1024], bs[232];
    int t = threadIdx.x;
    int w = blockIdx.x;
    int h = blockIdx.y;
    size_t base = ((size_t)(w * 16 + h)) * 1024;
    const float* gq = g_big;
    const float* gk = g_big + 33554432;
    const float* gv = g_big + 67108864;
#pragma unroll
    for (int i = 0; i < 4; i++) {
        *(float4*)(ks + t * 16 + i * 4) = *(const float4*)(gk + base + t * 16 + i * 4);
        *(float4*)(vs + t * 16 + i * 4) = *(const float4*)(gv + base + t * 16 + i * 4);
    }
    for (int r = t; r < 225; r += 64) bs[r] = rel_table[r * 16 + h];
    __syncthreads();

    float q[16];
#pragma unroll
    for (int i = 0; i < 4; i++)
        *(float4*)(q + i * 4) = *(const float4*)(gq + base + t * 16 + i * 4);
    int i1 = t >> 3, i2 = t & 7;

    float d[64];
#pragma unroll
    for (int j = 0; j < 64; j++) {
        const float4* kp = (const float4*)(ks + j * 16);
        float4 k0 = kp[0], k1 = kp[1], k2 = kp[2], k3 = kp[3];
        float s = q[0] * k0.x + q[1] * k0.y + q[2] * k0.z + q[3] * k0.w +
                  q[4] * k1.x + q[5] * k1.y + q[6] * k1.z + q[7] * k1.w +
                  q[8] * k2.x + q[9] * k2.y + q[10] * k2.z + q[11] * k2.w +
                  q[12] * k3.x + q[13] * k3.y + q[14] * k3.z + q[15] * k3.w;
        int j1 = j >> 3, j2 = j & 7;
        d[j] = 0.25f * s + bs[(i1 - j1 + 7) * 15 + (i2 - j2 + 7)];
    }
    float m = -1e30f;
#pragma unroll
    for (int j = 0; j < 64; j++) m = fmaxf(m, d[j]);
    float sum = 0.f;
#pragma unroll
    for (int j = 0; j < 64; j++) { d[j] = __expf(d[j] - m); sum += d[j]; }
    float inv = 1.0f / sum;

    float acc[16] = {};
#pragma unroll
    for (int j = 0; j < 64; j++) {
        float a = d[j] * inv;
        const float4* vp = (const float4*)(vs + j * 16);
        float4 v0 = vp[0], v1 = vp[1], v2 = vp[2], v3 = vp[3];
        acc[0] += a * v0.x;  acc[1] += a * v0.y;  acc[2] += a * v0.z;  acc[3] += a * v0.w;
        acc[4] += a * v1.x;  acc[5] += a * v1.y;  acc[6] += a * v1.z;  acc[7] += a * v1.w;
        acc[8] += a * v2.x;  acc[9] += a * v2.y;  acc[10] += a * v2.z; acc[11] += a * v2.w;
        acc[12] += a * v3.x; acc[13] += a * v3.y; acc[14] += a * v3.z; acc[15] += a * v3.w;
    }
    int b = w >> 10, wy = (w >> 5) & 31, wx = w & 31;
    int y = wy * 8 + i1, xq = wx * 8 + i2;
    __half* ophi = (__half*)g_obn;
    size_t ob = ((size_t)(b * 256 + h * 16)) * HW + y * 256 + xq;
#pragma unroll
    for (int e = 0; e < 16; e++)
        ophi[ob + (size_t)e * HW] = __float2half_rn(acc[e]);
}

// ---------------- kernel C: conv2 via fp16 1-pass mma -----------------------
__device__ __forceinline__ __half ldph(const __half* p, int r, int q) {
    if ((unsigned)r > 256u || (unsigned)q > 256u) return __float2half_rn(0.f);
    return p[((r == 256) ? 254 : r) * 256 + ((q == 256) ? 254 : q)];
}

__global__ void __launch_bounds__(256, 2) conv2_mma_kernel(const float* __restrict__ bias_x,
                                                           const float* __restrict__ bias_y) {
    extern __shared__ __align__(16) char dsm[];
    __half* Asm = (__half*)dsm;                  // [128][72] fp16 = 18432 B
    __half* Bsm = (__half*)(dsm + 18432);        // [128 x][72 k] fp16 = 18432 B
    int t = threadIdx.x, wid = t >> 5, lane = t & 31;
    int y = blockIdx.x, b = blockIdx.y, z = blockIdx.z;
    int mt = z >> 1, nt = z & 1;
    int x0 = nt * 128;
    int wm = wid & 3, wn = wid >> 2;
    const __half* ophi = (const __half*)g_obn;
    size_t cbase = (size_t)b * CC * HW;

    float acc[2][8][4];
#pragma unroll
    for (int i = 0; i < 2; i++)
#pragma unroll
        for (int j = 0; j < 8; j++)
#pragma unroll
            for (int r = 0; r < 4; r++) acc[i][j][r] = 0.f;

    uint32_t a_base = smem_u32(Asm);
    uint32_t b_base = smem_u32(Bsm);
    uint32_t a_loff = (uint32_t)((wm * 32 + (lane & 15)) * 144 + (lane >> 4) * 16);
    uint32_t b_loff = (uint32_t)(((lane & 7) + ((lane >> 4) << 3)) * 144 + ((lane >> 3) & 1) * 16);

    for (int s = 0; s < 64; s++) {
        const float4* wsrc = (const float4*)(g_wA + (size_t)(mt * 64 + s) * 9216);
#pragma unroll
        for (int i = 0; i < 5; i++) {
            int e = t + (i << 8);
            if (e < 1152) cpa16(a_base + e * 16, wsrc + e);
        }

        int c0 = 4 * s;
#pragma unroll
        for (int i = 0; i < 8; i++) {           // vertical taps
            int id = t + (i << 8);
            int xl = id & 127, u = id >> 7;
            int c_l = u >> 2, rp = u & 3;
            const __half* chi = ophi + cbase + (size_t)(c0 + c_l) * HW;
            int xq = x0 + xl;
            int r0 = y - 3 + 2 * rp, r1 = r0 + 1;
            __half2 ph;
            ph.x = ldph(chi, r0, xq); ph.y = ldph(chi, r1, xq);
            *(__half2*)(Bsm + xl * 72 + c_l * 16 + 2 * rp) = ph;
        }
#pragma unroll
        for (int i = 0; i < 8; i++) {           // horizontal taps
            int id = t + (i << 8);
            int xl = id & 127, u = id >> 7;
            int c_l = u >> 2, tp = u & 3;
            const __half* chi = ophi + cbase + (size_t)(c0 + c_l) * HW;
            int xq = x0 + xl;
            int q0 = xq + 2 * tp - 3, q1 = q0 + 1;
            __half2 ph;
            ph.x = ldph(chi, y, q0); ph.y = ldph(chi, y, q1);
            *(__half2*)(Bsm + xl * 72 + c_l * 16 + 8 + 2 * tp) = ph;
        }
        cpa_commit();
        cpa_wait();
        __syncthreads();
        MMA_CONSUME_H1(b_base);
        __syncthreads();
    }

    // epilogue: bias + float2 stores
    float* out1 = g_big;
    int g = lane >> 2, tq = lane & 3;
#pragma unroll
    for (int ma = 0; ma < 2; ma++) {
        int o_base = mt * 128 + wm * 32 + ma * 16;
        int o0 = o_base + g, o1 = o_base + g + 8;
        float bia0 = bias_x[o0] + bias_y[o0];
        float bia1 = bias_x[o1] + bias_y[o1];
        float* r0 = out1 + (size_t)(b * 256 + o0) * HW + y * 256;
        float* r1 = out1 + (size_t)(b * 256 + o1) * HW + y * 256;
#pragma unroll
        for (int na = 0; na < 8; na++) {
            int xq = x0 + wn * 64 + na * 8 + tq * 2;
            float2 w0; w0.x = acc[ma][na][0] + bia0; w0.y = acc[ma][na][1] + bia0;
            float2 w1; w1.x = acc[ma][na][2] + bia1; w1.y = acc[ma][na][3] + bia1;
            *(float2*)(r0 + xq) = w0;
            *(float2*)(r1 + xq) = w1;
        }
    }
}

// ---------------- kernel D: depthwise 8x8 + BN, fp16 split pairs out --------
__global__ void __launch_bounds__(256) dwbn_kernel(const float* __restrict__ wdw,
                                                   const float* __restrict__ gamma,
                                                   const float* __restrict__ beta,
                                                   const float* __restrict__ mean,
                                                   const float* __restrict__ var) {
    __shared__ float S[2][1560];
    __shared__ float ws[128];
    int t = threadIdx.x;
    int tile = blockIdx.x;
    int cp = blockIdx.y, b = blockIdx.z;
    int c0 = 2 * cp;
    int y0 = (tile >> 3) * 32, x0 = (tile & 7) * 32;
#pragma unroll
    for (int ch = 0; ch < 2; ch++) {
        const float* in = g_big + ((size_t)(b * 256 + c0 + ch)) * HW;
        for (int e = t; e < 39 * 39; e += 256) {
            int r = e / 39, j = e - r * 39;
            int row = y0 - 3 + r, col = x0 - 3 + j;
            float v = 0.f;
            if (row >= 0 && row <= 256 && col >= 0 && col <= 256) {
                int rr = (row == 256) ? 254 : row;
                int cc = (col == 256) ? 254 : col;
                v = in[rr * 256 + cc];
            }
            S[ch][r * 40 + j] = v;
        }
    }
    if (t < 128) ws[t] = wdw[c0 * 64 + t];
    __syncthreads();

    int ly = t >> 3, lx0 = (t & 7) * 4;
    float acc[2][4] = {};
#pragma unroll
    for (int ch = 0; ch < 2; ch++) {
#pragma unroll
        for (int ky = 0; ky < 8; ky++) {
            float rv[11];
#pragma unroll
            for (int u = 0; u < 11; u++) rv[u] = S[ch][(ly + ky) * 40 + lx0 + u];
#pragma unroll
            for (int kx = 0; kx < 8; kx++) {
                float wv = ws[ch * 64 + ky * 8 + kx];
#pragma unroll
                for (int j = 0; j < 4; j++) acc[ch][j] += wv * rv[kx + j];
            }
        }
    }
    float iv0 = rsqrtf(var[c0] + 1e-5f), iv1 = rsqrtf(var[c0 + 1] + 1e-5f);
    float sc0 = gamma[c0] * iv0, sc1 = gamma[c0 + 1] * iv1;
    float sh0 = beta[c0] - mean[c0] * sc0, sh1 = beta[c0 + 1] - mean[c0 + 1] * sc1;
    __half2* oh = (__half2*)g_obn;
    __half2* ol = oh + 16777216;
    size_t g = ((size_t)(b * 128 + cp)) * HW + (y0 + ly) * 256 + x0 + lx0;
#pragma unroll
    for (int j = 0; j < 4; j++) {
        float u0 = acc[0][j] * sc0 + sh0;
        float u1 = acc[1][j] * sc1 + sh1;
        __half2 hh, ll;
        split2h(u0, u1, hh, ll);
        oh[g + j] = hh;
        ol[g + j] = ll;
    }
}

// ---------------- kernel E: proj via fp16 2-pass mma -> d_out (exact R13) ---
__global__ void __launch_bounds__(256, 2) proj_mma_kernel(float* __restrict__ out) {
    extern __shared__ __align__(16) char dsm[];
    __half* Asm = (__half*)dsm;
    __half* Bsm = (__half*)(dsm + 18432);
    int t = threadIdx.x, wid = t >> 5, lane = t & 31;
    int y = blockIdx.x, b = blockIdx.y, z = blockIdx.z;
    int mt = z >> 1, nt = z & 1;
    int x0 = nt * 128;
    int wm = wid & 3, wn = wid >> 2;

    float acc[2][8][4];
#pragma unroll
    for (int i = 0; i < 2; i++)
#pragma unroll
        for (int j = 0; j < 8; j++)
#pragma unroll
            for (int r = 0; r < 4; r++) acc[i][j][r] = 0.f;

    uint32_t a_base = smem_u32(Asm);
    uint32_t b_base = smem_u32(Bsm);
    uint32_t a_loff = (uint32_t)((wm * 32 + (lane & 15)) * 144 + (lane >> 4) * 16);
    uint32_t b_loff = (uint32_t)(((lane & 7) + ((lane >> 4) << 3)) * 144 + ((lane >> 3) & 1) * 16);

    const __half2* dph = (const __half2*)g_obn;
    const __half2* dpl = dph + 16777216;
    size_t rowb = (size_t)(b * 128) * HW + y * 256 + x0;

    for (int s = 0; s < 4; s++) {
        const float4* wsrc = (const float4*)(g_wP + (size_t)(mt * 4 + s) * 9216);
#pragma unroll
        for (int i = 0; i < 5; i++) {
            int e = t + (i << 8);
            if (e < 1152) cpa16(a_base + e * 16, wsrc + e);
        }

        int cp0 = s * 32;
#pragma unroll
        for (int i = 0; i < 16; i++) {
            int id = t + (i << 8);
            int xl = id & 127, j = id >> 7;
            size_t g = rowb + (size_t)(cp0 + j) * HW + xl;
            int idx = xl * 72 + 2 * j;
            *(__half2*)(Bsm + idx) = dph[g];
            *(__half2*)(Bsm + 9216 + idx) = dpl[g];
        }
        cpa_commit();
        cpa_wait();
        __syncthreads();
        MMA_CONSUME_H(b_base);
        __syncthreads();
    }

    int g = lane >> 2, tq = lane & 3;
#pragma unroll
    for (int ma = 0; ma < 2; ma++) {
        int o_base = mt * 128 + wm * 32 + ma * 16;
        int o0 = o_base + g, o1 = o_base + g + 8;
        float* r0 = out + (size_t)(b * 256 + o0) * HW + y * 256;
        float* r1 = out + (size_t)(b * 256 + o1) * HW + y * 256;
#pragma unroll
        for (int na = 0; na < 8; na++) {
            int xq = x0 + wn * 64 + na * 8 + tq * 2;
            float2 w0; w0.x = acc[ma][na][0]; w0.y = acc[ma][na][1];
            float2 w1; w1.x = acc[ma][na][2]; w1.y = acc[ma][na][3];
            *(float2*)(r0 + xq) = w0;
            *(float2*)(r1 + xq) = w1;
        }
    }
}

// ---------------- launch ----------------------------------------------------
extern "C" void kernel_launch(void* const* d_in, const int* in_sizes, int n_in,
                              void* d_out, int out_size) {
    const float* x     = (const float*)d_in[0];
    const float* wqkv  = (const float*)d_in[1];
    const float* rel   = (const float*)d_in[2];
    const float* w_ax  = (const float*)d_in[3];
    const float* b_ax  = (const float*)d_in[4];
    const float* w_ay  = (const float*)d_in[5];
    const float* b_ay  = (const float*)d_in[6];
    const float* w_dw  = (const float*)d_in[7];
    const float* gm    = (const float*)d_in[8];
    const float* bt    = (const float*)d_in[9];
    const float* mn    = (const float*)d_in[10];
    const float* vr    = (const float*)d_in[11];
    const float* w_pr  = (const float*)d_in[12];
    float* out = (float*)d_out;

    cudaFuncSetAttribute(conv2_mma_kernel, cudaFuncAttributeMaxDynamicSharedMemorySize, 36864);
    cudaFuncSetAttribute(qkv_mma_kernel, cudaFuncAttributeMaxDynamicSharedMemorySize, 55296);
    cudaFuncSetAttribute(proj_mma_kernel, cudaFuncAttributeMaxDynamicSharedMemorySize, 55296);

    aprep_kernel<<<4096, 256>>>(w_ax, w_ay);
    qprep_kernel<<<768, 256>>>(wqkv);
    pprep_kernel<<<256, 256>>>(w_pr);
    xprep_kernel<<<65536, 256>>>(x);
    qkv_mma_kernel<<<dim3(256, 2, 12), 256, 55296>>>();
    attn_kernel<<<dim3(2048, 16), 64>>>(rel);
    conv2_mma_kernel<<<dim3(256, 2, 4), 256, 36864>>>(b_ax, b_ay);
    dwbn_kernel<<<dim3(64, 128, 2), 256>>>(w_dw, gm, bt, mn, vr);
    proj_mma_kernel<<<dim3(256, 2, 4), 256, 55296>>>(out);
}

// round 16
// speedup vs baseline: 3.1592x; 1.0770x over previous
#include <cuda_runtime.h>
#include <cuda_bf16.h>
#include <cuda_fp16.h>
#include <cstdint>

#define HW 65536
#define CC 256

// ---------------- scratch ---------------------------------------------------
__device__ float g_big[100663296];
// g_obn: attn writes single fp16 plane; dwbn overwrites with channel-paired fp16
__device__ float g_obn[33554432];
// conv weights: single fp16 plane per (mt, stage): [128 o][72 k]
__device__ __align__(16) __half g_wA[1179648];
// qkv weights: single fp16 plane per (mt 0..5, s 0..3)
__device__ __align__(16) __half g_wQ[221184];
// proj weights: single fp16 plane per (mt 0..1, s 0..3)
__device__ __align__(16) __half g_wP[73728];
// input x fp16, channel-paired half2: [0,16.7M) pairs
__device__ __align__(16) __half g_xsplit[33554432];

// ---------------- helpers ---------------------------------------------------
__device__ __forceinline__ uint32_t smem_u32(const void* p) {
    uint32_t a;
    asm("{ .reg .u64 t; cvta.to.shared.u64 t, %1; cvt.u32.u64 %0, t; }" : "=r"(a) : "l"(p));
    return a;
}
__device__ __forceinline__ void ldsm4(uint32_t& r0, uint32_t& r1, uint32_t& r2, uint32_t& r3,
                                      uint32_t addr) {
    asm volatile("ldmatrix.sync.aligned.m8n8.x4.shared.b16 {%0,%1,%2,%3}, [%4];"
                 : "=r"(r0), "=r"(r1), "=r"(r2), "=r"(r3) : "r"(addr));
}
__device__ __forceinline__ void mma16816h(float* c, uint32_t a0, uint32_t a1, uint32_t a2,
                                          uint32_t a3, uint32_t b0, uint32_t b1) {
    asm volatile("mma.sync.aligned.m16n8k16.row.col.f32.f16.f16.f32 "
                 "{%0,%1,%2,%3}, {%4,%5,%6,%7}, {%8,%9}, {%0,%1,%2,%3};"
                 : "+f"(c[0]), "+f"(c[1]), "+f"(c[2]), "+f"(c[3])
                 : "r"(a0), "r"(a1), "r"(a2), "r"(a3), "r"(b0), "r"(b1));
}
__device__ __forceinline__ void cpa16(uint32_t dst, const void* src) {
    asm volatile("cp.async.cg.shared.global [%0], [%1], 16;" :: "r"(dst), "l"(src));
}
__device__ __forceinline__ void cpa_commit() {
    asm volatile("cp.async.commit_group;");
}
__device__ __forceinline__ void cpa_wait() {
    asm volatile("cp.async.wait_group 0;" ::: "memory");
}

// ---------------- weight/input prep kernels --------------------------------
__global__ void aprep_kernel(const float* __restrict__ wx, const float* __restrict__ wy) {
    int e = blockIdx.x * 256 + threadIdx.x;     // < 1048576 (k<64)
    if (e >= 1048576) return;
    int k = e & 63, o_l = (e >> 6) & 127, s = (e >> 13) & 63, mt = e >> 19;
    int c = 4 * s + (k >> 4);
    int conv = (k >> 3) & 1, tap = k & 7;
    int o = mt * 128 + o_l;
    float v = (conv ? wy : wx)[(o * 256 + c) * 8 + tap];
    g_wA[(size_t)(mt * 64 + s) * 9216 + o_l * 72 + k] = __float2half_rn(v);
}
__global__ void qprep_kernel(const float* __restrict__ wqkv) {
    int e = blockIdx.x * 256 + threadIdx.x;     // < 196608
    if (e >= 196608) return;
    int k = e & 63, o_l = (e >> 6) & 127, s = (e >> 13) & 3, mt = e >> 15;
    float v = wqkv[(mt * 128 + o_l) * 256 + s * 64 + k];
    g_wQ[(size_t)(mt * 4 + s) * 9216 + o_l * 72 + k] = __float2half_rn(v);
}
__global__ void pprep_kernel(const float* __restrict__ wp) {
    int e = blockIdx.x * 256 + threadIdx.x;     // < 65536
    int k = e & 63, o_l = (e >> 6) & 127, s = (e >> 13) & 3, mt = e >> 15;
    float v = wp[(mt * 128 + o_l) * 256 + s * 64 + k];
    g_wP[(size_t)(mt * 4 + s) * 9216 + o_l * 72 + k] = __float2half_rn(v);
}
__global__ void xprep_kernel(const float* __restrict__ x) {
    int g = blockIdx.x * 256 + threadIdx.x;
    int pos = g & (HW - 1);
    int cpb = g >> 16;
    const float* src = x + (size_t)(2 * cpb) * HW + pos;
    __half2 h;
    h.x = __float2half_rn(src[0]);
    h.y = __float2half_rn(src[HW]);
    ((__half2*)g_xsplit)[g] = h;
}

// ---------------- fp16 1-pass consume (A single, B single) ------------------
#define MMA_CONSUME_H1(BBASE)                                                            \
    do {                                                                                 \
        _Pragma("unroll")                                                                \
        for (int kstep = 0; kstep < 4; kstep++) {                                        \
            uint32_t ah[2][4];                                                           \
            _Pragma("unroll")                                                            \
            for (int ma = 0; ma < 2; ma++) {                                             \
                uint32_t aaddr = a_base + a_loff + ma * 16 * 144 + kstep * 32;           \
                ldsm4(ah[ma][0], ah[ma][1], ah[ma][2], ah[ma][3], aaddr);                \
            }                                                                            \
            _Pragma("unroll")                                                            \
            for (int nc = 0; nc < 4; nc++) {                                             \
                uint32_t baddr = (BBASE) + b_loff + (wn * 64 + nc * 16) * 144 + kstep * 32; \
                uint32_t bh0, bh1, bh2, bh3;                                             \
                ldsm4(bh0, bh1, bh2, bh3, baddr);                                        \
                _Pragma("unroll")                                                        \
                for (int ma = 0; ma < 2; ma++) {                                         \
                    mma16816h(acc[ma][nc * 2 + 0], ah[ma][0], ah[ma][1], ah[ma][2], ah[ma][3], bh0, bh1); \
                    mma16816h(acc[ma][nc * 2 + 1], ah[ma][0], ah[ma][1], ah[ma][2], ah[ma][3], bh2, bh3); \
                }                                                                        \
            }                                                                            \
        }                                                                                \
    } while (0)

// ---------------- kernel A: qkv via fp16 1-pass mma -------------------------
__global__ void __launch_bounds__(256, 2) qkv_mma_kernel() {
    extern __shared__ __align__(16) char dsm[];
    __half* Asm = (__half*)dsm;                  // [128][72] fp16 = 18432 B
    __half* Bsm = (__half*)(dsm + 18432);        // [128 x][72 k] fp16 = 18432 B
    int t = threadIdx.x, wid = t >> 5, lane = t & 31;
    int y = blockIdx.x, b = blockIdx.y, z = blockIdx.z;
    int mt = z >> 1, nt = z & 1;
    int x0 = nt * 128;
    int wm = wid & 3, wn = wid >> 2;

    float acc[2][8][4];
#pragma unroll
    for (int i = 0; i < 2; i++)
#pragma unroll
        for (int j = 0; j < 8; j++)
#pragma unroll
            for (int r = 0; r < 4; r++) acc[i][j][r] = 0.f;

    uint32_t a_base = smem_u32(Asm);
    uint32_t b_base = smem_u32(Bsm);
    uint32_t a_loff = (uint32_t)((wm * 32 + (lane & 15)) * 144 + (lane >> 4) * 16);
    uint32_t b_loff = (uint32_t)(((lane & 7) + ((lane >> 4) << 3)) * 144 + ((lane >> 3) & 1) * 16);

    const __half2* xph = (const __half2*)g_xsplit;
    size_t rowb = (size_t)(b * 128) * HW + y * 256 + x0;

    for (int s = 0; s < 4; s++) {
        const float4* wsrc = (const float4*)(g_wQ + (size_t)(mt * 4 + s) * 9216);
#pragma unroll
        for (int i = 0; i < 5; i++) {
            int e = t + (i << 8);
            if (e < 1152) cpa16(a_base + e * 16, wsrc + e);
        }

        int cp0 = s * 32;
#pragma unroll
        for (int i = 0; i < 16; i++) {
            int id = t + (i << 8);
            int xl = id & 127, j = id >> 7;
            size_t g = rowb + (size_t)(cp0 + j) * HW + xl;
            *(__half2*)(Bsm + xl * 72 + 2 * j) = xph[g];
        }
        cpa_commit();
        cpa_wait();
        __syncthreads();
        MMA_CONSUME_H1(b_base);
        __syncthreads();
    }

    int g = lane >> 2, tq = lane & 3;
    int win_row = b * 1024 + (y >> 3) * 32;
    int tokb = (y & 7) * 8;
#pragma unroll
    for (int ma = 0; ma < 2; ma++) {
        int o_a = mt * 128 + wm * 32 + ma * 16 + g;
        int o_b = o_a + 8;
        int sel_a = o_a >> 8, h_a = (o_a >> 4) & 15, dd_a = o_a & 15;
        int sel_b = o_b >> 8, h_b = (o_b >> 4) & 15, dd_b = o_b & 15;
#pragma unroll
        for (int na = 0; na < 8; na++) {
            int xq = x0 + wn * 64 + na * 8 + tq * 2;
            int win = win_row + (xq >> 3);
            int tok = tokb + (xq & 7);
            size_t pa = (size_t)sel_a * 33554432 + (size_t)((win * 16 + h_a) * 64 + tok) * 16 + dd_a;
            size_t pb = (size_t)sel_b * 33554432 + (size_t)((win * 16 + h_b) * 64 + tok) * 16 + dd_b;
            g_big[pa] = acc[ma][na][0];
            g_big[pa + 16] = acc[ma][na][1];
            g_big[pb] = acc[ma][na][2];
            g_big[pb + 16] = acc[ma][na][3];
        }
    }
}

// ---------------- kernel B: window attention (single fp16 plane out) --------
__global__ void __launch_bounds__(64) attn_kernel(const float* __restrict__ rel_table) {
    __shared__ float ks[1024], vs[1024], bs[232];
    int t = threadIdx.x;
    int w = blockIdx.x;
    int h = blockIdx.y;
    size_t base = ((size_t)(w * 16 + h)) * 1024;
    const float* gq = g_big;
    const float* gk = g_big + 33554432;
    const float* gv = g_big + 67108864;
#pragma unroll
    for (int i = 0; i < 4; i++) {
        *(float4*)(ks + t * 16 + i * 4) = *(const float4*)(gk + base + t * 16 + i * 4);
        *(float4*)(vs + t * 16 + i * 4) = *(const float4*)(gv + base + t * 16 + i * 4);
    }
    for (int r = t; r < 225; r += 64) bs[r] = rel_table[r * 16 + h];
    __syncthreads();

    float q[16];
#pragma unroll
    for (int i = 0; i < 4; i++)
        *(float4*)(q + i * 4) = *(const float4*)(gq + base + t * 16 + i * 4);
    int i1 = t >> 3, i2 = t & 7;

    float d[64];
#pragma unroll
    for (int j = 0; j < 64; j++) {
        const float4* kp = (const float4*)(ks + j * 16);
        float4 k0 = kp[0], k1 = kp[1], k2 = kp[2], k3 = kp[3];
        float s = q[0] * k0.x + q[1] * k0.y + q[2] * k0.z + q[3] * k0.w +
                  q[4] * k1.x + q[5] * k1.y + q[6] * k1.z + q[7] * k1.w +
                  q[8] * k2.x + q[9] * k2.y + q[10] * k2.z + q[11] * k2.w +
                  q[12] * k3.x + q[13] * k3.y + q[14] * k3.z + q[15] * k3.w;
        int j1 = j >> 3, j2 = j & 7;
        d[j] = 0.25f * s + bs[(i1 - j1 + 7) * 15 + (i2 - j2 + 7)];
    }
    float m = -1e30f;
#pragma unroll
    for (int j = 0; j < 64; j++) m = fmaxf(m, d[j]);
    float sum = 0.f;
#pragma unroll
    for (int j = 0; j < 64; j++) { d[j] = __expf(d[j] - m); sum += d[j]; }
    float inv = 1.0f / sum;

    float acc[16] = {};
#pragma unroll
    for (int j = 0; j < 64; j++) {
        float a = d[j] * inv;
        const float4* vp = (const float4*)(vs + j * 16);
        float4 v0 = vp[0], v1 = vp[1], v2 = vp[2], v3 = vp[3];
        acc[0] += a * v0.x;  acc[1] += a * v0.y;  acc[2] += a * v0.z;  acc[3] += a * v0.w;
        acc[4] += a * v1.x;  acc[5] += a * v1.y;  acc[6] += a * v1.z;  acc[7] += a * v1.w;
        acc[8] += a * v2.x;  acc[9] += a * v2.y;  acc[10] += a * v2.z; acc[11] += a * v2.w;
        acc[12] += a * v3.x; acc[13] += a * v3.y; acc[14] += a * v3.z; acc[15] += a * v3.w;
    }
    int b = w >> 10, wy = (w >> 5) & 31, wx = w & 31;
    int y = wy * 8 + i1, xq = wx * 8 + i2;
    __half* ophi = (__half*)g_obn;
    size_t ob = ((size_t)(b * 256 + h * 16)) * HW + y * 256 + xq;
#pragma unroll
    for (int e = 0; e < 16; e++)
        ophi[ob + (size_t)e * HW] = __float2half_rn(acc[e]);
}

// ---------------- kernel C: conv2 via fp16 1-pass mma (exact R15) -----------
__device__ __forceinline__ __half ldph(const __half* p, int r, int q) {
    if ((unsigned)r > 256u || (unsigned)q > 256u) return __float2half_rn(0.f);
    return p[((r == 256) ? 254 : r) * 256 + ((q == 256) ? 254 : q)];
}

__global__ void __launch_bounds__(256, 2) conv2_mma_kernel(const float* __restrict__ bias_x,
                                                           const float* __restrict__ bias_y) {
    extern __shared__ __align__(16) char dsm[];
    __half* Asm = (__half*)dsm;
    __half* Bsm = (__half*)(dsm + 18432);
    int t = threadIdx.x, wid = t >> 5, lane = t & 31;
    int y = blockIdx.x, b = blockIdx.y, z = blockIdx.z;
    int mt = z >> 1, nt = z & 1;
    int x0 = nt * 128;
    int wm = wid & 3, wn = wid >> 2;
    const __half* ophi = (const __half*)g_obn;
    size_t cbase = (size_t)b * CC * HW;

    float acc[2][8][4];
#pragma unroll
    for (int i = 0; i < 2; i++)
#pragma unroll
        for (int j = 0; j < 8; j++)
#pragma unroll
            for (int r = 0; r < 4; r++) acc[i][j][r] = 0.f;

    uint32_t a_base = smem_u32(Asm);
    uint32_t b_base = smem_u32(Bsm);
    uint32_t a_loff = (uint32_t)((wm * 32 + (lane & 15)) * 144 + (lane >> 4) * 16);
    uint32_t b_loff = (uint32_t)(((lane & 7) + ((lane >> 4) << 3)) * 144 + ((lane >> 3) & 1) * 16);

    for (int s = 0; s < 64; s++) {
        const float4* wsrc = (const float4*)(g_wA + (size_t)(mt * 64 + s) * 9216);
#pragma unroll
        for (int i = 0; i < 5; i++) {
            int e = t + (i << 8);
            if (e < 1152) cpa16(a_base + e * 16, wsrc + e);
        }

        int c0 = 4 * s;
#pragma unroll
        for (int i = 0; i < 8; i++) {           // vertical taps
            int id = t + (i << 8);
            int xl = id & 127, u = id >> 7;
            int c_l = u >> 2, rp = u & 3;
            const __half* chi = ophi + cbase + (size_t)(c0 + c_l) * HW;
            int xq = x0 + xl;
            int r0 = y - 3 + 2 * rp, r1 = r0 + 1;
            __half2 ph;
            ph.x = ldph(chi, r0, xq); ph.y = ldph(chi, r1, xq);
            *(__half2*)(Bsm + xl * 72 + c_l * 16 + 2 * rp) = ph;
        }
#pragma unroll
        for (int i = 0; i < 8; i++) {           // horizontal taps
            int id = t + (i << 8);
            int xl = id & 127, u = id >> 7;
            int c_l = u >> 2, tp = u & 3;
            const __half* chi = ophi + cbase + (size_t)(c0 + c_l) * HW;
            int xq = x0 + xl;
            int q0 = xq + 2 * tp - 3, q1 = q0 + 1;
            __half2 ph;
            ph.x = ldph(chi, y, q0); ph.y = ldph(chi, y, q1);
            *(__half2*)(Bsm + xl * 72 + c_l * 16 + 8 + 2 * tp) = ph;
        }
        cpa_commit();
        cpa_wait();
        __syncthreads();
        MMA_CONSUME_H1(b_base);
        __syncthreads();
    }

    // epilogue: bias + float2 stores
    float* out1 = g_big;
    int g = lane >> 2, tq = lane & 3;
#pragma unroll
    for (int ma = 0; ma < 2; ma++) {
        int o_base = mt * 128 + wm * 32 + ma * 16;
        int o0 = o_base + g, o1 = o_base + g + 8;
        float bia0 = bias_x[o0] + bias_y[o0];
        float bia1 = bias_x[o1] + bias_y[o1];
        float* r0 = out1 + (size_t)(b * 256 + o0) * HW + y * 256;
        float* r1 = out1 + (size_t)(b * 256 + o1) * HW + y * 256;
#pragma unroll
        for (int na = 0; na < 8; na++) {
            int xq = x0 + wn * 64 + na * 8 + tq * 2;
            float2 w0; w0.x = acc[ma][na][0] + bia0; w0.y = acc[ma][na][1] + bia0;
            float2 w1; w1.x = acc[ma][na][2] + bia1; w1.y = acc[ma][na][3] + bia1;
            *(float2*)(r0 + xq) = w0;
            *(float2*)(r1 + xq) = w1;
        }
    }
}

// ---------------- kernel D: depthwise 8x8 + BN, fp16 pairs out --------------
__global__ void __launch_bounds__(256) dwbn_kernel(const float* __restrict__ wdw,
                                                   const float* __restrict__ gamma,
                                                   const float* __restrict__ beta,
                                                   const float* __restrict__ mean,
                                                   const float* __restrict__ var) {
    __shared__ float S[2][1560];
    __shared__ float ws[128];
    int t = threadIdx.x;
    int tile = blockIdx.x;
    int cp = blockIdx.y, b = blockIdx.z;
    int c0 = 2 * cp;
    int y0 = (tile >> 3) * 32, x0 = (tile & 7) * 32;
#pragma unroll
    for (int ch = 0; ch < 2; ch++) {
        const float* in = g_big + ((size_t)(b * 256 + c0 + ch)) * HW;
        for (int e = t; e < 39 * 39; e += 256) {
            int r = e / 39, j = e - r * 39;
            int row = y0 - 3 + r, col = x0 - 3 + j;
            float v = 0.f;
            if (row >= 0 && row <= 256 && col >= 0 && col <= 256) {
                int rr = (row == 256) ? 254 : row;
                int cc = (col == 256) ? 254 : col;
                v = in[rr * 256 + cc];
            }
            S[ch][r * 40 + j] = v;
        }
    }
    if (t < 128) ws[t] = wdw[c0 * 64 + t];
    __syncthreads();

    int ly = t >> 3, lx0 = (t & 7) * 4;
    float acc[2][4] = {};
#pragma unroll
    for (int ch = 0; ch < 2; ch++) {
#pragma unroll
        for (int ky = 0; ky < 8; ky++) {
            float rv[11];
#pragma unroll
            for (int u = 0; u < 11; u++) rv[u] = S[ch][(ly + ky) * 40 + lx0 + u];
#pragma unroll
            for (int kx = 0; kx < 8; kx++) {
                float wv = ws[ch * 64 + ky * 8 + kx];
#pragma unroll
                for (int j = 0; j < 4; j++) acc[ch][j] += wv * rv[kx + j];
            }
        }
    }
    float iv0 = rsqrtf(var[c0] + 1e-5f), iv1 = rsqrtf(var[c0 + 1] + 1e-5f);
    float sc0 = gamma[c0] * iv0, sc1 = gamma[c0 + 1] * iv1;
    float sh0 = beta[c0] - mean[c0] * sc0, sh1 = beta[c0 + 1] - mean[c0 + 1] * sc1;
    __half2* oh = (__half2*)g_obn;
    size_t g = ((size_t)(b * 128 + cp)) * HW + (y0 + ly) * 256 + x0 + lx0;
#pragma unroll
    for (int j = 0; j < 4; j++) {
        float u0 = acc[0][j] * sc0 + sh0;
        float u1 = acc[1][j] * sc1 + sh1;
        __half2 hh;
        hh.x = __float2half_rn(u0);
        hh.y = __float2half_rn(u1);
        oh[g + j] = hh;
    }
}

// ---------------- kernel E: proj via fp16 1-pass mma -> d_out ---------------
__global__ void __launch_bounds__(256, 2) proj_mma_kernel(float* __restrict__ out) {
    extern __shared__ __align__(16) char dsm[];
    __half* Asm = (__half*)dsm;
    __half* Bsm = (__half*)(dsm + 18432);
    int t = threadIdx.x, wid = t >> 5, lane = t & 31;
    int y = blockIdx.x, b = blockIdx.y, z = blockIdx.z;
    int mt = z >> 1, nt = z & 1;
    int x0 = nt * 128;
    int wm = wid & 3, wn = wid >> 2;

    float acc[2][8][4];
#pragma unroll
    for (int i = 0; i < 2; i++)
#pragma unroll
        for (int j = 0; j < 8; j++)
#pragma unroll
            for (int r = 0; r < 4; r++) acc[i][j][r] = 0.f;

    uint32_t a_base = smem_u32(Asm);
    uint32_t b_base = smem_u32(Bsm);
    uint32_t a_loff = (uint32_t)((wm * 32 + (lane & 15)) * 144 + (lane >> 4) * 16);
    uint32_t b_loff = (uint32_t)(((lane & 7) + ((lane >> 4) << 3)) * 144 + ((lane >> 3) & 1) * 16);

    const __half2* dph = (const __half2*)g_obn;
    size_t rowb = (size_t)(b * 128) * HW + y * 256 + x0;

    for (int s = 0; s < 4; s++) {
        const float4* wsrc = (const float4*)(g_wP + (size_t)(mt * 4 + s) * 9216);
#pragma unroll
        for (int i = 0; i < 5; i++) {
            int e = t + (i << 8);
            if (e < 1152) cpa16(a_base + e * 16, wsrc + e);
        }

        int cp0 = s * 32;
#pragma unroll
        for (int i = 0; i < 16; i++) {
            int id = t + (i << 8);
            int xl = id & 127, j = id >> 7;
            size_t g = rowb + (size_t)(cp0 + j) * HW + xl;
            *(__half2*)(Bsm + xl * 72 + 2 * j) = dph[g];
        }
        cpa_commit();
        cpa_wait();
        __syncthreads();
        MMA_CONSUME_H1(b_base);
        __syncthreads();
    }

    int g = lane >> 2, tq = lane & 3;
#pragma unroll
    for (int ma = 0; ma < 2; ma++) {
        int o_base = mt * 128 + wm * 32 + ma * 16;
        int o0 = o_base + g, o1 = o_base + g + 8;
        float* r0 = out + (size_t)(b * 256 + o0) * HW + y * 256;
        float* r1 = out + (size_t)(b * 256 + o1) * HW + y * 256;
#pragma unroll
        for (int na = 0; na < 8; na++) {
            int xq = x0 + wn * 64 + na * 8 + tq * 2;
            float2 w0; w0.x = acc[ma][na][0]; w0.y = acc[ma][na][1];
            float2 w1; w1.x = acc[ma][na][2]; w1.y = acc[ma][na][3];
            *(float2*)(r0 + xq) = w0;
            *(float2*)(r1 + xq) = w1;
        }
    }
}

// ---------------- launch ----------------------------------------------------
extern "C" void kernel_launch(void* const* d_in, const int* in_sizes, int n_in,
                              void* d_out, int out_size) {
    const float* x     = (const float*)d_in[0];
    const float* wqkv  = (const float*)d_in[1];
    const float* rel   = (const float*)d_in[2];
    const float* w_ax  = (const float*)d_in[3];
    const float* b_ax  = (const float*)d_in[4];
    const float* w_ay  = (const float*)d_in[5];
    const float* b_ay  = (const float*)d_in[6];
    const float* w_dw  = (const float*)d_in[7];
    const float* gm    = (const float*)d_in[8];
    const float* bt    = (const float*)d_in[9];
    const float* mn    = (const float*)d_in[10];
    const float* vr    = (const float*)d_in[11];
    const float* w_pr  = (const float*)d_in[12];
    float* out = (float*)d_out;

    cudaFuncSetAttribute(conv2_mma_kernel, cudaFuncAttributeMaxDynamicSharedMemorySize, 36864);
    cudaFuncSetAttribute(qkv_mma_kernel, cudaFuncAttributeMaxDynamicSharedMemorySize, 36864);
    cudaFuncSetAttribute(proj_mma_kernel, cudaFuncAttributeMaxDynamicSharedMemorySize, 36864);

    aprep_kernel<<<4096, 256>>>(w_ax, w_ay);
    qprep_kernel<<<768, 256>>>(wqkv);
    pprep_kernel<<<256, 256>>>(w_pr);
    xprep_kernel<<<65536, 256>>>(x);
    qkv_mma_kernel<<<dim3(256, 2, 12), 256, 36864>>>();
    attn_kernel<<<dim3(2048, 16), 64>>>(rel);
    conv2_mma_kernel<<<dim3(256, 2, 4), 256, 36864>>>(b_ax, b_ay);
    dwbn_kernel<<<dim3(64, 128, 2), 256>>>(w_dw, gm, bt, mn, vr);
    proj_mma_kernel<<<dim3(256, 2, 4), 256, 36864>>>(out);
}

// round 17
// speedup vs baseline: 3.2470x; 1.0278x over previous
#include <cuda_runtime.h>
#include <cuda_bf16.h>
#include <cuda_fp16.h>
#include <cstdint>

#define HW 65536
#define CC 256

// ---------------- scratch ---------------------------------------------------
// g_big: q/k/v fp32 planes; later out1 as fp16 plane at base (reuse)
__device__ float g_big[100663296];
// g_obn: attn writes single fp16 plane; dwbn overwrites with channel-paired fp16
__device__ float g_obn[33554432];
// conv weights: single fp16 plane per (mt, stage): [128 o][72 k]
__device__ __align__(16) __half g_wA[1179648];
// qkv weights: single fp16 plane per (mt 0..5, s 0..3)
__device__ __align__(16) __half g_wQ[221184];
// proj weights: single fp16 plane per (mt 0..1, s 0..3)
__device__ __align__(16) __half g_wP[73728];

// ---------------- helpers ---------------------------------------------------
__device__ __forceinline__ uint32_t smem_u32(const void* p) {
    uint32_t a;
    asm("{ .reg .u64 t; cvta.to.shared.u64 t, %1; cvt.u32.u64 %0, t; }" : "=r"(a) : "l"(p));
    return a;
}
__device__ __forceinline__ void ldsm4(uint32_t& r0, uint32_t& r1, uint32_t& r2, uint32_t& r3,
                                      uint32_t addr) {
    asm volatile("ldmatrix.sync.aligned.m8n8.x4.shared.b16 {%0,%1,%2,%3}, [%4];"
                 : "=r"(r0), "=r"(r1), "=r"(r2), "=r"(r3) : "r"(addr));
}
__device__ __forceinline__ void mma16816h(float* c, uint32_t a0, uint32_t a1, uint32_t a2,
                                          uint32_t a3, uint32_t b0, uint32_t b1) {
    asm volatile("mma.sync.aligned.m16n8k16.row.col.f32.f16.f16.f32 "
                 "{%0,%1,%2,%3}, {%4,%5,%6,%7}, {%8,%9}, {%0,%1,%2,%3};"
                 : "+f"(c[0]), "+f"(c[1]), "+f"(c[2]), "+f"(c[3])
                 : "r"(a0), "r"(a1), "r"(a2), "r"(a3), "r"(b0), "r"(b1));
}
__device__ __forceinline__ void cpa16(uint32_t dst, const void* src) {
    asm volatile("cp.async.cg.shared.global [%0], [%1], 16;" :: "r"(dst), "l"(src));
}
__device__ __forceinline__ void cpa_commit() {
    asm volatile("cp.async.commit_group;");
}
__device__ __forceinline__ void cpa_wait() {
    asm volatile("cp.async.wait_group 0;" ::: "memory");
}

// ---------------- weight prep kernels --------------------------------------
__global__ void aprep_kernel(const float* __restrict__ wx, const float* __restrict__ wy) {
    int e = blockIdx.x * 256 + threadIdx.x;     // < 1048576 (k<64)
    if (e >= 1048576) return;
    int k = e & 63, o_l = (e >> 6) & 127, s = (e >> 13) & 63, mt = e >> 19;
    int c = 4 * s + (k >> 4);
    int conv = (k >> 3) & 1, tap = k & 7;
    int o = mt * 128 + o_l;
    float v = (conv ? wy : wx)[(o * 256 + c) * 8 + tap];
    g_wA[(size_t)(mt * 64 + s) * 9216 + o_l * 72 + k] = __float2half_rn(v);
}
__global__ void qprep_kernel(const float* __restrict__ wqkv) {
    int e = blockIdx.x * 256 + threadIdx.x;     // < 196608
    if (e >= 196608) return;
    int k = e & 63, o_l = (e >> 6) & 127, s = (e >> 13) & 3, mt = e >> 15;
    float v = wqkv[(mt * 128 + o_l) * 256 + s * 64 + k];
    g_wQ[(size_t)(mt * 4 + s) * 9216 + o_l * 72 + k] = __float2half_rn(v);
}
__global__ void pprep_kernel(const float* __restrict__ wp) {
    int e = blockIdx.x * 256 + threadIdx.x;     // < 65536
    int k = e & 63, o_l = (e >> 6) & 127, s = (e >> 13) & 3, mt = e >> 15;
    float v = wp[(mt * 128 + o_l) * 256 + s * 64 + k];
    g_wP[(size_t)(mt * 4 + s) * 9216 + o_l * 72 + k] = __float2half_rn(v);
}

// ---------------- fp16 1-pass consume (A single, B single) ------------------
#define MMA_CONSUME_H1(BBASE)                                                            \
    do {                                                                                 \
        _Pragma("unroll")                                                                \
        for (int kstep = 0; kstep < 4; kstep++) {                                        \
            uint32_t ah[2][4];                                                           \
            _Pragma("unroll")                                                            \
            for (int ma = 0; ma < 2; ma++) {                                             \
                uint32_t aaddr = a_base + a_loff + ma * 16 * 144 + kstep * 32;           \
                ldsm4(ah[ma][0], ah[ma][1], ah[ma][2], ah[ma][3], aaddr);                \
            }                                                                            \
            _Pragma("unroll")                                                            \
            for (int nc = 0; nc < 4; nc++) {                                             \
                uint32_t baddr = (BBASE) + b_loff + (wn * 64 + nc * 16) * 144 + kstep * 32; \
                uint32_t bh0, bh1, bh2, bh3;                                             \
                ldsm4(bh0, bh1, bh2, bh3, baddr);                                        \
                _Pragma("unroll")                                                        \
                for (int ma = 0; ma < 2; ma++) {                                         \
                    mma16816h(acc[ma][nc * 2 + 0], ah[ma][0], ah[ma][1], ah[ma][2], ah[ma][3], bh0, bh1); \
                    mma16816h(acc[ma][nc * 2 + 1], ah[ma][0], ah[ma][1], ah[ma][2], ah[ma][3], bh2, bh3); \
                }                                                                        \
            }                                                                            \
        }                                                                                \
    } while (0)

// ---------------- kernel A: qkv via fp16 1-pass mma (inline x convert) ------
__global__ void __launch_bounds__(256, 2) qkv_mma_kernel(const float* __restrict__ x) {
    extern __shared__ __align__(16) char dsm[];
    __half* Asm = (__half*)dsm;                  // [128][72] fp16 = 18432 B
    __half* Bsm = (__half*)(dsm + 18432);        // [128 x][72 k] fp16 = 18432 B
    int t = threadIdx.x, wid = t >> 5, lane = t & 31;
    int y = blockIdx.x, b = blockIdx.y, z = blockIdx.z;
    int mt = z >> 1, nt = z & 1;
    int x0 = nt * 128;
    int wm = wid & 3, wn = wid >> 2;

    float acc[2][8][4];
#pragma unroll
    for (int i = 0; i < 2; i++)
#pragma unroll
        for (int j = 0; j < 8; j++)
#pragma unroll
            for (int r = 0; r < 4; r++) acc[i][j][r] = 0.f;

    uint32_t a_base = smem_u32(Asm);
    uint32_t b_base = smem_u32(Bsm);
    uint32_t a_loff = (uint32_t)((wm * 32 + (lane & 15)) * 144 + (lane >> 4) * 16);
    uint32_t b_loff = (uint32_t)(((lane & 7) + ((lane >> 4) << 3)) * 144 + ((lane >> 3) & 1) * 16);

    const float* xb = x + (size_t)b * CC * HW + y * 256 + x0;

    for (int s = 0; s < 4; s++) {
        const float4* wsrc = (const float4*)(g_wQ + (size_t)(mt * 4 + s) * 9216);
#pragma unroll
        for (int i = 0; i < 5; i++) {
            int e = t + (i << 8);
            if (e < 1152) cpa16(a_base + e * 16, wsrc + e);
        }

        int c0 = s * 64;
#pragma unroll
        for (int i = 0; i < 16; i++) {
            int id = t + (i << 8);
            int xl = id & 127, j = id >> 7;       // j in [0,32): channel pair
            const float* src = xb + (size_t)(c0 + 2 * j) * HW + xl;
            __half2 h;
            h.x = __float2half_rn(src[0]);
            h.y = __float2half_rn(src[HW]);
            *(__half2*)(Bsm + xl * 72 + 2 * j) = h;
        }
        cpa_commit();
        cpa_wait();
        __syncthreads();
        MMA_CONSUME_H1(b_base);
        __syncthreads();
    }

    int g = lane >> 2, tq = lane & 3;
    int win_row = b * 1024 + (y >> 3) * 32;
    int tokb = (y & 7) * 8;
#pragma unroll
    for (int ma = 0; ma < 2; ma++) {
        int o_a = mt * 128 + wm * 32 + ma * 16 + g;
        int o_b = o_a + 8;
        int sel_a = o_a >> 8, h_a = (o_a >> 4) & 15, dd_a = o_a & 15;
        int sel_b = o_b >> 8, h_b = (o_b >> 4) & 15, dd_b = o_b & 15;
#pragma unroll
        for (int na = 0; na < 8; na++) {
            int xq = x0 + wn * 64 + na * 8 + tq * 2;
            int win = win_row + (xq >> 3);
            int tok = tokb + (xq & 7);
            size_t pa = (size_t)sel_a * 33554432 + (size_t)((win * 16 + h_a) * 64 + tok) * 16 + dd_a;
            size_t pb = (size_t)sel_b * 33554432 + (size_t)((win * 16 + h_b) * 64 + tok) * 16 + dd_b;
            g_big[pa] = acc[ma][na][0];
            g_big[pa + 16] = acc[ma][na][1];
            g_big[pb] = acc[ma][na][2];
            g_big[pb + 16] = acc[ma][na][3];
        }
    }
}

// ---------------- kernel B: window attention (single fp16 plane out) --------
__global__ void __launch_bounds__(64) attn_kernel(const float* __restrict__ rel_table) {
    __shared__ float ks[1024], vs[1024], bs[232];
    int t = threadIdx.x;
    int w = blockIdx.x;
    int h = blockIdx.y;
    size_t base = ((size_t)(w * 16 + h)) * 1024;
    const float* gq = g_big;
    const float* gk = g_big + 33554432;
    const float* gv = g_big + 67108864;
#pragma unroll
    for (int i = 0; i < 4; i++) {
        *(float4*)(ks + t * 16 + i * 4) = *(const float4*)(gk + base + t * 16 + i * 4);
        *(float4*)(vs + t * 16 + i * 4) = *(const float4*)(gv + base + t * 16 + i * 4);
    }
    for (int r = t; r < 225; r += 64) bs[r] = rel_table[r * 16 + h];
    __syncthreads();

    float q[16];
#pragma unroll
    for (int i = 0; i < 4; i++)
        *(float4*)(q + i * 4) = *(const float4*)(gq + base + t * 16 + i * 4);
    int i1 = t >> 3, i2 = t & 7;

    float d[64];
#pragma unroll
    for (int j = 0; j < 64; j++) {
        const float4* kp = (const float4*)(ks + j * 16);
        float4 k0 = kp[0], k1 = kp[1], k2 = kp[2], k3 = kp[3];
        float s = q[0] * k0.x + q[1] * k0.y + q[2] * k0.z + q[3] * k0.w +
                  q[4] * k1.x + q[5] * k1.y + q[6] * k1.z + q[7] * k1.w +
                  q[8] * k2.x + q[9] * k2.y + q[10] * k2.z + q[11] * k2.w +
                  q[12] * k3.x + q[13] * k3.y + q[14] * k3.z + q[15] * k3.w;
        int j1 = j >> 3, j2 = j & 7;
        d[j] = 0.25f * s + bs[(i1 - j1 + 7) * 15 + (i2 - j2 + 7)];
    }
    float m = -1e30f;
#pragma unroll
    for (int j = 0; j < 64; j++) m = fmaxf(m, d[j]);
    float sum = 0.f;
#pragma unroll
    for (int j = 0; j < 64; j++) { d[j] = __expf(d[j] - m); sum += d[j]; }
    float inv = 1.0f / sum;

    float acc[16] = {};
#pragma unroll
    for (int j = 0; j < 64; j++) {
        float a = d[j] * inv;
        const float4* vp = (const float4*)(vs + j * 16);
        float4 v0 = vp[0], v1 = vp[1], v2 = vp[2], v3 = vp[3];
        acc[0] += a * v0.x;  acc[1] += a * v0.y;  acc[2] += a * v0.z;  acc[3] += a * v0.w;
        acc[4] += a * v1.x;  acc[5] += a * v1.y;  acc[6] += a * v1.z;  acc[7] += a * v1.w;
        acc[8] += a * v2.x;  acc[9] += a * v2.y;  acc[10] += a * v2.z; acc[11] += a * v2.w;
        acc[12] += a * v3.x; acc[13] += a * v3.y; acc[14] += a * v3.z; acc[15] += a * v3.w;
    }
    int b = w >> 10, wy = (w >> 5) & 31, wx = w & 31;
    int y = wy * 8 + i1, xq = wx * 8 + i2;
    __half* ophi = (__half*)g_obn;
    size_t ob = ((size_t)(b * 256 + h * 16)) * HW + y * 256 + xq;
#pragma unroll
    for (int e = 0; e < 16; e++)
        ophi[ob + (size_t)e * HW] = __float2half_rn(acc[e]);
}

// ---------------- kernel C: conv2 via fp16 1-pass mma, fp16 out -------------
__device__ __forceinline__ __half ldph(const __half* p, int r, int q) {
    if ((unsigned)r > 256u || (unsigned)q > 256u) return __float2half_rn(0.f);
    return p[((r == 256) ? 254 : r) * 256 + ((q == 256) ? 254 : q)];
}

__global__ void __launch_bounds__(256, 2) conv2_mma_kernel(const float* __restrict__ bias_x,
                                                           const float* __restrict__ bias_y) {
    extern __shared__ __align__(16) char dsm[];
    __half* Asm = (__half*)dsm;
    __half* Bsm = (__half*)(dsm + 18432);
    int t = threadIdx.x, wid = t >> 5, lane = t & 31;
    int y = blockIdx.x, b = blockIdx.y, z = blockIdx.z;
    int mt = z >> 1, nt = z & 1;
    int x0 = nt * 128;
    int wm = wid & 3, wn = wid >> 2;
    const __half* ophi = (const __half*)g_obn;
    size_t cbase = (size_t)b * CC * HW;

    float acc[2][8][4];
#pragma unroll
    for (int i = 0; i < 2; i++)
#pragma unroll
        for (int j = 0; j < 8; j++)
#pragma unroll
            for (int r = 0; r < 4; r++) acc[i][j][r] = 0.f;

    uint32_t a_base = smem_u32(Asm);
    uint32_t b_base = smem_u32(Bsm);
    uint32_t a_loff = (uint32_t)((wm * 32 + (lane & 15)) * 144 + (lane >> 4) * 16);
    uint32_t b_loff = (uint32_t)(((lane & 7) + ((lane >> 4) << 3)) * 144 + ((lane >> 3) & 1) * 16);

    for (int s = 0; s < 64; s++) {
        const float4* wsrc = (const float4*)(g_wA + (size_t)(mt * 64 + s) * 9216);
#pragma unroll
        for (int i = 0; i < 5; i++) {
            int e = t + (i << 8);
            if (e < 1152) cpa16(a_base + e * 16, wsrc + e);
        }

        int c0 = 4 * s;
#pragma unroll
        for (int i = 0; i < 8; i++) {           // vertical taps
            int id = t + (i << 8);
            int xl = id & 127, u = id >> 7;
            int c_l = u >> 2, rp = u & 3;
            const __half* chi = ophi + cbase + (size_t)(c0 + c_l) * HW;
            int xq = x0 + xl;
            int r0 = y - 3 + 2 * rp, r1 = r0 + 1;
            __half2 ph;
            ph.x = ldph(chi, r0, xq); ph.y = ldph(chi, r1, xq);
            *(__half2*)(Bsm + xl * 72 + c_l * 16 + 2 * rp) = ph;
        }
#pragma unroll
        for (int i = 0; i < 8; i++) {           // horizontal taps
            int id = t + (i << 8);
            int xl = id & 127, u = id >> 7;
            int c_l = u >> 2, tp = u & 3;
            const __half* chi = ophi + cbase + (size_t)(c0 + c_l) * HW;
            int xq = x0 + xl;
            int q0 = xq + 2 * tp - 3, q1 = q0 + 1;
            __half2 ph;
            ph.x = ldph(chi, y, q0); ph.y = ldph(chi, y, q1);
            *(__half2*)(Bsm + xl * 72 + c_l * 16 + 8 + 2 * tp) = ph;
        }
        cpa_commit();
        cpa_wait();
        __syncthreads();
        MMA_CONSUME_H1(b_base);
        __syncthreads();
    }

    // epilogue: bias + half2 stores (out1 as fp16 plane in g_big)
    __half* out1 = (__half*)g_big;
    int g = lane >> 2, tq = lane & 3;
#pragma unroll
    for (int ma = 0; ma < 2; ma++) {
        int o_base = mt * 128 + wm * 32 + ma * 16;
        int o0 = o_base + g, o1 = o_base + g + 8;
        float bia0 = bias_x[o0] + bias_y[o0];
        float bia1 = bias_x[o1] + bias_y[o1];
        __half* r0 = out1 + (size_t)(b * 256 + o0) * HW + y * 256;
        __half* r1 = out1 + (size_t)(b * 256 + o1) * HW + y * 256;
#pragma unroll
        for (int na = 0; na < 8; na++) {
            int xq = x0 + wn * 64 + na * 8 + tq * 2;
            __half2 w0, w1;
            w0.x = __float2half_rn(acc[ma][na][0] + bia0);
            w0.y = __float2half_rn(acc[ma][na][1] + bia0);
            w1.x = __float2half_rn(acc[ma][na][2] + bia1);
            w1.y = __float2half_rn(acc[ma][na][3] + bia1);
            *(__half2*)(r0 + xq) = w0;
            *(__half2*)(r1 + xq) = w1;
        }
    }
}

// ---------------- kernel D: depthwise 8x8 + BN (fp16 in, fp16 pairs out) ----
__global__ void __launch_bounds__(256) dwbn_kernel(const float* __restrict__ wdw,
                                                   const float* __restrict__ gamma,
                                                   const float* __restrict__ beta,
                                                   const float* __restrict__ mean,
                                                   const float* __restrict__ var) {
    __shared__ float S[2][1560];
    __shared__ float ws[128];
    int t = threadIdx.x;
    int tile = blockIdx.x;
    int cp = blockIdx.y, b = blockIdx.z;
    int c0 = 2 * cp;
    int y0 = (tile >> 3) * 32, x0 = (tile & 7) * 32;
    const __half* in_base = (const __half*)g_big;
#pragma unroll
    for (int ch = 0; ch < 2; ch++) {
        const __half* in = in_base + ((size_t)(b * 256 + c0 + ch)) * HW;
        for (int e = t; e < 39 * 39; e += 256) {
            int r = e / 39, j = e - r * 39;
            int row = y0 - 3 + r, col = x0 - 3 + j;
            float v = 0.f;
            if (row >= 0 && row <= 256 && col >= 0 && col <= 256) {
                int rr = (row == 256) ? 254 : row;
                int cc = (col == 256) ? 254 : col;
                v = __half2float(in[rr * 256 + cc]);
            }
            S[ch][r * 40 + j] = v;
        }
    }
    if (t < 128) ws[t] = wdw[c0 * 64 + t];
    __syncthreads();

    int ly = t >> 3, lx0 = (t & 7) * 4;
    float acc[2][4] = {};
#pragma unroll
    for (int ch = 0; ch < 2; ch++) {
#pragma unroll
        for (int ky = 0; ky < 8; ky++) {
            float rv[11];
#pragma unroll
            for (int u = 0; u < 11; u++) rv[u] = S[ch][(ly + ky) * 40 + lx0 + u];
#pragma unroll
            for (int kx = 0; kx < 8; kx++) {
                float wv = ws[ch * 64 + ky * 8 + kx];
#pragma unroll
                for (int j = 0; j < 4; j++) acc[ch][j] += wv * rv[kx + j];
            }
        }
    }
    float iv0 = rsqrtf(var[c0] + 1e-5f), iv1 = rsqrtf(var[c0 + 1] + 1e-5f);
    float sc0 = gamma[c0] * iv0, sc1 = gamma[c0 + 1] * iv1;
    float sh0 = beta[c0] - mean[c0] * sc0, sh1 = beta[c0 + 1] - mean[c0 + 1] * sc1;
    __half2* oh = (__half2*)g_obn;
    size_t g = ((size_t)(b * 128 + cp)) * HW + (y0 + ly) * 256 + x0 + lx0;
#pragma unroll
    for (int j = 0; j < 4; j++) {
        float u0 = acc[0][j] * sc0 + sh0;
        float u1 = acc[1][j] * sc1 + sh1;
        __half2 hh;
        hh.x = __float2half_rn(u0);
        hh.y = __float2half_rn(u1);
        oh[g + j] = hh;
    }
}

// ---------------- kernel E: proj via fp16 1-pass mma -> d_out ---------------
__global__ void __launch_bounds__(256, 2) proj_mma_kernel(float* __restrict__ out) {
    extern __shared__ __align__(16) char dsm[];
    __half* Asm = (__half*)dsm;
    __half* Bsm = (__half*)(dsm + 18432);
    int t = threadIdx.x, wid = t >> 5, lane = t & 31;
    int y = blockIdx.x, b = blockIdx.y, z = blockIdx.z;
    int mt = z >> 1, nt = z & 1;
    int x0 = nt * 128;
    int wm = wid & 3, wn = wid >> 2;

    float acc[2][8][4];
#pragma unroll
    for (int i = 0; i < 2; i++)
#pragma unroll
        for (int j = 0; j < 8; j++)
#pragma unroll
            for (int r = 0; r < 4; r++) acc[i][j][r] = 0.f;

    uint32_t a_base = smem_u32(Asm);
    uint32_t b_base = smem_u32(Bsm);
    uint32_t a_loff = (uint32_t)((wm * 32 + (lane & 15)) * 144 + (lane >> 4) * 16);
    uint32_t b_loff = (uint32_t)(((lane & 7) + ((lane >> 4) << 3)) * 144 + ((lane >> 3) & 1) * 16);

    const __half2* dph = (const __half2*)g_obn;
    size_t rowb = (size_t)(b * 128) * HW + y * 256 + x0;

    for (int s = 0; s < 4; s++) {
        const float4* wsrc = (const float4*)(g_wP + (size_t)(mt * 4 + s) * 9216);
#pragma unroll
        for (int i = 0; i < 5; i++) {
            int e = t + (i << 8);
            if (e < 1152) cpa16(a_base + e * 16, wsrc + e);
        }

        int cp0 = s * 32;
#pragma unroll
        for (int i = 0; i < 16; i++) {
            int id = t + (i << 8);
            int xl = id & 127, j = id >> 7;
            size_t g = rowb + (size_t)(cp0 + j) * HW + xl;
            *(__half2*)(Bsm + xl * 72 + 2 * j) = dph[g];
        }
        cpa_commit();
        cpa_wait();
        __syncthreads();
        MMA_CONSUME_H1(b_base);
        __syncthreads();
    }

    int g = lane >> 2, tq = lane & 3;
#pragma unroll
    for (int ma = 0; ma < 2; ma++) {
        int o_base = mt * 128 + wm * 32 + ma * 16;
        int o0 = o_base + g, o1 = o_base + g + 8;
        float* r0 = out + (size_t)(b * 256 + o0) * HW + y * 256;
        float* r1 = out + (size_t)(b * 256 + o1) * HW + y * 256;
#pragma unroll
        for (int na = 0; na < 8; na++) {
            int xq = x0 + wn * 64 + na * 8 + tq * 2;
            float2 w0; w0.x = acc[ma][na][0]; w0.y = acc[ma][na][1];
            float2 w1; w1.x = acc[ma][na][2]; w1.y = acc[ma][na][3];
            *(float2*)(r0 + xq) = w0;
            *(float2*)(r1 + xq) = w1;
        }
    }
}

// ---------------- launch ----------------------------------------------------
extern "C" void kernel_launch(void* const* d_in, const int* in_sizes, int n_in,
                              void* d_out, int out_size) {
    const float* x     = (const float*)d_in[0];
    const float* wqkv  = (const float*)d_in[1];
    const float* rel   = (const float*)d_in[2];
    const float* w_ax  = (const float*)d_in[3];
    const float* b_ax  = (const float*)d_in[4];
    const float* w_ay  = (const float*)d_in[5];
    const float* b_ay  = (const float*)d_in[6];
    const float* w_dw  = (const float*)d_in[7];
    const float* gm    = (const float*)d_in[8];
    const float* bt    = (const float*)d_in[9];
    const float* mn    = (const float*)d_in[10];
    const float* vr    = (const float*)d_in[11];
    const float* w_pr  = (const float*)d_in[12];
    float* out = (float*)d_out;

    cudaFuncSetAttribute(conv2_mma_kernel, cudaFuncAttributeMaxDynamicSharedMemorySize, 36864);
    cudaFuncSetAttribute(qkv_mma_kernel, cudaFuncAttributeMaxDynamicSharedMemorySize, 36864);
    cudaFuncSetAttribute(proj_mma_kernel, cudaFuncAttributeMaxDynamicSharedMemorySize, 36864);

    aprep_kernel<<<4096, 256>>>(w_ax, w_ay);
    qprep_kernel<<<768, 256>>>(wqkv);
    pprep_kernel<<<256, 256>>>(w_pr);
    qkv_mma_kernel<<<dim3(256, 2, 12), 256, 36864>>>(x);
    attn_kernel<<<dim3(2048, 16), 64>>>(rel);
    conv2_mma_kernel<<<dim3(256, 2, 4), 256, 36864>>>(b_ax, b_ay);
    dwbn_kernel<<<dim3(64, 128, 2), 256>>>(w_dw, gm, bt, mn, vr);
    proj_mma_kernel<<<dim3(256, 2, 4), 256, 36864>>>(out);
}